// round 5
// baseline (speedup 1.0000x reference)
#include <cuda_runtime.h>
#include <cuda_bf16.h>
#include <math.h>

#define D_MODEL 768
#define N_HEADS 12
#define HEAD_DIM 64
#define FFN_DIM 3072
#define T_TOK 2048
#define BATCH 2
#define M_ROWS (BATCH * T_TOK)   // 4096
#define QKV_N 2304               // 3 * D_MODEL

// -------------------- scratch ---------------------------------------------
__device__ float g_ni[M_ROWS * D_MODEL];
__device__ float g_qkv[M_ROWS * QKV_N];
__device__ float g_wqkv[D_MODEL * QKV_N];
__device__ float g_bqkv[QKV_N];
__device__ float g_attn[M_ROWS * D_MODEL];
__device__ float g_res1[M_ROWS * D_MODEL];
__device__ float g_ffin[M_ROWS * D_MODEL];
__device__ float g_h[M_ROWS * FFN_DIM];
__device__ float g_trig[T_TOK * 16 * 2];

// -------------------- async copy helpers ----------------------------------
__device__ __forceinline__ void cp16(void* smem_dst, const void* gptr) {
    unsigned a = (unsigned)__cvta_generic_to_shared(smem_dst);
    asm volatile("cp.async.ca.shared.global [%0], [%1], 16;" :: "r"(a), "l"(gptr));
}
__device__ __forceinline__ void cp_commit() { asm volatile("cp.async.commit_group;"); }
template <int NN>
__device__ __forceinline__ void cp_wait() { asm volatile("cp.async.wait_group %0;" :: "n"(NN)); }

__device__ __forceinline__ void mma_tf32(float* c, const unsigned* a, const unsigned* b) {
    asm volatile(
        "mma.sync.aligned.m16n8k8.row.col.f32.tf32.tf32.f32 "
        "{%0,%1,%2,%3}, {%4,%5,%6,%7}, {%8,%9}, {%0,%1,%2,%3};"
        : "+f"(c[0]), "+f"(c[1]), "+f"(c[2]), "+f"(c[3])
        : "r"(a[0]), "r"(a[1]), "r"(a[2]), "r"(a[3]), "r"(b[0]), "r"(b[1]));
}

// -------------------- block reduction -------------------------------------
__device__ __forceinline__ float block_sum_256(float val) {
    __shared__ float red[8];
    int lane = threadIdx.x & 31, w = threadIdx.x >> 5;
#pragma unroll
    for (int o = 16; o; o >>= 1) val += __shfl_xor_sync(0xffffffffu, val, o);
    if (lane == 0) red[w] = val;
    __syncthreads();
    if (w == 0) {
        float t = (lane < 8) ? red[lane] : 0.f;
#pragma unroll
        for (int o = 4; o; o >>= 1) t += __shfl_xor_sync(0xffffffffu, t, o);
        if (lane == 0) red[0] = t;
    }
    __syncthreads();
    float r = red[0];
    __syncthreads();
    return r;
}

// -------------------- LayerNorm -------------------------------------------
__global__ void ln_kernel(const float* __restrict__ x, const float* __restrict__ g,
                          const float* __restrict__ bta, float* __restrict__ y) {
    size_t row = blockIdx.x;
    int tid = threadIdx.x;
    const float* xr = x + row * D_MODEL;
    float v0 = xr[tid], v1 = xr[tid + 256], v2 = xr[tid + 512];
    float mu = block_sum_256(v0 + v1 + v2) * (1.f / 768.f);
    float d0 = v0 - mu, d1 = v1 - mu, d2 = v2 - mu;
    float var = block_sum_256(d0 * d0 + d1 * d1 + d2 * d2) * (1.f / 768.f);
    float rs = rsqrtf(var + 1e-5f);
    float* yr = y + row * D_MODEL;
    yr[tid]       = d0 * rs * g[tid]       + bta[tid];
    yr[tid + 256] = d1 * rs * g[tid + 256] + bta[tid + 256];
    yr[tid + 512] = d2 * rs * g[tid + 512] + bta[tid + 512];
}

// -------------------- QKV weight/bias concat (q scaled by 0.125) ----------
__global__ void concat_qkv(const float* __restrict__ wq, const float* __restrict__ wk,
                           const float* __restrict__ wv, const float* __restrict__ bq,
                           const float* __restrict__ bk, const float* __restrict__ bv,
                           float* __restrict__ W, float* __restrict__ Bo) {
    int idx = blockIdx.x * 256 + threadIdx.x;
    const int total = D_MODEL * QKV_N / 4;
    if (idx < total) {
        int e = idx * 4;
        int k = e / QKV_N, j = e % QKV_N;
        float4 v;
        if (j < 768) {
            v = *(const float4*)(wq + (size_t)k * 768 + j);
            v.x *= 0.125f; v.y *= 0.125f; v.z *= 0.125f; v.w *= 0.125f;
        } else if (j < 1536) {
            v = *(const float4*)(wk + (size_t)k * 768 + (j - 768));
        } else {
            v = *(const float4*)(wv + (size_t)k * 768 + (j - 1536));
        }
        *(float4*)(W + e) = v;
    }
    if (idx < QKV_N / 4) {
        int j = idx * 4;
        float4 v;
        if (j < 768) {
            v = *(const float4*)(bq + j);
            v.x *= 0.125f; v.y *= 0.125f; v.z *= 0.125f; v.w *= 0.125f;
        } else if (j < 1536) {
            v = *(const float4*)(bk + (j - 768));
        } else {
            v = *(const float4*)(bv + (j - 1536));
        }
        *(float4*)(Bo + j) = v;
    }
}

// -------------------- trig table ------------------------------------------
__global__ void trig_kernel(float* __restrict__ trig) {
    int idx = blockIdx.x * 256 + threadIdx.x;
    if (idx >= T_TOK * 16) return;
    int t = idx >> 4, i = idx & 15;
    double ts = pow(10000.0, (double)i / 32.0);
    double ang = (double)t / ts;
    double sd, cd;
    sincos(ang, &sd, &cd);
    trig[idx * 2]     = (float)cd;
    trig[idx * 2 + 1] = (float)sd;
}

// -------------------- p-RoPE apply ----------------------------------------
__global__ void rope_apply(float* __restrict__ qkv, const float* __restrict__ trig) {
    int idx = blockIdx.x * blockDim.x + threadIdx.x;
    const int total = BATCH * T_TOK * N_HEADS * 16;
    if (idx >= total) return;
    int i = idx & 15;
    int h = (idx >> 4) % N_HEADS;
    int t = (idx / (16 * N_HEADS)) % T_TOK;
    int b = idx / (16 * N_HEADS * T_TOK);
    size_t base = ((size_t)(b * T_TOK + t)) * QKV_N + h * HEAD_DIM + i;
    float cf = trig[(t * 16 + i) * 2];
    float sf = trig[(t * 16 + i) * 2 + 1];
    float x1 = qkv[base], x2 = qkv[base + 32];
    qkv[base]      = x1 * cf - x2 * sf;
    qkv[base + 32] = x2 * cf + x1 * sf;
    x1 = qkv[base + 768]; x2 = qkv[base + 800];
    qkv[base + 768] = x1 * cf - x2 * sf;
    qkv[base + 800] = x2 * cf + x1 * sf;
}

// -------------------- tf32 GEMM: BK=32, 3-stage cp.async pipeline ----------
#define AS_STRIDE 36
#define BS_STRIDE 136
#define GSTAGES 3
#define AS_SZ (128 * AS_STRIDE)
#define BS_SZ (32 * BS_STRIDE)
#define GEMM_SMEM_BYTES (GSTAGES * (AS_SZ + BS_SZ) * 4)

template <bool GELU>
__global__ __launch_bounds__(256, 2)
void gemm_tf32(const float* __restrict__ A, const float* __restrict__ Bm,
               const float* __restrict__ bias, const float* __restrict__ res,
               float* __restrict__ C, int M, int N, int K) {
    extern __shared__ unsigned gsm[];
    unsigned* AsB = gsm;
    unsigned* BsB = gsm + GSTAGES * AS_SZ;
    int tid = threadIdx.x;
    int wid = tid >> 5, lane = tid & 31;
    int g = lane >> 2, tig = lane & 3;
    int wm = wid & 3, wn = wid >> 2;
    int brow = blockIdx.y * 128, bcol = blockIdx.x * 128;

    int ar = tid >> 3, ac = (tid & 7) * 4;     // A: 32 rows/pass, 4 passes
    int br = tid >> 5, bc = (tid & 31) * 4;    // B: 8 rows/pass, 4 passes
    const float* Ap = A + (size_t)(brow + ar) * K + ac;
    const float* Bp = Bm + (size_t)br * N + bcol + bc;

    int nIter = K >> 5;

#define GEMM_ISSUE(KT, STG) do {                                             \
        const float* a0_ = Ap + (KT) * 32;                                   \
        unsigned* asd_ = AsB + (STG) * AS_SZ;                                \
        cp16(&asd_[ar * AS_STRIDE + ac], a0_);                               \
        cp16(&asd_[(ar + 32) * AS_STRIDE + ac], a0_ + (size_t)32 * K);       \
        cp16(&asd_[(ar + 64) * AS_STRIDE + ac], a0_ + (size_t)64 * K);       \
        cp16(&asd_[(ar + 96) * AS_STRIDE + ac], a0_ + (size_t)96 * K);       \
        const float* b0_ = Bp + (size_t)(KT) * 32 * N;                       \
        unsigned* bsd_ = BsB + (STG) * BS_SZ;                                \
        cp16(&bsd_[br * BS_STRIDE + bc], b0_);                               \
        cp16(&bsd_[(br + 8) * BS_STRIDE + bc], b0_ + (size_t)8 * N);         \
        cp16(&bsd_[(br + 16) * BS_STRIDE + bc], b0_ + (size_t)16 * N);       \
        cp16(&bsd_[(br + 24) * BS_STRIDE + bc], b0_ + (size_t)24 * N);       \
        cp_commit();                                                          \
    } while (0)

    GEMM_ISSUE(0, 0);
    GEMM_ISSUE(1, 1);

    float acc[2][8][4];
#pragma unroll
    for (int i = 0; i < 2; i++)
#pragma unroll
        for (int j = 0; j < 8; j++)
#pragma unroll
            for (int r = 0; r < 4; r++) acc[i][j][r] = 0.f;

    int cur = 0;
    for (int kt = 0; kt < nIter; ++kt) {
        if (kt + 1 < nIter) cp_wait<1>(); else cp_wait<0>();
        __syncthreads();
        if (kt + 2 < nIter) {
            int nxt = cur + 2; if (nxt >= GSTAGES) nxt -= GSTAGES;
            GEMM_ISSUE(kt + 2, nxt);
        }
        const unsigned* As = AsB + cur * AS_SZ;
        const unsigned* Bs = BsB + cur * BS_SZ;
#pragma unroll
        for (int ks = 0; ks < 32; ks += 8) {
            unsigned af[2][4];
#pragma unroll
            for (int mt = 0; mt < 2; mt++) {
                int r0 = wm * 32 + mt * 16 + g;
                af[mt][0] = As[r0 * AS_STRIDE + ks + tig];
                af[mt][1] = As[(r0 + 8) * AS_STRIDE + ks + tig];
                af[mt][2] = As[r0 * AS_STRIDE + ks + tig + 4];
                af[mt][3] = As[(r0 + 8) * AS_STRIDE + ks + tig + 4];
            }
#pragma unroll
            for (int nt = 0; nt < 8; nt++) {
                unsigned bf[2];
                int c0 = wn * 64 + nt * 8 + g;
                bf[0] = Bs[(ks + tig) * BS_STRIDE + c0];
                bf[1] = Bs[(ks + tig + 4) * BS_STRIDE + c0];
                mma_tf32(acc[0][nt], af[0], bf);
                mma_tf32(acc[1][nt], af[1], bf);
            }
        }
        __syncthreads();
        cur = cur + 1; if (cur >= GSTAGES) cur -= GSTAGES;
    }

#pragma unroll
    for (int mt = 0; mt < 2; mt++) {
        int row0 = brow + wm * 32 + mt * 16 + g;
#pragma unroll
        for (int nt = 0; nt < 8; nt++) {
            int col = bcol + wn * 64 + nt * 8 + tig * 2;
            float b0 = bias[col], b1 = bias[col + 1];
            float v00 = acc[mt][nt][0] + b0;
            float v01 = acc[mt][nt][1] + b1;
            float v10 = acc[mt][nt][2] + b0;
            float v11 = acc[mt][nt][3] + b1;
            if (GELU) {
                v00 *= normcdff(v00); v01 *= normcdff(v01);
                v10 *= normcdff(v10); v11 *= normcdff(v11);
            }
            if (res) {
                const float* r0p = res + (size_t)row0 * N + col;
                const float* r1p = res + (size_t)(row0 + 8) * N + col;
                v00 += r0p[0]; v01 += r0p[1];
                v10 += r1p[0]; v11 += r1p[1];
            }
            *(float2*)(C + (size_t)row0 * N + col) = make_float2(v00, v01);
            *(float2*)(C + (size_t)(row0 + 8) * N + col) = make_float2(v10, v11);
        }
    }
#undef GEMM_ISSUE
}

// -------------------- flash attention: double-buffered K/V -----------------
#define QS_STRIDE 68
#define KS_STRIDE 76
#define VS_STRIDE 72
#define SC_STRIDE 68
#define KS_SZ (64 * KS_STRIDE)
#define VS_SZ (64 * VS_STRIDE)
#define AT_SMEM_FLOATS (64*QS_STRIDE + 2*KS_SZ + 2*VS_SZ + 64*SC_STRIDE + 192)

__global__ __launch_bounds__(256)
void attn_tf32(const float* __restrict__ QKV, const float* __restrict__ ab,
               float* __restrict__ O) {
    extern __shared__ float sm[];
    unsigned* Qs = (unsigned*)sm;
    unsigned* KsB = Qs + 64 * QS_STRIDE;
    unsigned* VsB = KsB + 2 * KS_SZ;
    float* Sc = (float*)(VsB + 2 * VS_SZ);
    float* mrow = Sc + 64 * SC_STRIDE;
    float* lrow = mrow + 64;
    float* srow = lrow + 64;
    unsigned* Scu = (unsigned*)Sc;

    int tid = threadIdx.x;
    int wid = tid >> 5, lane = tid & 31;
    int g = lane >> 2, tig = lane & 3;
    int m0 = (wid >> 1) * 16;
    int n0b = (wid & 1) * 32;

    int qb = blockIdx.x * 64;
    int h = blockIdx.y, b = blockIdx.z;
    size_t bh = (size_t)b * T_TOK * QKV_N + h * HEAD_DIM;
    const float* qp = QKV + bh;
    const float* kp = QKV + bh + 768;
    const float* vp = QKV + bh + 1536;

#define KV_ISSUE(KT, BUF) do {                                                \
        int kb_ = (KT) * 64;                                                  \
        unsigned* ksd_ = KsB + (BUF) * KS_SZ;                                 \
        unsigned* vsd_ = VsB + (BUF) * VS_SZ;                                 \
        _Pragma("unroll")                                                     \
        for (int it = 0; it < 4; it++) {                                      \
            int idx_ = tid + it * 256;                                        \
            int r_ = idx_ >> 4, c4_ = (idx_ & 15) * 4;                        \
            cp16(&ksd_[r_ * KS_STRIDE + c4_], kp + (size_t)(kb_ + r_) * QKV_N + c4_); \
            cp16(&vsd_[r_ * VS_STRIDE + c4_], vp + (size_t)(kb_ + r_) * QKV_N + c4_); \
        }                                                                     \
        cp_commit();                                                          \
    } while (0)

    // prologue: Q, then KV tile 0
#pragma unroll
    for (int it = 0; it < 4; it++) {
        int idx = tid + it * 256;
        int r = idx >> 4, c4 = (idx & 15) * 4;
        cp16(&Qs[r * QS_STRIDE + c4], qp + (size_t)(qb + r) * QKV_N + c4);
    }
    cp_commit();
    KV_ISSUE(0, 0);
    if (tid < 64) { mrow[tid] = -1e30f; lrow[tid] = 0.f; }

    float o[4][4];
#pragma unroll
    for (int i = 0; i < 4; i++)
#pragma unroll
        for (int j = 0; j < 4; j++) o[i][j] = 0.f;

    float bias0 = ab[h * 2 + 0], bias1 = ab[h * 2 + 1];
    int qvar = qb >> 7;

    for (int kt = 0; kt < 32; kt++) {
        int cur = kt & 1;
        if (kt + 1 < 32) KV_ISSUE(kt + 1, cur ^ 1);      // safe: buf read last in kt-1, barrier passed
        if (kt + 1 < 32) cp_wait<1>(); else cp_wait<0>();
        __syncthreads();
        const unsigned* Ks = KsB + cur * KS_SZ;
        const unsigned* Vs = VsB + cur * VS_SZ;

        // ---- S = Q @ K^T ----
        float s[4][4];
#pragma unroll
        for (int i = 0; i < 4; i++)
#pragma unroll
            for (int j = 0; j < 4; j++) s[i][j] = 0.f;
#pragma unroll
        for (int ks = 0; ks < 64; ks += 8) {
            unsigned af[4];
            af[0] = Qs[(m0 + g) * QS_STRIDE + ks + tig];
            af[1] = Qs[(m0 + g + 8) * QS_STRIDE + ks + tig];
            af[2] = Qs[(m0 + g) * QS_STRIDE + ks + tig + 4];
            af[3] = Qs[(m0 + g + 8) * QS_STRIDE + ks + tig + 4];
#pragma unroll
            for (int nt = 0; nt < 4; nt++) {
                unsigned bf[2];
                int c0 = n0b + nt * 8 + g;
                bf[0] = Ks[c0 * KS_STRIDE + ks + tig];
                bf[1] = Ks[c0 * KS_STRIDE + ks + tig + 4];
                mma_tf32(s[nt], af, bf);
            }
        }
        float bias = (((kt * 64) >> 7) == qvar) ? bias0 : bias1;
#pragma unroll
        for (int nt = 0; nt < 4; nt++) {
            int col = n0b + nt * 8 + tig * 2;
            Sc[(m0 + g) * SC_STRIDE + col]     = s[nt][0] + bias;
            Sc[(m0 + g) * SC_STRIDE + col + 1] = s[nt][1] + bias;
            Sc[(m0 + g + 8) * SC_STRIDE + col]     = s[nt][2] + bias;
            Sc[(m0 + g + 8) * SC_STRIDE + col + 1] = s[nt][3] + bias;
        }
        __syncthreads();

        // ---- online softmax: 4 threads per row ----
        {
            int r = tid >> 2, seg = tid & 3;
            float* sr = &Sc[r * SC_STRIDE + seg * 16];
            float mo = mrow[r];
            float mx = -1e30f;
#pragma unroll
            for (int j = 0; j < 16; j++) mx = fmaxf(mx, sr[j]);
            mx = fmaxf(mx, __shfl_xor_sync(0xffffffffu, mx, 1));
            mx = fmaxf(mx, __shfl_xor_sync(0xffffffffu, mx, 2));
            mx = fmaxf(mx, mo);
            float sum = 0.f;
#pragma unroll
            for (int j = 0; j < 16; j++) {
                float p = __expf(sr[j] - mx);
                sr[j] = p;
                sum += p;
            }
            sum += __shfl_xor_sync(0xffffffffu, sum, 1);
            sum += __shfl_xor_sync(0xffffffffu, sum, 2);
            if (seg == 0) {
                float scl = __expf(mo - mx);
                mrow[r] = mx;
                lrow[r] = lrow[r] * scl + sum;
                srow[r] = scl;
            }
        }
        __syncthreads();

        // ---- rescale + O += P @ V ----
        float scl0 = srow[m0 + g], scl1 = srow[m0 + g + 8];
#pragma unroll
        for (int nt = 0; nt < 4; nt++) {
            o[nt][0] *= scl0; o[nt][1] *= scl0;
            o[nt][2] *= scl1; o[nt][3] *= scl1;
        }
#pragma unroll
        for (int ks = 0; ks < 64; ks += 8) {
            unsigned af[4];
            af[0] = Scu[(m0 + g) * SC_STRIDE + ks + tig];
            af[1] = Scu[(m0 + g + 8) * SC_STRIDE + ks + tig];
            af[2] = Scu[(m0 + g) * SC_STRIDE + ks + tig + 4];
            af[3] = Scu[(m0 + g + 8) * SC_STRIDE + ks + tig + 4];
#pragma unroll
            for (int nt = 0; nt < 4; nt++) {
                unsigned bf[2];
                int c0 = n0b + nt * 8 + g;
                bf[0] = Vs[(ks + tig) * VS_STRIDE + c0];
                bf[1] = Vs[(ks + tig + 4) * VS_STRIDE + c0];
                mma_tf32(o[nt], af, bf);
            }
        }
        __syncthreads();
    }
#undef KV_ISSUE

    float inv0 = 1.f / lrow[m0 + g], inv1 = 1.f / lrow[m0 + g + 8];
    int row0 = qb + m0 + g;
#pragma unroll
    for (int nt = 0; nt < 4; nt++) {
        int col = n0b + nt * 8 + tig * 2;
        float* o0 = O + (size_t)(b * T_TOK + row0) * D_MODEL + h * HEAD_DIM + col;
        float* o1 = O + (size_t)(b * T_TOK + row0 + 8) * D_MODEL + h * HEAD_DIM + col;
        *(float2*)o0 = make_float2(o[nt][0] * inv0, o[nt][1] * inv0);
        *(float2*)o1 = make_float2(o[nt][2] * inv1, o[nt][3] * inv1);
    }
}

// -------------------- launch ----------------------------------------------
extern "C" void kernel_launch(void* const* d_in, const int* in_sizes, int n_in,
                              void* d_out, int out_size) {
    const float* hs  = (const float*)d_in[0];
    const float* wq  = (const float*)d_in[1];
    const float* bq  = (const float*)d_in[2];
    const float* wk  = (const float*)d_in[3];
    const float* bk  = (const float*)d_in[4];
    const float* wv  = (const float*)d_in[5];
    const float* bv  = (const float*)d_in[6];
    const float* wo  = (const float*)d_in[7];
    const float* bo  = (const float*)d_in[8];
    const float* ab  = (const float*)d_in[9];
    const float* g1  = (const float*)d_in[10];
    const float* be1 = (const float*)d_in[11];
    const float* g3  = (const float*)d_in[12];
    const float* be3 = (const float*)d_in[13];
    const float* w1  = (const float*)d_in[14];
    const float* b1  = (const float*)d_in[15];
    const float* w2  = (const float*)d_in[16];
    const float* b2  = (const float*)d_in[17];
    float* out = (float*)d_out;

    float *ni, *qkv, *wqkv, *bqkv, *attn, *res1, *ffin, *hbuf, *trig;
    cudaGetSymbolAddress((void**)&ni,   g_ni);
    cudaGetSymbolAddress((void**)&qkv,  g_qkv);
    cudaGetSymbolAddress((void**)&wqkv, g_wqkv);
    cudaGetSymbolAddress((void**)&bqkv, g_bqkv);
    cudaGetSymbolAddress((void**)&attn, g_attn);
    cudaGetSymbolAddress((void**)&res1, g_res1);
    cudaGetSymbolAddress((void**)&ffin, g_ffin);
    cudaGetSymbolAddress((void**)&hbuf, g_h);
    cudaGetSymbolAddress((void**)&trig, g_trig);

    static bool attr_set = false;
    if (!attr_set) {
        cudaFuncSetAttribute(attn_tf32, cudaFuncAttributeMaxDynamicSharedMemorySize,
                             AT_SMEM_FLOATS * (int)sizeof(float));
        cudaFuncSetAttribute(gemm_tf32<false>, cudaFuncAttributeMaxDynamicSharedMemorySize,
                             GEMM_SMEM_BYTES);
        cudaFuncSetAttribute(gemm_tf32<true>, cudaFuncAttributeMaxDynamicSharedMemorySize,
                             GEMM_SMEM_BYTES);
        attr_set = true;
    }

    // 0. trig table + QKV weight concat
    trig_kernel<<<(T_TOK * 16 + 255) / 256, 256>>>(trig);
    concat_qkv<<<(D_MODEL * QKV_N / 4 + 255) / 256, 256>>>(wq, wk, wv, bq, bk, bv, wqkv, bqkv);

    // 1. LN1
    ln_kernel<<<M_ROWS, 256>>>(hs, g1, be1, ni);

    // 2. fused QKV projection
    dim3 gQKV(QKV_N / 128, M_ROWS / 128);
    gemm_tf32<false><<<gQKV, 256, GEMM_SMEM_BYTES>>>(ni, wqkv, bqkv, nullptr, qkv, M_ROWS, QKV_N, D_MODEL);

    // 3. RoPE (table lookup)
    {
        int total = BATCH * T_TOK * N_HEADS * 16;
        rope_apply<<<(total + 255) / 256, 256>>>(qkv, trig);
    }

    // 4. attention
    {
        dim3 ga(T_TOK / 64, N_HEADS, BATCH);
        attn_tf32<<<ga, 256, AT_SMEM_FLOATS * (int)sizeof(float)>>>(qkv, ab, attn);
    }

    // 5. out-proj + residual(hs)
    dim3 gP(D_MODEL / 128, M_ROWS / 128);
    gemm_tf32<false><<<gP, 256, GEMM_SMEM_BYTES>>>(attn, wo, bo, hs, res1, M_ROWS, D_MODEL, D_MODEL);

    // 6. LN3
    ln_kernel<<<M_ROWS, 256>>>(res1, g3, be3, ffin);

    // 7. FFN1 + exact GELU
    dim3 gF1(FFN_DIM / 128, M_ROWS / 128);
    gemm_tf32<true><<<gF1, 256, GEMM_SMEM_BYTES>>>(ffin, w1, b1, nullptr, hbuf, M_ROWS, FFN_DIM, D_MODEL);

    // 8. FFN2 + residual(res1) -> out
    gemm_tf32<false><<<gP, 256, GEMM_SMEM_BYTES>>>(hbuf, w2, b2, res1, out, M_ROWS, D_MODEL, FFN_DIM);
}

// round 6
// speedup vs baseline: 1.0760x; 1.0760x over previous
#include <cuda_runtime.h>
#include <cuda_bf16.h>
#include <math.h>

#define D_MODEL 768
#define N_HEADS 12
#define HEAD_DIM 64
#define FFN_DIM 3072
#define T_TOK 2048
#define BATCH 2
#define M_ROWS (BATCH * T_TOK)   // 4096
#define QKV_N 2304               // 3 * D_MODEL

// -------------------- scratch ---------------------------------------------
__device__ float g_ni[M_ROWS * D_MODEL];
__device__ float g_qkv[M_ROWS * QKV_N];
__device__ float g_wqkv[D_MODEL * QKV_N];
__device__ float g_bqkv[QKV_N];
__device__ float g_attn[M_ROWS * D_MODEL];
__device__ float g_res1[M_ROWS * D_MODEL];
__device__ float g_ffin[M_ROWS * D_MODEL];
__device__ float g_h[M_ROWS * FFN_DIM];
__device__ float g_trig[T_TOK * 16 * 2];

// -------------------- async copy helpers ----------------------------------
__device__ __forceinline__ void cp16(void* smem_dst, const void* gptr) {
    unsigned a = (unsigned)__cvta_generic_to_shared(smem_dst);
    asm volatile("cp.async.cg.shared.global [%0], [%1], 16;" :: "r"(a), "l"(gptr));
}
__device__ __forceinline__ void cp_commit() { asm volatile("cp.async.commit_group;"); }
template <int NN>
__device__ __forceinline__ void cp_wait() { asm volatile("cp.async.wait_group %0;" :: "n"(NN)); }

__device__ __forceinline__ void mma_tf32(float* c, const unsigned* a, const unsigned* b) {
    asm volatile(
        "mma.sync.aligned.m16n8k8.row.col.f32.tf32.tf32.f32 "
        "{%0,%1,%2,%3}, {%4,%5,%6,%7}, {%8,%9}, {%0,%1,%2,%3};"
        : "+f"(c[0]), "+f"(c[1]), "+f"(c[2]), "+f"(c[3])
        : "r"(a[0]), "r"(a[1]), "r"(a[2]), "r"(a[3]), "r"(b[0]), "r"(b[1]));
}

// -------------------- block reduction -------------------------------------
__device__ __forceinline__ float block_sum_256(float val) {
    __shared__ float red[8];
    int lane = threadIdx.x & 31, w = threadIdx.x >> 5;
#pragma unroll
    for (int o = 16; o; o >>= 1) val += __shfl_xor_sync(0xffffffffu, val, o);
    if (lane == 0) red[w] = val;
    __syncthreads();
    if (w == 0) {
        float t = (lane < 8) ? red[lane] : 0.f;
#pragma unroll
        for (int o = 4; o; o >>= 1) t += __shfl_xor_sync(0xffffffffu, t, o);
        if (lane == 0) red[0] = t;
    }
    __syncthreads();
    float r = red[0];
    __syncthreads();
    return r;
}

// -------------------- LayerNorm -------------------------------------------
__global__ void ln_kernel(const float* __restrict__ x, const float* __restrict__ g,
                          const float* __restrict__ bta, float* __restrict__ y) {
    size_t row = blockIdx.x;
    int tid = threadIdx.x;
    const float* xr = x + row * D_MODEL;
    float v0 = xr[tid], v1 = xr[tid + 256], v2 = xr[tid + 512];
    float mu = block_sum_256(v0 + v1 + v2) * (1.f / 768.f);
    float d0 = v0 - mu, d1 = v1 - mu, d2 = v2 - mu;
    float var = block_sum_256(d0 * d0 + d1 * d1 + d2 * d2) * (1.f / 768.f);
    float rs = rsqrtf(var + 1e-5f);
    float* yr = y + row * D_MODEL;
    yr[tid]       = d0 * rs * g[tid]       + bta[tid];
    yr[tid + 256] = d1 * rs * g[tid + 256] + bta[tid + 256];
    yr[tid + 512] = d2 * rs * g[tid + 512] + bta[tid + 512];
}

// -------------------- QKV weight/bias concat (q scaled by 0.125) ----------
__global__ void concat_qkv(const float* __restrict__ wq, const float* __restrict__ wk,
                           const float* __restrict__ wv, const float* __restrict__ bq,
                           const float* __restrict__ bk, const float* __restrict__ bv,
                           float* __restrict__ W, float* __restrict__ Bo) {
    int idx = blockIdx.x * 256 + threadIdx.x;
    const int total = D_MODEL * QKV_N / 4;
    if (idx < total) {
        int e = idx * 4;
        int k = e / QKV_N, j = e % QKV_N;
        float4 v;
        if (j < 768) {
            v = *(const float4*)(wq + (size_t)k * 768 + j);
            v.x *= 0.125f; v.y *= 0.125f; v.z *= 0.125f; v.w *= 0.125f;
        } else if (j < 1536) {
            v = *(const float4*)(wk + (size_t)k * 768 + (j - 768));
        } else {
            v = *(const float4*)(wv + (size_t)k * 768 + (j - 1536));
        }
        *(float4*)(W + e) = v;
    }
    if (idx < QKV_N / 4) {
        int j = idx * 4;
        float4 v;
        if (j < 768) {
            v = *(const float4*)(bq + j);
            v.x *= 0.125f; v.y *= 0.125f; v.z *= 0.125f; v.w *= 0.125f;
        } else if (j < 1536) {
            v = *(const float4*)(bk + (j - 768));
        } else {
            v = *(const float4*)(bv + (j - 1536));
        }
        *(float4*)(Bo + j) = v;
    }
}

// -------------------- trig table ------------------------------------------
__global__ void trig_kernel(float* __restrict__ trig) {
    int idx = blockIdx.x * 256 + threadIdx.x;
    if (idx >= T_TOK * 16) return;
    int t = idx >> 4, i = idx & 15;
    double ts = pow(10000.0, (double)i / 32.0);
    double ang = (double)t / ts;
    double sd, cd;
    sincos(ang, &sd, &cd);
    trig[idx * 2]     = (float)cd;
    trig[idx * 2 + 1] = (float)sd;
}

// -------------------- p-RoPE apply ----------------------------------------
__global__ void rope_apply(float* __restrict__ qkv, const float* __restrict__ trig) {
    int idx = blockIdx.x * blockDim.x + threadIdx.x;
    const int total = BATCH * T_TOK * N_HEADS * 16;
    if (idx >= total) return;
    int i = idx & 15;
    int h = (idx >> 4) % N_HEADS;
    int t = (idx / (16 * N_HEADS)) % T_TOK;
    int b = idx / (16 * N_HEADS * T_TOK);
    size_t base = ((size_t)(b * T_TOK + t)) * QKV_N + h * HEAD_DIM + i;
    float cf = trig[(t * 16 + i) * 2];
    float sf = trig[(t * 16 + i) * 2 + 1];
    float x1 = qkv[base], x2 = qkv[base + 32];
    qkv[base]      = x1 * cf - x2 * sf;
    qkv[base + 32] = x2 * cf + x1 * sf;
    x1 = qkv[base + 768]; x2 = qkv[base + 800];
    qkv[base + 768] = x1 * cf - x2 * sf;
    qkv[base + 800] = x2 * cf + x1 * sf;
}

// -------------------- tf32 GEMM: BK=16, 2-stage, ONE sync per iter --------
#define AS_STRIDE 20
#define BS_STRIDE 136

template <bool GELU>
__global__ __launch_bounds__(256, 2)
void gemm_tf32(const float* __restrict__ A, const float* __restrict__ Bm,
               const float* __restrict__ bias, const float* __restrict__ res,
               float* __restrict__ C, int M, int N, int K) {
    __shared__ unsigned As[2][128 * AS_STRIDE];
    __shared__ unsigned Bs[2][16 * BS_STRIDE];
    int tid = threadIdx.x;
    int wid = tid >> 5, lane = tid & 31;
    int g = lane >> 2, tig = lane & 3;
    int wm = wid & 3, wn = wid >> 2;
    int brow = blockIdx.y * 128, bcol = blockIdx.x * 128;

    int ar = tid >> 2, ac = (tid & 3) * 4;
    int br = tid >> 5, bc = (tid & 31) * 4;
    const float* Ap = A + (size_t)(brow + ar) * K + ac;
    const float* Bp = Bm + (size_t)br * N + bcol + bc;

    int nIter = K >> 4;

#define GEMM_ISSUE(KT, STG) do {                                              \
        const float* a0_ = Ap + (KT) * 16;                                    \
        cp16(&As[STG][ar * AS_STRIDE + ac], a0_);                             \
        cp16(&As[STG][(ar + 64) * AS_STRIDE + ac], a0_ + (size_t)64 * K);     \
        const float* b0_ = Bp + (size_t)(KT) * 16 * N;                        \
        cp16(&Bs[STG][br * BS_STRIDE + bc], b0_);                             \
        cp16(&Bs[STG][(br + 8) * BS_STRIDE + bc], b0_ + (size_t)8 * N);       \
        cp_commit();                                                           \
    } while (0)

    GEMM_ISSUE(0, 0);

    float acc[2][8][4];
#pragma unroll
    for (int i = 0; i < 2; i++)
#pragma unroll
        for (int j = 0; j < 8; j++)
#pragma unroll
            for (int r = 0; r < 4; r++) acc[i][j][r] = 0.f;

    for (int kt = 0; kt < nIter; ++kt) {
        int cur = kt & 1;
        cp_wait<0>();
        __syncthreads();
        // safe: this sync proves all threads finished reading buffer cur^1
        if (kt + 1 < nIter) GEMM_ISSUE(kt + 1, cur ^ 1);
#pragma unroll
        for (int ks = 0; ks < 16; ks += 8) {
            unsigned af[2][4];
#pragma unroll
            for (int mt = 0; mt < 2; mt++) {
                int r0 = wm * 32 + mt * 16 + g;
                af[mt][0] = As[cur][r0 * AS_STRIDE + ks + tig];
                af[mt][1] = As[cur][(r0 + 8) * AS_STRIDE + ks + tig];
                af[mt][2] = As[cur][r0 * AS_STRIDE + ks + tig + 4];
                af[mt][3] = As[cur][(r0 + 8) * AS_STRIDE + ks + tig + 4];
            }
#pragma unroll
            for (int nt = 0; nt < 8; nt++) {
                unsigned bf[2];
                int c0 = wn * 64 + nt * 8 + g;
                bf[0] = Bs[cur][(ks + tig) * BS_STRIDE + c0];
                bf[1] = Bs[cur][(ks + tig + 4) * BS_STRIDE + c0];
                mma_tf32(acc[0][nt], af[0], bf);
                mma_tf32(acc[1][nt], af[1], bf);
            }
        }
    }
#undef GEMM_ISSUE

#pragma unroll
    for (int mt = 0; mt < 2; mt++) {
        int row0 = brow + wm * 32 + mt * 16 + g;
#pragma unroll
        for (int nt = 0; nt < 8; nt++) {
            int col = bcol + wn * 64 + nt * 8 + tig * 2;
            float b0 = bias[col], b1 = bias[col + 1];
            float v00 = acc[mt][nt][0] + b0;
            float v01 = acc[mt][nt][1] + b1;
            float v10 = acc[mt][nt][2] + b0;
            float v11 = acc[mt][nt][3] + b1;
            if (GELU) {
                v00 *= normcdff(v00); v01 *= normcdff(v01);
                v10 *= normcdff(v10); v11 *= normcdff(v11);
            }
            if (res) {
                const float* r0p = res + (size_t)row0 * N + col;
                const float* r1p = res + (size_t)(row0 + 8) * N + col;
                v00 += r0p[0]; v01 += r0p[1];
                v10 += r1p[0]; v11 += r1p[1];
            }
            *(float2*)(C + (size_t)row0 * N + col) = make_float2(v00, v01);
            *(float2*)(C + (size_t)(row0 + 8) * N + col) = make_float2(v10, v11);
        }
    }
}

// -------------------- flash attention: double-buffered K/V, 2 CTA/SM ------
#define QS_STRIDE 68
#define KS_STRIDE 76
#define VS_STRIDE 72
#define SC_STRIDE 68
#define KS_SZ (64 * KS_STRIDE)
#define VS_SZ (64 * VS_STRIDE)
#define AT_SMEM_FLOATS (64*QS_STRIDE + 2*KS_SZ + 2*VS_SZ + 64*SC_STRIDE + 192)

__global__ __launch_bounds__(256, 2)
void attn_tf32(const float* __restrict__ QKV, const float* __restrict__ ab,
               float* __restrict__ O) {
    extern __shared__ float sm[];
    unsigned* Qs = (unsigned*)sm;
    unsigned* KsB = Qs + 64 * QS_STRIDE;
    unsigned* VsB = KsB + 2 * KS_SZ;
    float* Sc = (float*)(VsB + 2 * VS_SZ);
    float* mrow = Sc + 64 * SC_STRIDE;
    float* lrow = mrow + 64;
    float* srow = lrow + 64;
    unsigned* Scu = (unsigned*)Sc;

    int tid = threadIdx.x;
    int wid = tid >> 5, lane = tid & 31;
    int g = lane >> 2, tig = lane & 3;
    int m0 = (wid >> 1) * 16;
    int n0b = (wid & 1) * 32;

    int qb = blockIdx.x * 64;
    int h = blockIdx.y, b = blockIdx.z;
    size_t bh = (size_t)b * T_TOK * QKV_N + h * HEAD_DIM;
    const float* qp = QKV + bh;
    const float* kp = QKV + bh + 768;
    const float* vp = QKV + bh + 1536;

#define KV_ISSUE(KT, BUF) do {                                                \
        int kb_ = (KT) * 64;                                                  \
        unsigned* ksd_ = KsB + (BUF) * KS_SZ;                                 \
        unsigned* vsd_ = VsB + (BUF) * VS_SZ;                                 \
        _Pragma("unroll")                                                     \
        for (int it = 0; it < 4; it++) {                                      \
            int idx_ = tid + it * 256;                                        \
            int r_ = idx_ >> 4, c4_ = (idx_ & 15) * 4;                        \
            cp16(&ksd_[r_ * KS_STRIDE + c4_], kp + (size_t)(kb_ + r_) * QKV_N + c4_); \
            cp16(&vsd_[r_ * VS_STRIDE + c4_], vp + (size_t)(kb_ + r_) * QKV_N + c4_); \
        }                                                                     \
        cp_commit();                                                          \
    } while (0)

#pragma unroll
    for (int it = 0; it < 4; it++) {
        int idx = tid + it * 256;
        int r = idx >> 4, c4 = (idx & 15) * 4;
        cp16(&Qs[r * QS_STRIDE + c4], qp + (size_t)(qb + r) * QKV_N + c4);
    }
    cp_commit();
    KV_ISSUE(0, 0);
    if (tid < 64) { mrow[tid] = -1e30f; lrow[tid] = 0.f; }

    float o[4][4];
#pragma unroll
    for (int i = 0; i < 4; i++)
#pragma unroll
        for (int j = 0; j < 4; j++) o[i][j] = 0.f;

    float bias0 = ab[h * 2 + 0], bias1 = ab[h * 2 + 1];
    int qvar = qb >> 7;

    for (int kt = 0; kt < 32; kt++) {
        int cur = kt & 1;
        if (kt + 1 < 32) KV_ISSUE(kt + 1, cur ^ 1);      // safe: trailing sync of kt-1 passed
        if (kt + 1 < 32) cp_wait<1>(); else cp_wait<0>();
        __syncthreads();
        const unsigned* Ks = KsB + cur * KS_SZ;
        const unsigned* Vs = VsB + cur * VS_SZ;

        // ---- S = Q @ K^T ----
        float s[4][4];
#pragma unroll
        for (int i = 0; i < 4; i++)
#pragma unroll
            for (int j = 0; j < 4; j++) s[i][j] = 0.f;
#pragma unroll
        for (int ks = 0; ks < 64; ks += 8) {
            unsigned af[4];
            af[0] = Qs[(m0 + g) * QS_STRIDE + ks + tig];
            af[1] = Qs[(m0 + g + 8) * QS_STRIDE + ks + tig];
            af[2] = Qs[(m0 + g) * QS_STRIDE + ks + tig + 4];
            af[3] = Qs[(m0 + g + 8) * QS_STRIDE + ks + tig + 4];
#pragma unroll
            for (int nt = 0; nt < 4; nt++) {
                unsigned bf[2];
                int c0 = n0b + nt * 8 + g;
                bf[0] = Ks[c0 * KS_STRIDE + ks + tig];
                bf[1] = Ks[c0 * KS_STRIDE + ks + tig + 4];
                mma_tf32(s[nt], af, bf);
            }
        }
        float bias = (((kt * 64) >> 7) == qvar) ? bias0 : bias1;
#pragma unroll
        for (int nt = 0; nt < 4; nt++) {
            int col = n0b + nt * 8 + tig * 2;
            Sc[(m0 + g) * SC_STRIDE + col]     = s[nt][0] + bias;
            Sc[(m0 + g) * SC_STRIDE + col + 1] = s[nt][1] + bias;
            Sc[(m0 + g + 8) * SC_STRIDE + col]     = s[nt][2] + bias;
            Sc[(m0 + g + 8) * SC_STRIDE + col + 1] = s[nt][3] + bias;
        }
        __syncthreads();

        // ---- online softmax: 4 threads per row ----
        {
            int r = tid >> 2, seg = tid & 3;
            float* sr = &Sc[r * SC_STRIDE + seg * 16];
            float mo = mrow[r];
            float mx = -1e30f;
#pragma unroll
            for (int j = 0; j < 16; j++) mx = fmaxf(mx, sr[j]);
            mx = fmaxf(mx, __shfl_xor_sync(0xffffffffu, mx, 1));
            mx = fmaxf(mx, __shfl_xor_sync(0xffffffffu, mx, 2));
            mx = fmaxf(mx, mo);
            float sum = 0.f;
#pragma unroll
            for (int j = 0; j < 16; j++) {
                float p = __expf(sr[j] - mx);
                sr[j] = p;
                sum += p;
            }
            sum += __shfl_xor_sync(0xffffffffu, sum, 1);
            sum += __shfl_xor_sync(0xffffffffu, sum, 2);
            if (seg == 0) {
                float scl = __expf(mo - mx);
                mrow[r] = mx;
                lrow[r] = lrow[r] * scl + sum;
                srow[r] = scl;
            }
        }
        __syncthreads();

        // ---- rescale + O += P @ V ----
        float scl0 = srow[m0 + g], scl1 = srow[m0 + g + 8];
#pragma unroll
        for (int nt = 0; nt < 4; nt++) {
            o[nt][0] *= scl0; o[nt][1] *= scl0;
            o[nt][2] *= scl1; o[nt][3] *= scl1;
        }
#pragma unroll
        for (int ks = 0; ks < 64; ks += 8) {
            unsigned af[4];
            af[0] = Scu[(m0 + g) * SC_STRIDE + ks + tig];
            af[1] = Scu[(m0 + g + 8) * SC_STRIDE + ks + tig];
            af[2] = Scu[(m0 + g) * SC_STRIDE + ks + tig + 4];
            af[3] = Scu[(m0 + g + 8) * SC_STRIDE + ks + tig + 4];
#pragma unroll
            for (int nt = 0; nt < 4; nt++) {
                unsigned bf[2];
                int c0 = n0b + nt * 8 + g;
                bf[0] = Vs[(ks + tig) * VS_STRIDE + c0];
                bf[1] = Vs[(ks + tig + 4) * VS_STRIDE + c0];
                mma_tf32(o[nt], af, bf);
            }
        }
        __syncthreads();
    }
#undef KV_ISSUE

    float inv0 = 1.f / lrow[m0 + g], inv1 = 1.f / lrow[m0 + g + 8];
    int row0 = qb + m0 + g;
#pragma unroll
    for (int nt = 0; nt < 4; nt++) {
        int col = n0b + nt * 8 + tig * 2;
        float* o0 = O + (size_t)(b * T_TOK + row0) * D_MODEL + h * HEAD_DIM + col;
        float* o1 = O + (size_t)(b * T_TOK + row0 + 8) * D_MODEL + h * HEAD_DIM + col;
        *(float2*)o0 = make_float2(o[nt][0] * inv0, o[nt][1] * inv0);
        *(float2*)o1 = make_float2(o[nt][2] * inv1, o[nt][3] * inv1);
    }
}

// -------------------- launch ----------------------------------------------
extern "C" void kernel_launch(void* const* d_in, const int* in_sizes, int n_in,
                              void* d_out, int out_size) {
    const float* hs  = (const float*)d_in[0];
    const float* wq  = (const float*)d_in[1];
    const float* bq  = (const float*)d_in[2];
    const float* wk  = (const float*)d_in[3];
    const float* bk  = (const float*)d_in[4];
    const float* wv  = (const float*)d_in[5];
    const float* bv  = (const float*)d_in[6];
    const float* wo  = (const float*)d_in[7];
    const float* bo  = (const float*)d_in[8];
    const float* ab  = (const float*)d_in[9];
    const float* g1  = (const float*)d_in[10];
    const float* be1 = (const float*)d_in[11];
    const float* g3  = (const float*)d_in[12];
    const float* be3 = (const float*)d_in[13];
    const float* w1  = (const float*)d_in[14];
    const float* b1  = (const float*)d_in[15];
    const float* w2  = (const float*)d_in[16];
    const float* b2  = (const float*)d_in[17];
    float* out = (float*)d_out;

    float *ni, *qkv, *wqkv, *bqkv, *attn, *res1, *ffin, *hbuf, *trig;
    cudaGetSymbolAddress((void**)&ni,   g_ni);
    cudaGetSymbolAddress((void**)&qkv,  g_qkv);
    cudaGetSymbolAddress((void**)&wqkv, g_wqkv);
    cudaGetSymbolAddress((void**)&bqkv, g_bqkv);
    cudaGetSymbolAddress((void**)&attn, g_attn);
    cudaGetSymbolAddress((void**)&res1, g_res1);
    cudaGetSymbolAddress((void**)&ffin, g_ffin);
    cudaGetSymbolAddress((void**)&hbuf, g_h);
    cudaGetSymbolAddress((void**)&trig, g_trig);

    static bool attr_set = false;
    if (!attr_set) {
        cudaFuncSetAttribute(attn_tf32, cudaFuncAttributeMaxDynamicSharedMemorySize,
                             AT_SMEM_FLOATS * (int)sizeof(float));
        attr_set = true;
    }

    // 0. trig table + QKV weight concat
    trig_kernel<<<(T_TOK * 16 + 255) / 256, 256>>>(trig);
    concat_qkv<<<(D_MODEL * QKV_N / 4 + 255) / 256, 256>>>(wq, wk, wv, bq, bk, bv, wqkv, bqkv);

    // 1. LN1
    ln_kernel<<<M_ROWS, 256>>>(hs, g1, be1, ni);

    // 2. fused QKV projection
    dim3 gQKV(QKV_N / 128, M_ROWS / 128);
    gemm_tf32<false><<<gQKV, 256>>>(ni, wqkv, bqkv, nullptr, qkv, M_ROWS, QKV_N, D_MODEL);

    // 3. RoPE (table lookup)
    {
        int total = BATCH * T_TOK * N_HEADS * 16;
        rope_apply<<<(total + 255) / 256, 256>>>(qkv, trig);
    }

    // 4. attention
    {
        dim3 ga(T_TOK / 64, N_HEADS, BATCH);
        attn_tf32<<<ga, 256, AT_SMEM_FLOATS * (int)sizeof(float)>>>(qkv, ab, attn);
    }

    // 5. out-proj + residual(hs)
    dim3 gP(D_MODEL / 128, M_ROWS / 128);
    gemm_tf32<false><<<gP, 256>>>(attn, wo, bo, hs, res1, M_ROWS, D_MODEL, D_MODEL);

    // 6. LN3
    ln_kernel<<<M_ROWS, 256>>>(res1, g3, be3, ffin);

    // 7. FFN1 + exact GELU
    dim3 gF1(FFN_DIM / 128, M_ROWS / 128);
    gemm_tf32<true><<<gF1, 256>>>(ffin, w1, b1, nullptr, hbuf, M_ROWS, FFN_DIM, D_MODEL);

    // 8. FFN2 + residual(res1) -> out
    gemm_tf32<false><<<gP, 256>>>(hbuf, w2, b2, res1, out, M_ROWS, D_MODEL, FFN_DIM);
}

// round 7
// speedup vs baseline: 1.2288x; 1.1420x over previous
#include <cuda_runtime.h>
#include <cuda_bf16.h>
#include <math.h>

#define D_MODEL 768
#define N_HEADS 12
#define HEAD_DIM 64
#define FFN_DIM 3072
#define T_TOK 2048
#define BATCH 2
#define M_ROWS (BATCH * T_TOK)   // 4096
#define QKV_N 2304               // 3 * D_MODEL

// -------------------- scratch ---------------------------------------------
__device__ float g_ni[M_ROWS * D_MODEL];
__device__ float g_qkv[M_ROWS * QKV_N];
__device__ float g_wqkv[D_MODEL * QKV_N];
__device__ float g_bqkv[QKV_N];
__device__ float g_attn[M_ROWS * D_MODEL];
__device__ float g_res1[M_ROWS * D_MODEL];
__device__ float g_ffin[M_ROWS * D_MODEL];
__device__ float g_h[M_ROWS * FFN_DIM];
__device__ float g_trig[T_TOK * 16 * 2];

// -------------------- async copy helpers ----------------------------------
__device__ __forceinline__ void cp16(void* smem_dst, const void* gptr) {
    unsigned a = (unsigned)__cvta_generic_to_shared(smem_dst);
    asm volatile("cp.async.cg.shared.global [%0], [%1], 16;" :: "r"(a), "l"(gptr));
}
__device__ __forceinline__ void cp_commit() { asm volatile("cp.async.commit_group;"); }
template <int NN>
__device__ __forceinline__ void cp_wait() { asm volatile("cp.async.wait_group %0;" :: "n"(NN)); }

__device__ __forceinline__ void mma_tf32(float* c, const unsigned* a, const unsigned* b) {
    asm volatile(
        "mma.sync.aligned.m16n8k8.row.col.f32.tf32.tf32.f32 "
        "{%0,%1,%2,%3}, {%4,%5,%6,%7}, {%8,%9}, {%0,%1,%2,%3};"
        : "+f"(c[0]), "+f"(c[1]), "+f"(c[2]), "+f"(c[3])
        : "r"(a[0]), "r"(a[1]), "r"(a[2]), "r"(a[3]), "r"(b[0]), "r"(b[1]));
}

// -------------------- block reduction -------------------------------------
__device__ __forceinline__ float block_sum_256(float val) {
    __shared__ float red[8];
    int lane = threadIdx.x & 31, w = threadIdx.x >> 5;
#pragma unroll
    for (int o = 16; o; o >>= 1) val += __shfl_xor_sync(0xffffffffu, val, o);
    if (lane == 0) red[w] = val;
    __syncthreads();
    if (w == 0) {
        float t = (lane < 8) ? red[lane] : 0.f;
#pragma unroll
        for (int o = 4; o; o >>= 1) t += __shfl_xor_sync(0xffffffffu, t, o);
        if (lane == 0) red[0] = t;
    }
    __syncthreads();
    float r = red[0];
    __syncthreads();
    return r;
}

// -------------------- LayerNorm -------------------------------------------
__global__ void ln_kernel(const float* __restrict__ x, const float* __restrict__ g,
                          const float* __restrict__ bta, float* __restrict__ y) {
    size_t row = blockIdx.x;
    int tid = threadIdx.x;
    const float* xr = x + row * D_MODEL;
    float v0 = xr[tid], v1 = xr[tid + 256], v2 = xr[tid + 512];
    float mu = block_sum_256(v0 + v1 + v2) * (1.f / 768.f);
    float d0 = v0 - mu, d1 = v1 - mu, d2 = v2 - mu;
    float var = block_sum_256(d0 * d0 + d1 * d1 + d2 * d2) * (1.f / 768.f);
    float rs = rsqrtf(var + 1e-5f);
    float* yr = y + row * D_MODEL;
    yr[tid]       = d0 * rs * g[tid]       + bta[tid];
    yr[tid + 256] = d1 * rs * g[tid + 256] + bta[tid + 256];
    yr[tid + 512] = d2 * rs * g[tid + 512] + bta[tid + 512];
}

// -------------------- QKV weight/bias concat (q scaled by 0.125) ----------
__global__ void concat_qkv(const float* __restrict__ wq, const float* __restrict__ wk,
                           const float* __restrict__ wv, const float* __restrict__ bq,
                           const float* __restrict__ bk, const float* __restrict__ bv,
                           float* __restrict__ W, float* __restrict__ Bo) {
    int idx = blockIdx.x * 256 + threadIdx.x;
    const int total = D_MODEL * QKV_N / 4;
    if (idx < total) {
        int e = idx * 4;
        int k = e / QKV_N, j = e % QKV_N;
        float4 v;
        if (j < 768) {
            v = *(const float4*)(wq + (size_t)k * 768 + j);
            v.x *= 0.125f; v.y *= 0.125f; v.z *= 0.125f; v.w *= 0.125f;
        } else if (j < 1536) {
            v = *(const float4*)(wk + (size_t)k * 768 + (j - 768));
        } else {
            v = *(const float4*)(wv + (size_t)k * 768 + (j - 1536));
        }
        *(float4*)(W + e) = v;
    }
    if (idx < QKV_N / 4) {
        int j = idx * 4;
        float4 v;
        if (j < 768) {
            v = *(const float4*)(bq + j);
            v.x *= 0.125f; v.y *= 0.125f; v.z *= 0.125f; v.w *= 0.125f;
        } else if (j < 1536) {
            v = *(const float4*)(bk + (j - 768));
        } else {
            v = *(const float4*)(bv + (j - 1536));
        }
        *(float4*)(Bo + j) = v;
    }
}

// -------------------- trig table ------------------------------------------
__global__ void trig_kernel(float* __restrict__ trig) {
    int idx = blockIdx.x * 256 + threadIdx.x;
    if (idx >= T_TOK * 16) return;
    int t = idx >> 4, i = idx & 15;
    double ts = pow(10000.0, (double)i / 32.0);
    double ang = (double)t / ts;
    double sd, cd;
    sincos(ang, &sd, &cd);
    trig[idx * 2]     = (float)cd;
    trig[idx * 2 + 1] = (float)sd;
}

// -------------------- p-RoPE apply ----------------------------------------
__global__ void rope_apply(float* __restrict__ qkv, const float* __restrict__ trig) {
    int idx = blockIdx.x * blockDim.x + threadIdx.x;
    const int total = BATCH * T_TOK * N_HEADS * 16;
    if (idx >= total) return;
    int i = idx & 15;
    int h = (idx >> 4) % N_HEADS;
    int t = (idx / (16 * N_HEADS)) % T_TOK;
    int b = idx / (16 * N_HEADS * T_TOK);
    size_t base = ((size_t)(b * T_TOK + t)) * QKV_N + h * HEAD_DIM + i;
    float cf = trig[(t * 16 + i) * 2];
    float sf = trig[(t * 16 + i) * 2 + 1];
    float x1 = qkv[base], x2 = qkv[base + 32];
    qkv[base]      = x1 * cf - x2 * sf;
    qkv[base + 32] = x2 * cf + x1 * sf;
    x1 = qkv[base + 768]; x2 = qkv[base + 800];
    qkv[base + 768] = x1 * cf - x2 * sf;
    qkv[base + 800] = x2 * cf + x1 * sf;
}

// -------------------- tf32 GEMM 128x128: BK=16, 2-stage, one sync ---------
#define AS_STRIDE 20
#define BS_STRIDE 136

template <bool GELU>
__global__ __launch_bounds__(256, 2)
void gemm_tf32(const float* __restrict__ A, const float* __restrict__ Bm,
               const float* __restrict__ bias, const float* __restrict__ res,
               float* __restrict__ C, int M, int N, int K) {
    __shared__ unsigned As[2][128 * AS_STRIDE];
    __shared__ unsigned Bs[2][16 * BS_STRIDE];
    int tid = threadIdx.x;
    int wid = tid >> 5, lane = tid & 31;
    int g = lane >> 2, tig = lane & 3;
    int wm = wid & 3, wn = wid >> 2;
    int brow = blockIdx.y * 128, bcol = blockIdx.x * 128;

    int ar = tid >> 2, ac = (tid & 3) * 4;
    int br = tid >> 5, bc = (tid & 31) * 4;
    const float* Ap = A + (size_t)(brow + ar) * K + ac;
    const float* Bp = Bm + (size_t)br * N + bcol + bc;

    int nIter = K >> 4;

#define GEMM_ISSUE(KT, STG) do {                                              \
        const float* a0_ = Ap + (KT) * 16;                                    \
        cp16(&As[STG][ar * AS_STRIDE + ac], a0_);                             \
        cp16(&As[STG][(ar + 64) * AS_STRIDE + ac], a0_ + (size_t)64 * K);     \
        const float* b0_ = Bp + (size_t)(KT) * 16 * N;                        \
        cp16(&Bs[STG][br * BS_STRIDE + bc], b0_);                             \
        cp16(&Bs[STG][(br + 8) * BS_STRIDE + bc], b0_ + (size_t)8 * N);       \
        cp_commit();                                                           \
    } while (0)

    GEMM_ISSUE(0, 0);

    float acc[2][8][4];
#pragma unroll
    for (int i = 0; i < 2; i++)
#pragma unroll
        for (int j = 0; j < 8; j++)
#pragma unroll
            for (int r = 0; r < 4; r++) acc[i][j][r] = 0.f;

    for (int kt = 0; kt < nIter; ++kt) {
        int cur = kt & 1;
        cp_wait<0>();
        __syncthreads();
        if (kt + 1 < nIter) GEMM_ISSUE(kt + 1, cur ^ 1);
#pragma unroll
        for (int ks = 0; ks < 16; ks += 8) {
            unsigned af[2][4];
#pragma unroll
            for (int mt = 0; mt < 2; mt++) {
                int r0 = wm * 32 + mt * 16 + g;
                af[mt][0] = As[cur][r0 * AS_STRIDE + ks + tig];
                af[mt][1] = As[cur][(r0 + 8) * AS_STRIDE + ks + tig];
                af[mt][2] = As[cur][r0 * AS_STRIDE + ks + tig + 4];
                af[mt][3] = As[cur][(r0 + 8) * AS_STRIDE + ks + tig + 4];
            }
#pragma unroll
            for (int nt = 0; nt < 8; nt++) {
                unsigned bf[2];
                int c0 = wn * 64 + nt * 8 + g;
                bf[0] = Bs[cur][(ks + tig) * BS_STRIDE + c0];
                bf[1] = Bs[cur][(ks + tig + 4) * BS_STRIDE + c0];
                mma_tf32(acc[0][nt], af[0], bf);
                mma_tf32(acc[1][nt], af[1], bf);
            }
        }
    }
#undef GEMM_ISSUE

#pragma unroll
    for (int mt = 0; mt < 2; mt++) {
        int row0 = brow + wm * 32 + mt * 16 + g;
#pragma unroll
        for (int nt = 0; nt < 8; nt++) {
            int col = bcol + wn * 64 + nt * 8 + tig * 2;
            float b0 = bias[col], b1 = bias[col + 1];
            float v00 = acc[mt][nt][0] + b0;
            float v01 = acc[mt][nt][1] + b1;
            float v10 = acc[mt][nt][2] + b0;
            float v11 = acc[mt][nt][3] + b1;
            if (GELU) {
                v00 *= normcdff(v00); v01 *= normcdff(v01);
                v10 *= normcdff(v10); v11 *= normcdff(v11);
            }
            if (res) {
                const float* r0p = res + (size_t)row0 * N + col;
                const float* r1p = res + (size_t)(row0 + 8) * N + col;
                v00 += r0p[0]; v01 += r0p[1];
                v10 += r1p[0]; v11 += r1p[1];
            }
            *(float2*)(C + (size_t)row0 * N + col) = make_float2(v00, v01);
            *(float2*)(C + (size_t)(row0 + 8) * N + col) = make_float2(v10, v11);
        }
    }
}

// -------------------- tf32 GEMM 64x128: for N=768 GEMMs (more blocks) -----
template <bool GELU>
__global__ __launch_bounds__(256, 3)
void gemm_tf32_m64(const float* __restrict__ A, const float* __restrict__ Bm,
                   const float* __restrict__ bias, const float* __restrict__ res,
                   float* __restrict__ C, int M, int N, int K) {
    __shared__ unsigned As[2][64 * AS_STRIDE];
    __shared__ unsigned Bs[2][16 * BS_STRIDE];
    int tid = threadIdx.x;
    int wid = tid >> 5, lane = tid & 31;
    int g = lane >> 2, tig = lane & 3;
    int wm = wid & 1, wn = wid >> 1;          // warp grid 2m x 4n, tile 32x32
    int brow = blockIdx.y * 64, bcol = blockIdx.x * 128;

    int ar = tid >> 2, ac = (tid & 3) * 4;    // 64 rows x 16 cols, 1 cp16/thread
    int br = tid >> 5, bc = (tid & 31) * 4;
    const float* Ap = A + (size_t)(brow + ar) * K + ac;
    const float* Bp = Bm + (size_t)br * N + bcol + bc;

    int nIter = K >> 4;

#define GEMM_ISSUE64(KT, STG) do {                                            \
        cp16(&As[STG][ar * AS_STRIDE + ac], Ap + (KT) * 16);                  \
        const float* b0_ = Bp + (size_t)(KT) * 16 * N;                        \
        cp16(&Bs[STG][br * BS_STRIDE + bc], b0_);                             \
        cp16(&Bs[STG][(br + 8) * BS_STRIDE + bc], b0_ + (size_t)8 * N);       \
        cp_commit();                                                           \
    } while (0)

    GEMM_ISSUE64(0, 0);

    float acc[2][4][4];
#pragma unroll
    for (int i = 0; i < 2; i++)
#pragma unroll
        for (int j = 0; j < 4; j++)
#pragma unroll
            for (int r = 0; r < 4; r++) acc[i][j][r] = 0.f;

    for (int kt = 0; kt < nIter; ++kt) {
        int cur = kt & 1;
        cp_wait<0>();
        __syncthreads();
        if (kt + 1 < nIter) GEMM_ISSUE64(kt + 1, cur ^ 1);
#pragma unroll
        for (int ks = 0; ks < 16; ks += 8) {
            unsigned af[2][4];
#pragma unroll
            for (int mt = 0; mt < 2; mt++) {
                int r0 = wm * 32 + mt * 16 + g;
                af[mt][0] = As[cur][r0 * AS_STRIDE + ks + tig];
                af[mt][1] = As[cur][(r0 + 8) * AS_STRIDE + ks + tig];
                af[mt][2] = As[cur][r0 * AS_STRIDE + ks + tig + 4];
                af[mt][3] = As[cur][(r0 + 8) * AS_STRIDE + ks + tig + 4];
            }
#pragma unroll
            for (int nt = 0; nt < 4; nt++) {
                unsigned bf[2];
                int c0 = wn * 32 + nt * 8 + g;
                bf[0] = Bs[cur][(ks + tig) * BS_STRIDE + c0];
                bf[1] = Bs[cur][(ks + tig + 4) * BS_STRIDE + c0];
                mma_tf32(acc[0][nt], af[0], bf);
                mma_tf32(acc[1][nt], af[1], bf);
            }
        }
    }
#undef GEMM_ISSUE64

#pragma unroll
    for (int mt = 0; mt < 2; mt++) {
        int row0 = brow + wm * 32 + mt * 16 + g;
#pragma unroll
        for (int nt = 0; nt < 4; nt++) {
            int col = bcol + wn * 32 + nt * 8 + tig * 2;
            float b0 = bias[col], b1 = bias[col + 1];
            float v00 = acc[mt][nt][0] + b0;
            float v01 = acc[mt][nt][1] + b1;
            float v10 = acc[mt][nt][2] + b0;
            float v11 = acc[mt][nt][3] + b1;
            if (GELU) {
                v00 *= normcdff(v00); v01 *= normcdff(v01);
                v10 *= normcdff(v10); v11 *= normcdff(v11);
            }
            if (res) {
                const float* r0p = res + (size_t)row0 * N + col;
                const float* r1p = res + (size_t)(row0 + 8) * N + col;
                v00 += r0p[0]; v01 += r0p[1];
                v10 += r1p[0]; v11 += r1p[1];
            }
            *(float2*)(C + (size_t)row0 * N + col) = make_float2(v00, v01);
            *(float2*)(C + (size_t)(row0 + 8) * N + col) = make_float2(v10, v11);
        }
    }
}

// -------------------- flash attention: BM=128, staggered K/V prefetch -----
#define QS_STRIDE 68
#define KS_STRIDE 76
#define VS_STRIDE 72
#define SC_STRIDE 68
#define AT_SMEM_FLOATS (128*QS_STRIDE + 64*KS_STRIDE + 64*VS_STRIDE + 128*SC_STRIDE + 384)

__global__ __launch_bounds__(256, 2)
void attn_tf32(const float* __restrict__ QKV, const float* __restrict__ ab,
               float* __restrict__ O) {
    extern __shared__ float sm[];
    unsigned* Qs = (unsigned*)sm;                    // [128][68]
    unsigned* Ks = Qs + 128 * QS_STRIDE;             // [64][76]
    unsigned* Vs = Ks + 64 * KS_STRIDE;              // [64][72]
    float* Sc = (float*)(Vs + 64 * VS_STRIDE);       // [128][68]
    float* mrow = Sc + 128 * SC_STRIDE;
    float* lrow = mrow + 128;
    float* srow = lrow + 128;
    unsigned* Scu = (unsigned*)Sc;

    int tid = threadIdx.x;
    int wid = tid >> 5, lane = tid & 31;
    int g = lane >> 2, tig = lane & 3;
    int wm = wid >> 1, wn = wid & 1;          // 4m x 2n, warp tile 32 rows x 32 cols
    int m0 = wm * 32, n0 = wn * 32;

    int qb = blockIdx.x * 128;
    int h = blockIdx.y, b = blockIdx.z;
    size_t bh = (size_t)b * T_TOK * QKV_N + h * HEAD_DIM;
    const float* qp = QKV + bh;
    const float* kp = QKV + bh + 768;
    const float* vp = QKV + bh + 1536;

#define K_ISSUE(KT) do {                                                      \
        int kb_ = (KT) * 64;                                                  \
        _Pragma("unroll")                                                     \
        for (int it = 0; it < 4; it++) {                                      \
            int idx_ = tid + it * 256;                                        \
            int r_ = idx_ >> 4, c4_ = (idx_ & 15) * 4;                        \
            cp16(&Ks[r_ * KS_STRIDE + c4_], kp + (size_t)(kb_ + r_) * QKV_N + c4_); \
        }                                                                     \
        cp_commit();                                                          \
    } while (0)
#define V_ISSUE(KT) do {                                                      \
        int kb_ = (KT) * 64;                                                  \
        _Pragma("unroll")                                                     \
        for (int it = 0; it < 4; it++) {                                      \
            int idx_ = tid + it * 256;                                        \
            int r_ = idx_ >> 4, c4_ = (idx_ & 15) * 4;                        \
            cp16(&Vs[r_ * VS_STRIDE + c4_], vp + (size_t)(kb_ + r_) * QKV_N + c4_); \
        }                                                                     \
        cp_commit();                                                          \
    } while (0)

    // prologue: Q (8/thread), K0, V0
#pragma unroll
    for (int it = 0; it < 8; it++) {
        int idx = tid + it * 256;
        int r = idx >> 4, c4 = (idx & 15) * 4;
        cp16(&Qs[r * QS_STRIDE + c4], qp + (size_t)(qb + r) * QKV_N + c4);
    }
    cp_commit();
    K_ISSUE(0);
    V_ISSUE(0);
    if (tid < 128) { mrow[tid] = -1e30f; lrow[tid] = 0.f; }

    float o[2][4][4];
#pragma unroll
    for (int mt = 0; mt < 2; mt++)
#pragma unroll
        for (int nt = 0; nt < 4; nt++)
#pragma unroll
            for (int r = 0; r < 4; r++) o[mt][nt][r] = 0.f;

    float bias0 = ab[h * 2 + 0], bias1 = ab[h * 2 + 1];
    int qvar = qb >> 7;

    for (int kt = 0; kt < 32; kt++) {
        // sync #1: K(kt) visible; PV(kt-1) readers of Vs/Sc all done
        cp_wait<0>();
        __syncthreads();
        if (kt > 0) V_ISSUE(kt);          // overlaps QK + softmax of this iter

        // ---- S = Q @ K^T ----
        float s[2][4][4];
#pragma unroll
        for (int mt = 0; mt < 2; mt++)
#pragma unroll
            for (int nt = 0; nt < 4; nt++)
#pragma unroll
                for (int r = 0; r < 4; r++) s[mt][nt][r] = 0.f;
#pragma unroll
        for (int ks = 0; ks < 64; ks += 8) {
            unsigned af[2][4];
#pragma unroll
            for (int mt = 0; mt < 2; mt++) {
                int r0 = m0 + mt * 16 + g;
                af[mt][0] = Qs[r0 * QS_STRIDE + ks + tig];
                af[mt][1] = Qs[(r0 + 8) * QS_STRIDE + ks + tig];
                af[mt][2] = Qs[r0 * QS_STRIDE + ks + tig + 4];
                af[mt][3] = Qs[(r0 + 8) * QS_STRIDE + ks + tig + 4];
            }
#pragma unroll
            for (int nt = 0; nt < 4; nt++) {
                unsigned bf[2];
                int c0 = n0 + nt * 8 + g;
                bf[0] = Ks[c0 * KS_STRIDE + ks + tig];
                bf[1] = Ks[c0 * KS_STRIDE + ks + tig + 4];
                mma_tf32(s[0][nt], af[0], bf);
                mma_tf32(s[1][nt], af[1], bf);
            }
        }
        float bias = (((kt * 64) >> 7) == qvar) ? bias0 : bias1;
#pragma unroll
        for (int mt = 0; mt < 2; mt++) {
            int r0 = m0 + mt * 16 + g;
#pragma unroll
            for (int nt = 0; nt < 4; nt++) {
                int col = n0 + nt * 8 + tig * 2;
                Sc[r0 * SC_STRIDE + col]     = s[mt][nt][0] + bias;
                Sc[r0 * SC_STRIDE + col + 1] = s[mt][nt][1] + bias;
                Sc[(r0 + 8) * SC_STRIDE + col]     = s[mt][nt][2] + bias;
                Sc[(r0 + 8) * SC_STRIDE + col + 1] = s[mt][nt][3] + bias;
            }
        }
        __syncthreads();                  // sync #2: Sc visible; Ks reads done
        if (kt + 1 < 32) K_ISSUE(kt + 1); // overlaps softmax + PV

        // ---- online softmax: 2 threads per row, 32 cols each ----
        {
            int r = tid >> 1, seg = tid & 1;
            float* sr = &Sc[r * SC_STRIDE + seg * 32];
            float mo = mrow[r];
            float mx = -1e30f;
#pragma unroll
            for (int j = 0; j < 32; j++) mx = fmaxf(mx, sr[j]);
            mx = fmaxf(mx, __shfl_xor_sync(0xffffffffu, mx, 1));
            mx = fmaxf(mx, mo);
            float sum = 0.f;
#pragma unroll
            for (int j = 0; j < 32; j++) {
                float p = __expf(sr[j] - mx);
                sr[j] = p;
                sum += p;
            }
            sum += __shfl_xor_sync(0xffffffffu, sum, 1);
            if (seg == 0) {
                float scl = __expf(mo - mx);
                mrow[r] = mx;
                lrow[r] = lrow[r] * scl + sum;
                srow[r] = scl;
            }
        }
        if (kt + 1 < 32) cp_wait<1>(); else cp_wait<0>();   // V(kt) done (K(kt+1) may fly)
        __syncthreads();                  // sync #3: P and V(kt) visible

        // ---- rescale + O += P @ V ----
#pragma unroll
        for (int mt = 0; mt < 2; mt++) {
            int r0 = m0 + mt * 16 + g;
            float scl0 = srow[r0], scl1 = srow[r0 + 8];
#pragma unroll
            for (int nt = 0; nt < 4; nt++) {
                o[mt][nt][0] *= scl0; o[mt][nt][1] *= scl0;
                o[mt][nt][2] *= scl1; o[mt][nt][3] *= scl1;
            }
        }
#pragma unroll
        for (int ks = 0; ks < 64; ks += 8) {
            unsigned af[2][4];
#pragma unroll
            for (int mt = 0; mt < 2; mt++) {
                int r0 = m0 + mt * 16 + g;
                af[mt][0] = Scu[r0 * SC_STRIDE + ks + tig];
                af[mt][1] = Scu[(r0 + 8) * SC_STRIDE + ks + tig];
                af[mt][2] = Scu[r0 * SC_STRIDE + ks + tig + 4];
                af[mt][3] = Scu[(r0 + 8) * SC_STRIDE + ks + tig + 4];
            }
#pragma unroll
            for (int nt = 0; nt < 4; nt++) {
                unsigned bf[2];
                int c0 = n0 + nt * 8 + g;
                bf[0] = Vs[(ks + tig) * VS_STRIDE + c0];
                bf[1] = Vs[(ks + tig + 4) * VS_STRIDE + c0];
                mma_tf32(o[0][nt], af[0], bf);
                mma_tf32(o[1][nt], af[1], bf);
            }
        }
    }
#undef K_ISSUE
#undef V_ISSUE

    // ---- normalize + write ----
#pragma unroll
    for (int mt = 0; mt < 2; mt++) {
        int r0 = m0 + mt * 16 + g;
        float inv0 = 1.f / lrow[r0], inv1 = 1.f / lrow[r0 + 8];
        int row0 = qb + r0;
#pragma unroll
        for (int nt = 0; nt < 4; nt++) {
            int col = n0 + nt * 8 + tig * 2;
            float* o0 = O + (size_t)(b * T_TOK + row0) * D_MODEL + h * HEAD_DIM + col;
            float* o1 = O + (size_t)(b * T_TOK + row0 + 8) * D_MODEL + h * HEAD_DIM + col;
            *(float2*)o0 = make_float2(o[mt][nt][0] * inv0, o[mt][nt][1] * inv0);
            *(float2*)o1 = make_float2(o[mt][nt][2] * inv1, o[mt][nt][3] * inv1);
        }
    }
}

// -------------------- launch ----------------------------------------------
extern "C" void kernel_launch(void* const* d_in, const int* in_sizes, int n_in,
                              void* d_out, int out_size) {
    const float* hs  = (const float*)d_in[0];
    const float* wq  = (const float*)d_in[1];
    const float* bq  = (const float*)d_in[2];
    const float* wk  = (const float*)d_in[3];
    const float* bk  = (const float*)d_in[4];
    const float* wv  = (const float*)d_in[5];
    const float* bv  = (const float*)d_in[6];
    const float* wo  = (const float*)d_in[7];
    const float* bo  = (const float*)d_in[8];
    const float* ab  = (const float*)d_in[9];
    const float* g1  = (const float*)d_in[10];
    const float* be1 = (const float*)d_in[11];
    const float* g3  = (const float*)d_in[12];
    const float* be3 = (const float*)d_in[13];
    const float* w1  = (const float*)d_in[14];
    const float* b1  = (const float*)d_in[15];
    const float* w2  = (const float*)d_in[16];
    const float* b2  = (const float*)d_in[17];
    float* out = (float*)d_out;

    float *ni, *qkv, *wqkv, *bqkv, *attn, *res1, *ffin, *hbuf, *trig;
    cudaGetSymbolAddress((void**)&ni,   g_ni);
    cudaGetSymbolAddress((void**)&qkv,  g_qkv);
    cudaGetSymbolAddress((void**)&wqkv, g_wqkv);
    cudaGetSymbolAddress((void**)&bqkv, g_bqkv);
    cudaGetSymbolAddress((void**)&attn, g_attn);
    cudaGetSymbolAddress((void**)&res1, g_res1);
    cudaGetSymbolAddress((void**)&ffin, g_ffin);
    cudaGetSymbolAddress((void**)&hbuf, g_h);
    cudaGetSymbolAddress((void**)&trig, g_trig);

    static bool attr_set = false;
    if (!attr_set) {
        cudaFuncSetAttribute(attn_tf32, cudaFuncAttributeMaxDynamicSharedMemorySize,
                             AT_SMEM_FLOATS * (int)sizeof(float));
        attr_set = true;
    }

    // 0. trig table + QKV weight concat
    trig_kernel<<<(T_TOK * 16 + 255) / 256, 256>>>(trig);
    concat_qkv<<<(D_MODEL * QKV_N / 4 + 255) / 256, 256>>>(wq, wk, wv, bq, bk, bv, wqkv, bqkv);

    // 1. LN1
    ln_kernel<<<M_ROWS, 256>>>(hs, g1, be1, ni);

    // 2. fused QKV projection
    dim3 gQKV(QKV_N / 128, M_ROWS / 128);
    gemm_tf32<false><<<gQKV, 256>>>(ni, wqkv, bqkv, nullptr, qkv, M_ROWS, QKV_N, D_MODEL);

    // 3. RoPE
    {
        int total = BATCH * T_TOK * N_HEADS * 16;
        rope_apply<<<(total + 255) / 256, 256>>>(qkv, trig);
    }

    // 4. attention (BM=128)
    {
        dim3 ga(T_TOK / 128, N_HEADS, BATCH);
        attn_tf32<<<ga, 256, AT_SMEM_FLOATS * (int)sizeof(float)>>>(qkv, ab, attn);
    }

    // 5. out-proj + residual(hs)  (M64 variant: 384 blocks)
    dim3 gP64(D_MODEL / 128, M_ROWS / 64);
    gemm_tf32_m64<false><<<gP64, 256>>>(attn, wo, bo, hs, res1, M_ROWS, D_MODEL, D_MODEL);

    // 6. LN3
    ln_kernel<<<M_ROWS, 256>>>(res1, g3, be3, ffin);

    // 7. FFN1 + exact GELU
    dim3 gF1(FFN_DIM / 128, M_ROWS / 128);
    gemm_tf32<true><<<gF1, 256>>>(ffin, w1, b1, nullptr, hbuf, M_ROWS, FFN_DIM, D_MODEL);

    // 8. FFN2 + residual(res1) -> out  (M64 variant)
    gemm_tf32_m64<false><<<gP64, 256>>>(hbuf, w2, b2, res1, out, M_ROWS, D_MODEL, FFN_DIM);
}

// round 8
// speedup vs baseline: 1.2350x; 1.0051x over previous
#include <cuda_runtime.h>
#include <cuda_bf16.h>
#include <math.h>

#define D_MODEL 768
#define N_HEADS 12
#define HEAD_DIM 64
#define FFN_DIM 3072
#define T_TOK 2048
#define BATCH 2
#define M_ROWS (BATCH * T_TOK)   // 4096
#define QKV_N 2304               // 3 * D_MODEL

// -------------------- scratch ---------------------------------------------
__device__ float g_ni[M_ROWS * D_MODEL];
__device__ float g_qkv[M_ROWS * QKV_N];
__device__ float g_wqkv[D_MODEL * QKV_N];
__device__ float g_bqkv[QKV_N];
__device__ float g_attn[M_ROWS * D_MODEL];
__device__ float g_res1[M_ROWS * D_MODEL];
__device__ float g_ffin[M_ROWS * D_MODEL];
__device__ float g_h[M_ROWS * FFN_DIM];
__device__ float g_trig[T_TOK * 16 * 2];

// -------------------- async copy helpers ----------------------------------
__device__ __forceinline__ void cp16(void* smem_dst, const void* gptr) {
    unsigned a = (unsigned)__cvta_generic_to_shared(smem_dst);
    asm volatile("cp.async.cg.shared.global [%0], [%1], 16;" :: "r"(a), "l"(gptr));
}
__device__ __forceinline__ void cp_commit() { asm volatile("cp.async.commit_group;"); }
template <int NN>
__device__ __forceinline__ void cp_wait() { asm volatile("cp.async.wait_group %0;" :: "n"(NN)); }

__device__ __forceinline__ void mma_tf32(float* c, const unsigned* a, const unsigned* b) {
    asm volatile(
        "mma.sync.aligned.m16n8k8.row.col.f32.tf32.tf32.f32 "
        "{%0,%1,%2,%3}, {%4,%5,%6,%7}, {%8,%9}, {%0,%1,%2,%3};"
        : "+f"(c[0]), "+f"(c[1]), "+f"(c[2]), "+f"(c[3])
        : "r"(a[0]), "r"(a[1]), "r"(a[2]), "r"(a[3]), "r"(b[0]), "r"(b[1]));
}

// -------------------- block reduction -------------------------------------
__device__ __forceinline__ float block_sum_256(float val) {
    __shared__ float red[8];
    int lane = threadIdx.x & 31, w = threadIdx.x >> 5;
#pragma unroll
    for (int o = 16; o; o >>= 1) val += __shfl_xor_sync(0xffffffffu, val, o);
    if (lane == 0) red[w] = val;
    __syncthreads();
    if (w == 0) {
        float t = (lane < 8) ? red[lane] : 0.f;
#pragma unroll
        for (int o = 4; o; o >>= 1) t += __shfl_xor_sync(0xffffffffu, t, o);
        if (lane == 0) red[0] = t;
    }
    __syncthreads();
    float r = red[0];
    __syncthreads();
    return r;
}

// -------------------- LayerNorm -------------------------------------------
__global__ void ln_kernel(const float* __restrict__ x, const float* __restrict__ g,
                          const float* __restrict__ bta, float* __restrict__ y) {
    size_t row = blockIdx.x;
    int tid = threadIdx.x;
    const float* xr = x + row * D_MODEL;
    float v0 = xr[tid], v1 = xr[tid + 256], v2 = xr[tid + 512];
    float mu = block_sum_256(v0 + v1 + v2) * (1.f / 768.f);
    float d0 = v0 - mu, d1 = v1 - mu, d2 = v2 - mu;
    float var = block_sum_256(d0 * d0 + d1 * d1 + d2 * d2) * (1.f / 768.f);
    float rs = rsqrtf(var + 1e-5f);
    float* yr = y + row * D_MODEL;
    yr[tid]       = d0 * rs * g[tid]       + bta[tid];
    yr[tid + 256] = d1 * rs * g[tid + 256] + bta[tid + 256];
    yr[tid + 512] = d2 * rs * g[tid + 512] + bta[tid + 512];
}

// -------------------- QKV weight/bias concat (q scaled by 0.125) ----------
__global__ void concat_qkv(const float* __restrict__ wq, const float* __restrict__ wk,
                           const float* __restrict__ wv, const float* __restrict__ bq,
                           const float* __restrict__ bk, const float* __restrict__ bv,
                           float* __restrict__ W, float* __restrict__ Bo) {
    int idx = blockIdx.x * 256 + threadIdx.x;
    const int total = D_MODEL * QKV_N / 4;
    if (idx < total) {
        int e = idx * 4;
        int k = e / QKV_N, j = e % QKV_N;
        float4 v;
        if (j < 768) {
            v = *(const float4*)(wq + (size_t)k * 768 + j);
            v.x *= 0.125f; v.y *= 0.125f; v.z *= 0.125f; v.w *= 0.125f;
        } else if (j < 1536) {
            v = *(const float4*)(wk + (size_t)k * 768 + (j - 768));
        } else {
            v = *(const float4*)(wv + (size_t)k * 768 + (j - 1536));
        }
        *(float4*)(W + e) = v;
    }
    if (idx < QKV_N / 4) {
        int j = idx * 4;
        float4 v;
        if (j < 768) {
            v = *(const float4*)(bq + j);
            v.x *= 0.125f; v.y *= 0.125f; v.z *= 0.125f; v.w *= 0.125f;
        } else if (j < 1536) {
            v = *(const float4*)(bk + (j - 768));
        } else {
            v = *(const float4*)(bv + (j - 1536));
        }
        *(float4*)(Bo + j) = v;
    }
}

// -------------------- trig table ------------------------------------------
__global__ void trig_kernel(float* __restrict__ trig) {
    int idx = blockIdx.x * 256 + threadIdx.x;
    if (idx >= T_TOK * 16) return;
    int t = idx >> 4, i = idx & 15;
    double ts = pow(10000.0, (double)i / 32.0);
    double ang = (double)t / ts;
    double sd, cd;
    sincos(ang, &sd, &cd);
    trig[idx * 2]     = (float)cd;
    trig[idx * 2 + 1] = (float)sd;
}

// -------------------- p-RoPE apply ----------------------------------------
__global__ void rope_apply(float* __restrict__ qkv, const float* __restrict__ trig) {
    int idx = blockIdx.x * blockDim.x + threadIdx.x;
    const int total = BATCH * T_TOK * N_HEADS * 16;
    if (idx >= total) return;
    int i = idx & 15;
    int h = (idx >> 4) % N_HEADS;
    int t = (idx / (16 * N_HEADS)) % T_TOK;
    int b = idx / (16 * N_HEADS * T_TOK);
    size_t base = ((size_t)(b * T_TOK + t)) * QKV_N + h * HEAD_DIM + i;
    float cf = trig[(t * 16 + i) * 2];
    float sf = trig[(t * 16 + i) * 2 + 1];
    float x1 = qkv[base], x2 = qkv[base + 32];
    qkv[base]      = x1 * cf - x2 * sf;
    qkv[base + 32] = x2 * cf + x1 * sf;
    x1 = qkv[base + 768]; x2 = qkv[base + 800];
    qkv[base + 768] = x1 * cf - x2 * sf;
    qkv[base + 800] = x2 * cf + x1 * sf;
}

// -------------------- tf32 GEMM 128x128: BK=16, 3-stage, one sync ---------
#define AS_STRIDE 20
#define BS_STRIDE 136
#define AS_SZ (128 * AS_STRIDE)
#define BS_SZ (16 * BS_STRIDE)
#define G128_SMEM_BYTES (3 * (AS_SZ + BS_SZ) * 4)     // 56832
#define AS64_SZ (64 * AS_STRIDE)
#define G64_SMEM_BYTES (3 * (AS64_SZ + BS_SZ) * 4)    // 41472

template <bool GELU>
__global__ __launch_bounds__(256, 2)
void gemm_tf32(const float* __restrict__ A, const float* __restrict__ Bm,
               const float* __restrict__ bias, const float* __restrict__ res,
               float* __restrict__ C, int M, int N, int K) {
    extern __shared__ unsigned gsm[];
    unsigned* AsB = gsm;                       // 3 stages of [128][20]
    unsigned* BsB = gsm + 3 * AS_SZ;           // 3 stages of [16][136]
    int tid = threadIdx.x;
    int wid = tid >> 5, lane = tid & 31;
    int g = lane >> 2, tig = lane & 3;
    int wm = wid & 3, wn = wid >> 2;
    int brow = blockIdx.y * 128, bcol = blockIdx.x * 128;

    int ar = tid >> 2, ac = (tid & 3) * 4;
    int br = tid >> 5, bc = (tid & 31) * 4;
    const float* Ap = A + (size_t)(brow + ar) * K + ac;
    const float* Bp = Bm + (size_t)br * N + bcol + bc;

    int nIter = K >> 4;

#define GEMM_ISSUE(KT, STG) do {                                              \
        const float* a0_ = Ap + (KT) * 16;                                    \
        unsigned* asd_ = AsB + (STG) * AS_SZ;                                 \
        cp16(&asd_[ar * AS_STRIDE + ac], a0_);                                \
        cp16(&asd_[(ar + 64) * AS_STRIDE + ac], a0_ + (size_t)64 * K);        \
        const float* b0_ = Bp + (size_t)(KT) * 16 * N;                        \
        unsigned* bsd_ = BsB + (STG) * BS_SZ;                                 \
        cp16(&bsd_[br * BS_STRIDE + bc], b0_);                                \
        cp16(&bsd_[(br + 8) * BS_STRIDE + bc], b0_ + (size_t)8 * N);          \
        cp_commit();                                                           \
    } while (0)

    GEMM_ISSUE(0, 0);
    GEMM_ISSUE(1, 1);

    float acc[2][8][4];
#pragma unroll
    for (int i = 0; i < 2; i++)
#pragma unroll
        for (int j = 0; j < 8; j++)
#pragma unroll
            for (int r = 0; r < 4; r++) acc[i][j][r] = 0.f;

    int cur = 0, nxt = 2;
    for (int kt = 0; kt < nIter; ++kt) {
        if (kt + 1 < nIter) cp_wait<1>(); else cp_wait<0>();
        __syncthreads();
        // sync proves all threads finished reading the buffer nxt (used in kt-1)
        if (kt + 2 < nIter) GEMM_ISSUE(kt + 2, nxt);
        const unsigned* As = AsB + cur * AS_SZ;
        const unsigned* Bs = BsB + cur * BS_SZ;
#pragma unroll
        for (int ks = 0; ks < 16; ks += 8) {
            unsigned af[2][4];
#pragma unroll
            for (int mt = 0; mt < 2; mt++) {
                int r0 = wm * 32 + mt * 16 + g;
                af[mt][0] = As[r0 * AS_STRIDE + ks + tig];
                af[mt][1] = As[(r0 + 8) * AS_STRIDE + ks + tig];
                af[mt][2] = As[r0 * AS_STRIDE + ks + tig + 4];
                af[mt][3] = As[(r0 + 8) * AS_STRIDE + ks + tig + 4];
            }
#pragma unroll
            for (int nt = 0; nt < 8; nt++) {
                unsigned bf[2];
                int c0 = wn * 64 + nt * 8 + g;
                bf[0] = Bs[(ks + tig) * BS_STRIDE + c0];
                bf[1] = Bs[(ks + tig + 4) * BS_STRIDE + c0];
                mma_tf32(acc[0][nt], af[0], bf);
                mma_tf32(acc[1][nt], af[1], bf);
            }
        }
        cur = cur + 1; if (cur == 3) cur = 0;
        nxt = nxt + 1; if (nxt == 3) nxt = 0;
    }
#undef GEMM_ISSUE

#pragma unroll
    for (int mt = 0; mt < 2; mt++) {
        int row0 = brow + wm * 32 + mt * 16 + g;
#pragma unroll
        for (int nt = 0; nt < 8; nt++) {
            int col = bcol + wn * 64 + nt * 8 + tig * 2;
            float b0 = bias[col], b1 = bias[col + 1];
            float v00 = acc[mt][nt][0] + b0;
            float v01 = acc[mt][nt][1] + b1;
            float v10 = acc[mt][nt][2] + b0;
            float v11 = acc[mt][nt][3] + b1;
            if (GELU) {
                v00 *= normcdff(v00); v01 *= normcdff(v01);
                v10 *= normcdff(v10); v11 *= normcdff(v11);
            }
            if (res) {
                const float* r0p = res + (size_t)row0 * N + col;
                const float* r1p = res + (size_t)(row0 + 8) * N + col;
                v00 += r0p[0]; v01 += r0p[1];
                v10 += r1p[0]; v11 += r1p[1];
            }
            *(float2*)(C + (size_t)row0 * N + col) = make_float2(v00, v01);
            *(float2*)(C + (size_t)(row0 + 8) * N + col) = make_float2(v10, v11);
        }
    }
}

// -------------------- tf32 GEMM 64x128: 3-stage, one sync -----------------
template <bool GELU>
__global__ __launch_bounds__(256, 3)
void gemm_tf32_m64(const float* __restrict__ A, const float* __restrict__ Bm,
                   const float* __restrict__ bias, const float* __restrict__ res,
                   float* __restrict__ C, int M, int N, int K) {
    extern __shared__ unsigned gsm[];
    unsigned* AsB = gsm;                       // 3 stages of [64][20]
    unsigned* BsB = gsm + 3 * AS64_SZ;         // 3 stages of [16][136]
    int tid = threadIdx.x;
    int wid = tid >> 5, lane = tid & 31;
    int g = lane >> 2, tig = lane & 3;
    int wm = wid & 1, wn = wid >> 1;
    int brow = blockIdx.y * 64, bcol = blockIdx.x * 128;

    int ar = tid >> 2, ac = (tid & 3) * 4;
    int br = tid >> 5, bc = (tid & 31) * 4;
    const float* Ap = A + (size_t)(brow + ar) * K + ac;
    const float* Bp = Bm + (size_t)br * N + bcol + bc;

    int nIter = K >> 4;

#define GEMM_ISSUE64(KT, STG) do {                                            \
        cp16(&AsB[(STG) * AS64_SZ + ar * AS_STRIDE + ac], Ap + (KT) * 16);    \
        const float* b0_ = Bp + (size_t)(KT) * 16 * N;                        \
        unsigned* bsd_ = BsB + (STG) * BS_SZ;                                 \
        cp16(&bsd_[br * BS_STRIDE + bc], b0_);                                \
        cp16(&bsd_[(br + 8) * BS_STRIDE + bc], b0_ + (size_t)8 * N);          \
        cp_commit();                                                           \
    } while (0)

    GEMM_ISSUE64(0, 0);
    GEMM_ISSUE64(1, 1);

    float acc[2][4][4];
#pragma unroll
    for (int i = 0; i < 2; i++)
#pragma unroll
        for (int j = 0; j < 4; j++)
#pragma unroll
            for (int r = 0; r < 4; r++) acc[i][j][r] = 0.f;

    int cur = 0, nxt = 2;
    for (int kt = 0; kt < nIter; ++kt) {
        if (kt + 1 < nIter) cp_wait<1>(); else cp_wait<0>();
        __syncthreads();
        if (kt + 2 < nIter) GEMM_ISSUE64(kt + 2, nxt);
        const unsigned* As = AsB + cur * AS64_SZ;
        const unsigned* Bs = BsB + cur * BS_SZ;
#pragma unroll
        for (int ks = 0; ks < 16; ks += 8) {
            unsigned af[2][4];
#pragma unroll
            for (int mt = 0; mt < 2; mt++) {
                int r0 = wm * 32 + mt * 16 + g;
                af[mt][0] = As[r0 * AS_STRIDE + ks + tig];
                af[mt][1] = As[(r0 + 8) * AS_STRIDE + ks + tig];
                af[mt][2] = As[r0 * AS_STRIDE + ks + tig + 4];
                af[mt][3] = As[(r0 + 8) * AS_STRIDE + ks + tig + 4];
            }
#pragma unroll
            for (int nt = 0; nt < 4; nt++) {
                unsigned bf[2];
                int c0 = wn * 32 + nt * 8 + g;
                bf[0] = Bs[(ks + tig) * BS_STRIDE + c0];
                bf[1] = Bs[(ks + tig + 4) * BS_STRIDE + c0];
                mma_tf32(acc[0][nt], af[0], bf);
                mma_tf32(acc[1][nt], af[1], bf);
            }
        }
        cur = cur + 1; if (cur == 3) cur = 0;
        nxt = nxt + 1; if (nxt == 3) nxt = 0;
    }
#undef GEMM_ISSUE64

#pragma unroll
    for (int mt = 0; mt < 2; mt++) {
        int row0 = brow + wm * 32 + mt * 16 + g;
#pragma unroll
        for (int nt = 0; nt < 4; nt++) {
            int col = bcol + wn * 32 + nt * 8 + tig * 2;
            float b0 = bias[col], b1 = bias[col + 1];
            float v00 = acc[mt][nt][0] + b0;
            float v01 = acc[mt][nt][1] + b1;
            float v10 = acc[mt][nt][2] + b0;
            float v11 = acc[mt][nt][3] + b1;
            if (GELU) {
                v00 *= normcdff(v00); v01 *= normcdff(v01);
                v10 *= normcdff(v10); v11 *= normcdff(v11);
            }
            if (res) {
                const float* r0p = res + (size_t)row0 * N + col;
                const float* r1p = res + (size_t)(row0 + 8) * N + col;
                v00 += r0p[0]; v01 += r0p[1];
                v10 += r1p[0]; v11 += r1p[1];
            }
            *(float2*)(C + (size_t)row0 * N + col) = make_float2(v00, v01);
            *(float2*)(C + (size_t)(row0 + 8) * N + col) = make_float2(v10, v11);
        }
    }
}

// -------------------- flash attention: BM=128, staggered K/V prefetch -----
#define QS_STRIDE 68
#define KS_STRIDE 76
#define VS_STRIDE 72
#define SC_STRIDE 68
#define AT_SMEM_FLOATS (128*QS_STRIDE + 64*KS_STRIDE + 64*VS_STRIDE + 128*SC_STRIDE + 384)

__global__ __launch_bounds__(256, 2)
void attn_tf32(const float* __restrict__ QKV, const float* __restrict__ ab,
               float* __restrict__ O) {
    extern __shared__ float sm[];
    unsigned* Qs = (unsigned*)sm;
    unsigned* Ks = Qs + 128 * QS_STRIDE;
    unsigned* Vs = Ks + 64 * KS_STRIDE;
    float* Sc = (float*)(Vs + 64 * VS_STRIDE);
    float* mrow = Sc + 128 * SC_STRIDE;
    float* lrow = mrow + 128;
    float* srow = lrow + 128;
    unsigned* Scu = (unsigned*)Sc;

    int tid = threadIdx.x;
    int wid = tid >> 5, lane = tid & 31;
    int g = lane >> 2, tig = lane & 3;
    int wm = wid >> 1, wn = wid & 1;
    int m0 = wm * 32, n0 = wn * 32;

    int qb = blockIdx.x * 128;
    int h = blockIdx.y, b = blockIdx.z;
    size_t bh = (size_t)b * T_TOK * QKV_N + h * HEAD_DIM;
    const float* qp = QKV + bh;
    const float* kp = QKV + bh + 768;
    const float* vp = QKV + bh + 1536;

#define K_ISSUE(KT) do {                                                      \
        int kb_ = (KT) * 64;                                                  \
        _Pragma("unroll")                                                     \
        for (int it = 0; it < 4; it++) {                                      \
            int idx_ = tid + it * 256;                                        \
            int r_ = idx_ >> 4, c4_ = (idx_ & 15) * 4;                        \
            cp16(&Ks[r_ * KS_STRIDE + c4_], kp + (size_t)(kb_ + r_) * QKV_N + c4_); \
        }                                                                     \
        cp_commit();                                                          \
    } while (0)
#define V_ISSUE(KT) do {                                                      \
        int kb_ = (KT) * 64;                                                  \
        _Pragma("unroll")                                                     \
        for (int it = 0; it < 4; it++) {                                      \
            int idx_ = tid + it * 256;                                        \
            int r_ = idx_ >> 4, c4_ = (idx_ & 15) * 4;                        \
            cp16(&Vs[r_ * VS_STRIDE + c4_], vp + (size_t)(kb_ + r_) * QKV_N + c4_); \
        }                                                                     \
        cp_commit();                                                          \
    } while (0)

#pragma unroll
    for (int it = 0; it < 8; it++) {
        int idx = tid + it * 256;
        int r = idx >> 4, c4 = (idx & 15) * 4;
        cp16(&Qs[r * QS_STRIDE + c4], qp + (size_t)(qb + r) * QKV_N + c4);
    }
    cp_commit();
    K_ISSUE(0);
    V_ISSUE(0);
    if (tid < 128) { mrow[tid] = -1e30f; lrow[tid] = 0.f; }

    float o[2][4][4];
#pragma unroll
    for (int mt = 0; mt < 2; mt++)
#pragma unroll
        for (int nt = 0; nt < 4; nt++)
#pragma unroll
            for (int r = 0; r < 4; r++) o[mt][nt][r] = 0.f;

    float bias0 = ab[h * 2 + 0], bias1 = ab[h * 2 + 1];
    int qvar = qb >> 7;

    for (int kt = 0; kt < 32; kt++) {
        cp_wait<0>();
        __syncthreads();
        if (kt > 0) V_ISSUE(kt);

        float s[2][4][4];
#pragma unroll
        for (int mt = 0; mt < 2; mt++)
#pragma unroll
            for (int nt = 0; nt < 4; nt++)
#pragma unroll
                for (int r = 0; r < 4; r++) s[mt][nt][r] = 0.f;
#pragma unroll
        for (int ks = 0; ks < 64; ks += 8) {
            unsigned af[2][4];
#pragma unroll
            for (int mt = 0; mt < 2; mt++) {
                int r0 = m0 + mt * 16 + g;
                af[mt][0] = Qs[r0 * QS_STRIDE + ks + tig];
                af[mt][1] = Qs[(r0 + 8) * QS_STRIDE + ks + tig];
                af[mt][2] = Qs[r0 * QS_STRIDE + ks + tig + 4];
                af[mt][3] = Qs[(r0 + 8) * QS_STRIDE + ks + tig + 4];
            }
#pragma unroll
            for (int nt = 0; nt < 4; nt++) {
                unsigned bf[2];
                int c0 = n0 + nt * 8 + g;
                bf[0] = Ks[c0 * KS_STRIDE + ks + tig];
                bf[1] = Ks[c0 * KS_STRIDE + ks + tig + 4];
                mma_tf32(s[0][nt], af[0], bf);
                mma_tf32(s[1][nt], af[1], bf);
            }
        }
        float bias = (((kt * 64) >> 7) == qvar) ? bias0 : bias1;
#pragma unroll
        for (int mt = 0; mt < 2; mt++) {
            int r0 = m0 + mt * 16 + g;
#pragma unroll
            for (int nt = 0; nt < 4; nt++) {
                int col = n0 + nt * 8 + tig * 2;
                Sc[r0 * SC_STRIDE + col]     = s[mt][nt][0] + bias;
                Sc[r0 * SC_STRIDE + col + 1] = s[mt][nt][1] + bias;
                Sc[(r0 + 8) * SC_STRIDE + col]     = s[mt][nt][2] + bias;
                Sc[(r0 + 8) * SC_STRIDE + col + 1] = s[mt][nt][3] + bias;
            }
        }
        __syncthreads();
        if (kt + 1 < 32) K_ISSUE(kt + 1);

        {
            int r = tid >> 1, seg = tid & 1;
            float* sr = &Sc[r * SC_STRIDE + seg * 32];
            float mo = mrow[r];
            float mx = -1e30f;
#pragma unroll
            for (int j = 0; j < 32; j++) mx = fmaxf(mx, sr[j]);
            mx = fmaxf(mx, __shfl_xor_sync(0xffffffffu, mx, 1));
            mx = fmaxf(mx, mo);
            float sum = 0.f;
#pragma unroll
            for (int j = 0; j < 32; j++) {
                float p = __expf(sr[j] - mx);
                sr[j] = p;
                sum += p;
            }
            sum += __shfl_xor_sync(0xffffffffu, sum, 1);
            if (seg == 0) {
                float scl = __expf(mo - mx);
                mrow[r] = mx;
                lrow[r] = lrow[r] * scl + sum;
                srow[r] = scl;
            }
        }
        if (kt + 1 < 32) cp_wait<1>(); else cp_wait<0>();
        __syncthreads();

#pragma unroll
        for (int mt = 0; mt < 2; mt++) {
            int r0 = m0 + mt * 16 + g;
            float scl0 = srow[r0], scl1 = srow[r0 + 8];
#pragma unroll
            for (int nt = 0; nt < 4; nt++) {
                o[mt][nt][0] *= scl0; o[mt][nt][1] *= scl0;
                o[mt][nt][2] *= scl1; o[mt][nt][3] *= scl1;
            }
        }
#pragma unroll
        for (int ks = 0; ks < 64; ks += 8) {
            unsigned af[2][4];
#pragma unroll
            for (int mt = 0; mt < 2; mt++) {
                int r0 = m0 + mt * 16 + g;
                af[mt][0] = Scu[r0 * SC_STRIDE + ks + tig];
                af[mt][1] = Scu[(r0 + 8) * SC_STRIDE + ks + tig];
                af[mt][2] = Scu[r0 * SC_STRIDE + ks + tig + 4];
                af[mt][3] = Scu[(r0 + 8) * SC_STRIDE + ks + tig + 4];
            }
#pragma unroll
            for (int nt = 0; nt < 4; nt++) {
                unsigned bf[2];
                int c0 = n0 + nt * 8 + g;
                bf[0] = Vs[(ks + tig) * VS_STRIDE + c0];
                bf[1] = Vs[(ks + tig + 4) * VS_STRIDE + c0];
                mma_tf32(o[0][nt], af[0], bf);
                mma_tf32(o[1][nt], af[1], bf);
            }
        }
    }
#undef K_ISSUE
#undef V_ISSUE

#pragma unroll
    for (int mt = 0; mt < 2; mt++) {
        int r0 = m0 + mt * 16 + g;
        float inv0 = 1.f / lrow[r0], inv1 = 1.f / lrow[r0 + 8];
        int row0 = qb + r0;
#pragma unroll
        for (int nt = 0; nt < 4; nt++) {
            int col = n0 + nt * 8 + tig * 2;
            float* o0 = O + (size_t)(b * T_TOK + row0) * D_MODEL + h * HEAD_DIM + col;
            float* o1 = O + (size_t)(b * T_TOK + row0 + 8) * D_MODEL + h * HEAD_DIM + col;
            *(float2*)o0 = make_float2(o[mt][nt][0] * inv0, o[mt][nt][1] * inv0);
            *(float2*)o1 = make_float2(o[mt][nt][2] * inv1, o[mt][nt][3] * inv1);
        }
    }
}

// -------------------- launch ----------------------------------------------
extern "C" void kernel_launch(void* const* d_in, const int* in_sizes, int n_in,
                              void* d_out, int out_size) {
    const float* hs  = (const float*)d_in[0];
    const float* wq  = (const float*)d_in[1];
    const float* bq  = (const float*)d_in[2];
    const float* wk  = (const float*)d_in[3];
    const float* bk  = (const float*)d_in[4];
    const float* wv  = (const float*)d_in[5];
    const float* bv  = (const float*)d_in[6];
    const float* wo  = (const float*)d_in[7];
    const float* bo  = (const float*)d_in[8];
    const float* ab  = (const float*)d_in[9];
    const float* g1  = (const float*)d_in[10];
    const float* be1 = (const float*)d_in[11];
    const float* g3  = (const float*)d_in[12];
    const float* be3 = (const float*)d_in[13];
    const float* w1  = (const float*)d_in[14];
    const float* b1  = (const float*)d_in[15];
    const float* w2  = (const float*)d_in[16];
    const float* b2  = (const float*)d_in[17];
    float* out = (float*)d_out;

    float *ni, *qkv, *wqkv, *bqkv, *attn, *res1, *ffin, *hbuf, *trig;
    cudaGetSymbolAddress((void**)&ni,   g_ni);
    cudaGetSymbolAddress((void**)&qkv,  g_qkv);
    cudaGetSymbolAddress((void**)&wqkv, g_wqkv);
    cudaGetSymbolAddress((void**)&bqkv, g_bqkv);
    cudaGetSymbolAddress((void**)&attn, g_attn);
    cudaGetSymbolAddress((void**)&res1, g_res1);
    cudaGetSymbolAddress((void**)&ffin, g_ffin);
    cudaGetSymbolAddress((void**)&hbuf, g_h);
    cudaGetSymbolAddress((void**)&trig, g_trig);

    static bool attr_set = false;
    if (!attr_set) {
        cudaFuncSetAttribute(attn_tf32, cudaFuncAttributeMaxDynamicSharedMemorySize,
                             AT_SMEM_FLOATS * (int)sizeof(float));
        cudaFuncSetAttribute(gemm_tf32<false>, cudaFuncAttributeMaxDynamicSharedMemorySize,
                             G128_SMEM_BYTES);
        cudaFuncSetAttribute(gemm_tf32<true>, cudaFuncAttributeMaxDynamicSharedMemorySize,
                             G128_SMEM_BYTES);
        cudaFuncSetAttribute(gemm_tf32_m64<false>, cudaFuncAttributeMaxDynamicSharedMemorySize,
                             G64_SMEM_BYTES);
        attr_set = true;
    }

    // 0. trig table + QKV weight concat
    trig_kernel<<<(T_TOK * 16 + 255) / 256, 256>>>(trig);
    concat_qkv<<<(D_MODEL * QKV_N / 4 + 255) / 256, 256>>>(wq, wk, wv, bq, bk, bv, wqkv, bqkv);

    // 1. LN1
    ln_kernel<<<M_ROWS, 256>>>(hs, g1, be1, ni);

    // 2. fused QKV projection
    dim3 gQKV(QKV_N / 128, M_ROWS / 128);
    gemm_tf32<false><<<gQKV, 256, G128_SMEM_BYTES>>>(ni, wqkv, bqkv, nullptr, qkv, M_ROWS, QKV_N, D_MODEL);

    // 3. RoPE
    {
        int total = BATCH * T_TOK * N_HEADS * 16;
        rope_apply<<<(total + 255) / 256, 256>>>(qkv, trig);
    }

    // 4. attention (BM=128)
    {
        dim3 ga(T_TOK / 128, N_HEADS, BATCH);
        attn_tf32<<<ga, 256, AT_SMEM_FLOATS * (int)sizeof(float)>>>(qkv, ab, attn);
    }

    // 5. out-proj + residual(hs)  (M64)
    dim3 gP64(D_MODEL / 128, M_ROWS / 64);
    gemm_tf32_m64<false><<<gP64, 256, G64_SMEM_BYTES>>>(attn, wo, bo, hs, res1, M_ROWS, D_MODEL, D_MODEL);

    // 6. LN3
    ln_kernel<<<M_ROWS, 256>>>(res1, g3, be3, ffin);

    // 7. FFN1 + exact GELU
    dim3 gF1(FFN_DIM / 128, M_ROWS / 128);
    gemm_tf32<true><<<gF1, 256, G128_SMEM_BYTES>>>(ffin, w1, b1, nullptr, hbuf, M_ROWS, FFN_DIM, D_MODEL);

    // 8. FFN2 + residual(res1) -> out  (M64)
    gemm_tf32_m64<false><<<gP64, 256, G64_SMEM_BYTES>>>(hbuf, w2, b2, res1, out, M_ROWS, D_MODEL, FFN_DIM);
}

// round 9
// speedup vs baseline: 1.2482x; 1.0106x over previous
#include <cuda_runtime.h>
#include <cuda_bf16.h>
#include <math.h>

#define D_MODEL 768
#define N_HEADS 12
#define HEAD_DIM 64
#define FFN_DIM 3072
#define T_TOK 2048
#define BATCH 2
#define M_ROWS (BATCH * T_TOK)   // 4096
#define QKV_N 2304               // 3 * D_MODEL

// -------------------- scratch ---------------------------------------------
__device__ float g_ni[M_ROWS * D_MODEL];
__device__ float g_qkv[M_ROWS * QKV_N];
__device__ float g_wqkvT[QKV_N * D_MODEL];     // [2304][768]
__device__ float g_bqkv[QKV_N];
__device__ float g_woT[D_MODEL * D_MODEL];     // [768][768]
__device__ float g_w1T[FFN_DIM * D_MODEL];     // [3072][768]
__device__ float g_w2T[D_MODEL * FFN_DIM];     // [768][3072]
__device__ float g_attn[M_ROWS * D_MODEL];
__device__ float g_res1[M_ROWS * D_MODEL];
__device__ float g_ffin[M_ROWS * D_MODEL];
__device__ float g_h[M_ROWS * FFN_DIM];
__device__ float g_trig[T_TOK * 16 * 2];

// -------------------- helpers ---------------------------------------------
__device__ __forceinline__ unsigned su32(const void* p) {
    return (unsigned)__cvta_generic_to_shared(p);
}
__device__ __forceinline__ void cp16(void* smem_dst, const void* gptr) {
    asm volatile("cp.async.cg.shared.global [%0], [%1], 16;" :: "r"(su32(smem_dst)), "l"(gptr));
}
__device__ __forceinline__ void cp_commit() { asm volatile("cp.async.commit_group;"); }
template <int NN>
__device__ __forceinline__ void cp_wait() { asm volatile("cp.async.wait_group %0;" :: "n"(NN)); }

__device__ __forceinline__ void mma_tf32(float* c, const unsigned* a, const unsigned* b) {
    asm volatile(
        "mma.sync.aligned.m16n8k8.row.col.f32.tf32.tf32.f32 "
        "{%0,%1,%2,%3}, {%4,%5,%6,%7}, {%8,%9}, {%0,%1,%2,%3};"
        : "+f"(c[0]), "+f"(c[1]), "+f"(c[2]), "+f"(c[3])
        : "r"(a[0]), "r"(a[1]), "r"(a[2]), "r"(a[3]), "r"(b[0]), "r"(b[1]));
}
__device__ __forceinline__ void ldsm4(unsigned* r, unsigned addr) {
    asm volatile("ldmatrix.sync.aligned.m8n8.x4.shared.b16 {%0,%1,%2,%3}, [%4];"
                 : "=r"(r[0]), "=r"(r[1]), "=r"(r[2]), "=r"(r[3]) : "r"(addr));
}

// -------------------- block reduction -------------------------------------
__device__ __forceinline__ float block_sum_256(float val) {
    __shared__ float red[8];
    int lane = threadIdx.x & 31, w = threadIdx.x >> 5;
#pragma unroll
    for (int o = 16; o; o >>= 1) val += __shfl_xor_sync(0xffffffffu, val, o);
    if (lane == 0) red[w] = val;
    __syncthreads();
    if (w == 0) {
        float t = (lane < 8) ? red[lane] : 0.f;
#pragma unroll
        for (int o = 4; o; o >>= 1) t += __shfl_xor_sync(0xffffffffu, t, o);
        if (lane == 0) red[0] = t;
    }
    __syncthreads();
    float r = red[0];
    __syncthreads();
    return r;
}

// -------------------- LayerNorm -------------------------------------------
__global__ void ln_kernel(const float* __restrict__ x, const float* __restrict__ g,
                          const float* __restrict__ bta, float* __restrict__ y) {
    size_t row = blockIdx.x;
    int tid = threadIdx.x;
    const float* xr = x + row * D_MODEL;
    float v0 = xr[tid], v1 = xr[tid + 256], v2 = xr[tid + 512];
    float mu = block_sum_256(v0 + v1 + v2) * (1.f / 768.f);
    float d0 = v0 - mu, d1 = v1 - mu, d2 = v2 - mu;
    float var = block_sum_256(d0 * d0 + d1 * d1 + d2 * d2) * (1.f / 768.f);
    float rs = rsqrtf(var + 1e-5f);
    float* yr = y + row * D_MODEL;
    yr[tid]       = d0 * rs * g[tid]       + bta[tid];
    yr[tid + 256] = d1 * rs * g[tid + 256] + bta[tid + 256];
    yr[tid + 512] = d2 * rs * g[tid + 512] + bta[tid + 512];
}

// -------------------- weight transpose (src[R][C] -> dst[C][R]) -----------
__global__ void transpose_w(const float* __restrict__ src, float* __restrict__ dst,
                            int R, int C, float scale) {
    __shared__ float t[32][33];
    int bx = blockIdx.x * 32;   // C tile
    int by = blockIdx.y * 32;   // R tile
    int x = threadIdx.x, y = threadIdx.y;  // 32 x 8
#pragma unroll
    for (int i = 0; i < 32; i += 8)
        t[y + i][x] = src[(size_t)(by + y + i) * C + bx + x] * scale;
    __syncthreads();
#pragma unroll
    for (int i = 0; i < 32; i += 8)
        dst[(size_t)(bx + y + i) * R + by + x] = t[x][y + i];
}

// -------------------- bias concat -----------------------------------------
__global__ void concat_bias(const float* __restrict__ bq, const float* __restrict__ bk,
                            const float* __restrict__ bv, float* __restrict__ Bo) {
    int j = blockIdx.x * 256 + threadIdx.x;
    if (j < 768) Bo[j] = bq[j] * 0.125f;
    else if (j < 1536) Bo[j] = bk[j - 768];
    else if (j < 2304) Bo[j] = bv[j - 1536];
}

// -------------------- trig table ------------------------------------------
__global__ void trig_kernel(float* __restrict__ trig) {
    int idx = blockIdx.x * 256 + threadIdx.x;
    if (idx >= T_TOK * 16) return;
    int t = idx >> 4, i = idx & 15;
    double ts = pow(10000.0, (double)i / 32.0);
    double ang = (double)t / ts;
    double sd, cd;
    sincos(ang, &sd, &cd);
    trig[idx * 2]     = (float)cd;
    trig[idx * 2 + 1] = (float)sd;
}

// -------------------- p-RoPE apply ----------------------------------------
__global__ void rope_apply(float* __restrict__ qkv, const float* __restrict__ trig) {
    int idx = blockIdx.x * blockDim.x + threadIdx.x;
    const int total = BATCH * T_TOK * N_HEADS * 16;
    if (idx >= total) return;
    int i = idx & 15;
    int h = (idx >> 4) % N_HEADS;
    int t = (idx / (16 * N_HEADS)) % T_TOK;
    int b = idx / (16 * N_HEADS * T_TOK);
    size_t base = ((size_t)(b * T_TOK + t)) * QKV_N + h * HEAD_DIM + i;
    float cf = trig[(t * 16 + i) * 2];
    float sf = trig[(t * 16 + i) * 2 + 1];
    float x1 = qkv[base], x2 = qkv[base + 32];
    qkv[base]      = x1 * cf - x2 * sf;
    qkv[base + 32] = x2 * cf + x1 * sf;
    x1 = qkv[base + 768]; x2 = qkv[base + 800];
    qkv[base + 768] = x1 * cf - x2 * sf;
    qkv[base + 800] = x2 * cf + x1 * sf;
}

// -------------------- tf32 GEMM (B transposed [N][K]), ldmatrix frags -----
#define TST 20                               // smem stride for A and B tiles
#define AS_SZ (128 * TST)
#define BS_SZ (128 * TST)
#define G128_SMEM_BYTES (3 * (AS_SZ + BS_SZ) * 4)
#define AS64_SZ (64 * TST)
#define G64_SMEM_BYTES (3 * (AS64_SZ + BS_SZ) * 4)

template <bool GELU>
__global__ __launch_bounds__(256, 2)
void gemm_tf32(const float* __restrict__ A, const float* __restrict__ BmT,
               const float* __restrict__ bias, const float* __restrict__ res,
               float* __restrict__ C, int M, int N, int K) {
    extern __shared__ unsigned gsm[];
    unsigned* AsB = gsm;
    unsigned* BsB = gsm + 3 * AS_SZ;
    int tid = threadIdx.x;
    int wid = tid >> 5, lane = tid & 31;
    int g = lane >> 2, tig = lane & 3;
    int wm = wid & 3, wn = wid >> 2;
    int brow = blockIdx.y * 128, bcol = blockIdx.x * 128;

    int ar = tid >> 2, ac = (tid & 3) * 4;
    const float* Ap = A + (size_t)(brow + ar) * K + ac;
    const float* Bp = BmT + (size_t)(bcol + ar) * K + ac;

    int nIter = K >> 4;

#define GEMM_ISSUE(KT, STG) do {                                              \
        const float* a0_ = Ap + (KT) * 16;                                    \
        unsigned* asd_ = AsB + (STG) * AS_SZ;                                 \
        cp16(&asd_[ar * TST + ac], a0_);                                      \
        cp16(&asd_[(ar + 64) * TST + ac], a0_ + (size_t)64 * K);              \
        const float* b0_ = Bp + (KT) * 16;                                    \
        unsigned* bsd_ = BsB + (STG) * BS_SZ;                                 \
        cp16(&bsd_[ar * TST + ac], b0_);                                      \
        cp16(&bsd_[(ar + 64) * TST + ac], b0_ + (size_t)64 * K);              \
        cp_commit();                                                           \
    } while (0)

    GEMM_ISSUE(0, 0);
    GEMM_ISSUE(1, 1);

    float acc[2][8][4];
#pragma unroll
    for (int i = 0; i < 2; i++)
#pragma unroll
        for (int j = 0; j < 8; j++)
#pragma unroll
            for (int r = 0; r < 4; r++) acc[i][j][r] = 0.f;

    int l15 = lane & 15, lkh = (lane >> 4) << 2;          // A: row sel, k-half
    int l8 = lane & 7, bk4 = ((lane >> 3) & 1) << 2, bns = (lane >> 4) & 1; // B

    int cur = 0, nxt = 2;
    for (int kt = 0; kt < nIter; ++kt) {
        if (kt + 1 < nIter) cp_wait<1>(); else cp_wait<0>();
        __syncthreads();
        if (kt + 2 < nIter) GEMM_ISSUE(kt + 2, nxt);
        const unsigned* As = AsB + cur * AS_SZ;
        const unsigned* Bs = BsB + cur * BS_SZ;
#pragma unroll
        for (int ks = 0; ks < 16; ks += 8) {
            unsigned af[2][4];
#pragma unroll
            for (int mt = 0; mt < 2; mt++) {
                int R = wm * 32 + mt * 16;
                ldsm4(af[mt], su32(&As[(R + l15) * TST + ks + lkh]));
            }
#pragma unroll
            for (int p = 0; p < 4; p++) {
                unsigned bf[4];
                int nrow = wn * 64 + ((p << 1) + bns) * 8 + l8;
                ldsm4(bf, su32(&Bs[nrow * TST + ks + bk4]));
                mma_tf32(acc[0][2 * p],     af[0], bf);
                mma_tf32(acc[1][2 * p],     af[1], bf);
                mma_tf32(acc[0][2 * p + 1], af[0], bf + 2);
                mma_tf32(acc[1][2 * p + 1], af[1], bf + 2);
            }
        }
        cur = cur + 1; if (cur == 3) cur = 0;
        nxt = nxt + 1; if (nxt == 3) nxt = 0;
    }
#undef GEMM_ISSUE

#pragma unroll
    for (int mt = 0; mt < 2; mt++) {
        int row0 = brow + wm * 32 + mt * 16 + g;
#pragma unroll
        for (int nt = 0; nt < 8; nt++) {
            int col = bcol + wn * 64 + nt * 8 + tig * 2;
            float b0 = bias[col], b1 = bias[col + 1];
            float v00 = acc[mt][nt][0] + b0;
            float v01 = acc[mt][nt][1] + b1;
            float v10 = acc[mt][nt][2] + b0;
            float v11 = acc[mt][nt][3] + b1;
            if (GELU) {
                v00 *= normcdff(v00); v01 *= normcdff(v01);
                v10 *= normcdff(v10); v11 *= normcdff(v11);
            }
            if (res) {
                const float* r0p = res + (size_t)row0 * N + col;
                const float* r1p = res + (size_t)(row0 + 8) * N + col;
                v00 += r0p[0]; v01 += r0p[1];
                v10 += r1p[0]; v11 += r1p[1];
            }
            *(float2*)(C + (size_t)row0 * N + col) = make_float2(v00, v01);
            *(float2*)(C + (size_t)(row0 + 8) * N + col) = make_float2(v10, v11);
        }
    }
}

// -------------------- tf32 GEMM 64x128 (B transposed), ldmatrix -----------
template <bool GELU>
__global__ __launch_bounds__(256, 3)
void gemm_tf32_m64(const float* __restrict__ A, const float* __restrict__ BmT,
                   const float* __restrict__ bias, const float* __restrict__ res,
                   float* __restrict__ C, int M, int N, int K) {
    extern __shared__ unsigned gsm[];
    unsigned* AsB = gsm;
    unsigned* BsB = gsm + 3 * AS64_SZ;
    int tid = threadIdx.x;
    int wid = tid >> 5, lane = tid & 31;
    int g = lane >> 2, tig = lane & 3;
    int wm = wid & 1, wn = wid >> 1;
    int brow = blockIdx.y * 64, bcol = blockIdx.x * 128;

    int ar = tid >> 2, ac = (tid & 3) * 4;
    const float* Ap = A + (size_t)(brow + ar) * K + ac;
    const float* Bp = BmT + (size_t)(bcol + ar) * K + ac;

    int nIter = K >> 4;

#define GEMM_ISSUE64(KT, STG) do {                                            \
        cp16(&AsB[(STG) * AS64_SZ + ar * TST + ac], Ap + (KT) * 16);          \
        const float* b0_ = Bp + (KT) * 16;                                    \
        unsigned* bsd_ = BsB + (STG) * BS_SZ;                                 \
        cp16(&bsd_[ar * TST + ac], b0_);                                      \
        cp16(&bsd_[(ar + 64) * TST + ac], b0_ + (size_t)64 * K);              \
        cp_commit();                                                           \
    } while (0)

    GEMM_ISSUE64(0, 0);
    GEMM_ISSUE64(1, 1);

    float acc[2][4][4];
#pragma unroll
    for (int i = 0; i < 2; i++)
#pragma unroll
        for (int j = 0; j < 4; j++)
#pragma unroll
            for (int r = 0; r < 4; r++) acc[i][j][r] = 0.f;

    int l15 = lane & 15, lkh = (lane >> 4) << 2;
    int l8 = lane & 7, bk4 = ((lane >> 3) & 1) << 2, bns = (lane >> 4) & 1;

    int cur = 0, nxt = 2;
    for (int kt = 0; kt < nIter; ++kt) {
        if (kt + 1 < nIter) cp_wait<1>(); else cp_wait<0>();
        __syncthreads();
        if (kt + 2 < nIter) GEMM_ISSUE64(kt + 2, nxt);
        const unsigned* As = AsB + cur * AS64_SZ;
        const unsigned* Bs = BsB + cur * BS_SZ;
#pragma unroll
        for (int ks = 0; ks < 16; ks += 8) {
            unsigned af[2][4];
#pragma unroll
            for (int mt = 0; mt < 2; mt++) {
                int R = wm * 32 + mt * 16;
                ldsm4(af[mt], su32(&As[(R + l15) * TST + ks + lkh]));
            }
#pragma unroll
            for (int p = 0; p < 2; p++) {
                unsigned bf[4];
                int nrow = wn * 32 + ((p << 1) + bns) * 8 + l8;
                ldsm4(bf, su32(&Bs[nrow * TST + ks + bk4]));
                mma_tf32(acc[0][2 * p],     af[0], bf);
                mma_tf32(acc[1][2 * p],     af[1], bf);
                mma_tf32(acc[0][2 * p + 1], af[0], bf + 2);
                mma_tf32(acc[1][2 * p + 1], af[1], bf + 2);
            }
        }
        cur = cur + 1; if (cur == 3) cur = 0;
        nxt = nxt + 1; if (nxt == 3) nxt = 0;
    }
#undef GEMM_ISSUE64

#pragma unroll
    for (int mt = 0; mt < 2; mt++) {
        int row0 = brow + wm * 32 + mt * 16 + g;
#pragma unroll
        for (int nt = 0; nt < 4; nt++) {
            int col = bcol + wn * 32 + nt * 8 + tig * 2;
            float b0 = bias[col], b1 = bias[col + 1];
            float v00 = acc[mt][nt][0] + b0;
            float v01 = acc[mt][nt][1] + b1;
            float v10 = acc[mt][nt][2] + b0;
            float v11 = acc[mt][nt][3] + b1;
            if (GELU) {
                v00 *= normcdff(v00); v01 *= normcdff(v01);
                v10 *= normcdff(v10); v11 *= normcdff(v11);
            }
            if (res) {
                const float* r0p = res + (size_t)row0 * N + col;
                const float* r1p = res + (size_t)(row0 + 8) * N + col;
                v00 += r0p[0]; v01 += r0p[1];
                v10 += r1p[0]; v11 += r1p[1];
            }
            *(float2*)(C + (size_t)row0 * N + col) = make_float2(v00, v01);
            *(float2*)(C + (size_t)(row0 + 8) * N + col) = make_float2(v10, v11);
        }
    }
}

// -------------------- flash attention: BM=128, ldmatrix Q/K/P -------------
#define QS_STRIDE 68
#define KS_STRIDE 76
#define VS_STRIDE 72
#define SC_STRIDE 68
#define AT_SMEM_FLOATS (128*QS_STRIDE + 64*KS_STRIDE + 64*VS_STRIDE + 128*SC_STRIDE + 384)

__global__ __launch_bounds__(256, 2)
void attn_tf32(const float* __restrict__ QKV, const float* __restrict__ ab,
               float* __restrict__ O) {
    extern __shared__ float sm[];
    unsigned* Qs = (unsigned*)sm;
    unsigned* Ks = Qs + 128 * QS_STRIDE;
    unsigned* Vs = Ks + 64 * KS_STRIDE;
    float* Sc = (float*)(Vs + 64 * VS_STRIDE);
    float* mrow = Sc + 128 * SC_STRIDE;
    float* lrow = mrow + 128;
    float* srow = lrow + 128;
    unsigned* Scu = (unsigned*)Sc;

    int tid = threadIdx.x;
    int wid = tid >> 5, lane = tid & 31;
    int g = lane >> 2, tig = lane & 3;
    int wm = wid >> 1, wn = wid & 1;
    int m0 = wm * 32, n0 = wn * 32;

    int l15 = lane & 15, lkh = (lane >> 4) << 2;
    int l8 = lane & 7, bk4 = ((lane >> 3) & 1) << 2, bns = (lane >> 4) & 1;

    int qb = blockIdx.x * 128;
    int h = blockIdx.y, b = blockIdx.z;
    size_t bh = (size_t)b * T_TOK * QKV_N + h * HEAD_DIM;
    const float* qp = QKV + bh;
    const float* kp = QKV + bh + 768;
    const float* vp = QKV + bh + 1536;

#define K_ISSUE(KT) do {                                                      \
        int kb_ = (KT) * 64;                                                  \
        _Pragma("unroll")                                                     \
        for (int it = 0; it < 4; it++) {                                      \
            int idx_ = tid + it * 256;                                        \
            int r_ = idx_ >> 4, c4_ = (idx_ & 15) * 4;                        \
            cp16(&Ks[r_ * KS_STRIDE + c4_], kp + (size_t)(kb_ + r_) * QKV_N + c4_); \
        }                                                                     \
        cp_commit();                                                          \
    } while (0)
#define V_ISSUE(KT) do {                                                      \
        int kb_ = (KT) * 64;                                                  \
        _Pragma("unroll")                                                     \
        for (int it = 0; it < 4; it++) {                                      \
            int idx_ = tid + it * 256;                                        \
            int r_ = idx_ >> 4, c4_ = (idx_ & 15) * 4;                        \
            cp16(&Vs[r_ * VS_STRIDE + c4_], vp + (size_t)(kb_ + r_) * QKV_N + c4_); \
        }                                                                     \
        cp_commit();                                                          \
    } while (0)

#pragma unroll
    for (int it = 0; it < 8; it++) {
        int idx = tid + it * 256;
        int r = idx >> 4, c4 = (idx & 15) * 4;
        cp16(&Qs[r * QS_STRIDE + c4], qp + (size_t)(qb + r) * QKV_N + c4);
    }
    cp_commit();
    K_ISSUE(0);
    V_ISSUE(0);
    if (tid < 128) { mrow[tid] = -1e30f; lrow[tid] = 0.f; }

    float o[2][4][4];
#pragma unroll
    for (int mt = 0; mt < 2; mt++)
#pragma unroll
        for (int nt = 0; nt < 4; nt++)
#pragma unroll
            for (int r = 0; r < 4; r++) o[mt][nt][r] = 0.f;

    float bias0 = ab[h * 2 + 0], bias1 = ab[h * 2 + 1];
    int qvar = qb >> 7;

    for (int kt = 0; kt < 32; kt++) {
        cp_wait<0>();
        __syncthreads();
        if (kt > 0) V_ISSUE(kt);

        // ---- S = Q @ K^T (ldmatrix on Q and K) ----
        float s[2][4][4];
#pragma unroll
        for (int mt = 0; mt < 2; mt++)
#pragma unroll
            for (int nt = 0; nt < 4; nt++)
#pragma unroll
                for (int r = 0; r < 4; r++) s[mt][nt][r] = 0.f;
#pragma unroll
        for (int ks = 0; ks < 64; ks += 8) {
            unsigned af[2][4];
#pragma unroll
            for (int mt = 0; mt < 2; mt++) {
                int R = m0 + mt * 16;
                ldsm4(af[mt], su32(&Qs[(R + l15) * QS_STRIDE + ks + lkh]));
            }
#pragma unroll
            for (int p = 0; p < 2; p++) {
                unsigned bf[4];
                int nrow = n0 + ((p << 1) + bns) * 8 + l8;
                ldsm4(bf, su32(&Ks[nrow * KS_STRIDE + ks + bk4]));
                mma_tf32(s[0][2 * p],     af[0], bf);
                mma_tf32(s[1][2 * p],     af[1], bf);
                mma_tf32(s[0][2 * p + 1], af[0], bf + 2);
                mma_tf32(s[1][2 * p + 1], af[1], bf + 2);
            }
        }
        float bias = (((kt * 64) >> 7) == qvar) ? bias0 : bias1;
#pragma unroll
        for (int mt = 0; mt < 2; mt++) {
            int r0 = m0 + mt * 16 + g;
#pragma unroll
            for (int nt = 0; nt < 4; nt++) {
                int col = n0 + nt * 8 + tig * 2;
                Sc[r0 * SC_STRIDE + col]     = s[mt][nt][0] + bias;
                Sc[r0 * SC_STRIDE + col + 1] = s[mt][nt][1] + bias;
                Sc[(r0 + 8) * SC_STRIDE + col]     = s[mt][nt][2] + bias;
                Sc[(r0 + 8) * SC_STRIDE + col + 1] = s[mt][nt][3] + bias;
            }
        }
        __syncthreads();
        if (kt + 1 < 32) K_ISSUE(kt + 1);

        // ---- online softmax ----
        {
            int r = tid >> 1, seg = tid & 1;
            float* sr = &Sc[r * SC_STRIDE + seg * 32];
            float mo = mrow[r];
            float mx = -1e30f;
#pragma unroll
            for (int j = 0; j < 32; j++) mx = fmaxf(mx, sr[j]);
            mx = fmaxf(mx, __shfl_xor_sync(0xffffffffu, mx, 1));
            mx = fmaxf(mx, mo);
            float sum = 0.f;
#pragma unroll
            for (int j = 0; j < 32; j++) {
                float p = __expf(sr[j] - mx);
                sr[j] = p;
                sum += p;
            }
            sum += __shfl_xor_sync(0xffffffffu, sum, 1);
            if (seg == 0) {
                float scl = __expf(mo - mx);
                mrow[r] = mx;
                lrow[r] = lrow[r] * scl + sum;
                srow[r] = scl;
            }
        }
        if (kt + 1 < 32) cp_wait<1>(); else cp_wait<0>();
        __syncthreads();

        // ---- rescale + O += P @ V (ldmatrix on P, scalar V) ----
#pragma unroll
        for (int mt = 0; mt < 2; mt++) {
            int r0 = m0 + mt * 16 + g;
            float scl0 = srow[r0], scl1 = srow[r0 + 8];
#pragma unroll
            for (int nt = 0; nt < 4; nt++) {
                o[mt][nt][0] *= scl0; o[mt][nt][1] *= scl0;
                o[mt][nt][2] *= scl1; o[mt][nt][3] *= scl1;
            }
        }
#pragma unroll
        for (int ks = 0; ks < 64; ks += 8) {
            unsigned af[2][4];
#pragma unroll
            for (int mt = 0; mt < 2; mt++) {
                int R = m0 + mt * 16;
                ldsm4(af[mt], su32(&Scu[(R + l15) * SC_STRIDE + ks + lkh]));
            }
#pragma unroll
            for (int nt = 0; nt < 4; nt++) {
                unsigned bf[2];
                int c0 = n0 + nt * 8 + g;
                bf[0] = Vs[(ks + tig) * VS_STRIDE + c0];
                bf[1] = Vs[(ks + tig + 4) * VS_STRIDE + c0];
                mma_tf32(o[0][nt], af[0], bf);
                mma_tf32(o[1][nt], af[1], bf);
            }
        }
    }
#undef K_ISSUE
#undef V_ISSUE

#pragma unroll
    for (int mt = 0; mt < 2; mt++) {
        int r0 = m0 + mt * 16 + g;
        float inv0 = 1.f / lrow[r0], inv1 = 1.f / lrow[r0 + 8];
        int row0 = qb + r0;
#pragma unroll
        for (int nt = 0; nt < 4; nt++) {
            int col = n0 + nt * 8 + tig * 2;
            float* o0 = O + (size_t)(b * T_TOK + row0) * D_MODEL + h * HEAD_DIM + col;
            float* o1 = O + (size_t)(b * T_TOK + row0 + 8) * D_MODEL + h * HEAD_DIM + col;
            *(float2*)o0 = make_float2(o[mt][nt][0] * inv0, o[mt][nt][1] * inv0);
            *(float2*)o1 = make_float2(o[mt][nt][2] * inv1, o[mt][nt][3] * inv1);
        }
    }
}

// -------------------- launch ----------------------------------------------
extern "C" void kernel_launch(void* const* d_in, const int* in_sizes, int n_in,
                              void* d_out, int out_size) {
    const float* hs  = (const float*)d_in[0];
    const float* wq  = (const float*)d_in[1];
    const float* bq  = (const float*)d_in[2];
    const float* wk  = (const float*)d_in[3];
    const float* bk  = (const float*)d_in[4];
    const float* wv  = (const float*)d_in[5];
    const float* bv  = (const float*)d_in[6];
    const float* wo  = (const float*)d_in[7];
    const float* bo  = (const float*)d_in[8];
    const float* ab  = (const float*)d_in[9];
    const float* g1  = (const float*)d_in[10];
    const float* be1 = (const float*)d_in[11];
    const float* g3  = (const float*)d_in[12];
    const float* be3 = (const float*)d_in[13];
    const float* w1  = (const float*)d_in[14];
    const float* b1  = (const float*)d_in[15];
    const float* w2  = (const float*)d_in[16];
    const float* b2  = (const float*)d_in[17];
    float* out = (float*)d_out;

    float *ni, *qkv, *wqkvT, *bqkv, *woT, *w1T, *w2T, *attn, *res1, *ffin, *hbuf, *trig;
    cudaGetSymbolAddress((void**)&ni,    g_ni);
    cudaGetSymbolAddress((void**)&qkv,   g_qkv);
    cudaGetSymbolAddress((void**)&wqkvT, g_wqkvT);
    cudaGetSymbolAddress((void**)&bqkv,  g_bqkv);
    cudaGetSymbolAddress((void**)&woT,   g_woT);
    cudaGetSymbolAddress((void**)&w1T,   g_w1T);
    cudaGetSymbolAddress((void**)&w2T,   g_w2T);
    cudaGetSymbolAddress((void**)&attn,  g_attn);
    cudaGetSymbolAddress((void**)&res1,  g_res1);
    cudaGetSymbolAddress((void**)&ffin,  g_ffin);
    cudaGetSymbolAddress((void**)&hbuf,  g_h);
    cudaGetSymbolAddress((void**)&trig,  g_trig);

    static bool attr_set = false;
    if (!attr_set) {
        cudaFuncSetAttribute(attn_tf32, cudaFuncAttributeMaxDynamicSharedMemorySize,
                             AT_SMEM_FLOATS * (int)sizeof(float));
        cudaFuncSetAttribute(gemm_tf32<false>, cudaFuncAttributeMaxDynamicSharedMemorySize,
                             G128_SMEM_BYTES);
        cudaFuncSetAttribute(gemm_tf32<true>, cudaFuncAttributeMaxDynamicSharedMemorySize,
                             G128_SMEM_BYTES);
        cudaFuncSetAttribute(gemm_tf32_m64<false>, cudaFuncAttributeMaxDynamicSharedMemorySize,
                             G64_SMEM_BYTES);
        attr_set = true;
    }

    // 0. prep: trig table, bias concat, weight transposes
    trig_kernel<<<(T_TOK * 16 + 255) / 256, 256>>>(trig);
    concat_bias<<<(QKV_N + 255) / 256, 256>>>(bq, bk, bv, bqkv);
    {
        dim3 blk(32, 8);
        transpose_w<<<dim3(24, 24), blk>>>(wq, wqkvT, 768, 768, 0.125f);
        transpose_w<<<dim3(24, 24), blk>>>(wk, wqkvT + 768 * 768, 768, 768, 1.f);
        transpose_w<<<dim3(24, 24), blk>>>(wv, wqkvT + 1536 * 768, 768, 768, 1.f);
        transpose_w<<<dim3(24, 24), blk>>>(wo, woT, 768, 768, 1.f);
        transpose_w<<<dim3(96, 24), blk>>>(w1, w1T, 768, 3072, 1.f);
        transpose_w<<<dim3(24, 96), blk>>>(w2, w2T, 3072, 768, 1.f);
    }

    // 1. LN1
    ln_kernel<<<M_ROWS, 256>>>(hs, g1, be1, ni);

    // 2. fused QKV projection
    dim3 gQKV(QKV_N / 128, M_ROWS / 128);
    gemm_tf32<false><<<gQKV, 256, G128_SMEM_BYTES>>>(ni, wqkvT, bqkv, nullptr, qkv, M_ROWS, QKV_N, D_MODEL);

    // 3. RoPE
    {
        int total = BATCH * T_TOK * N_HEADS * 16;
        rope_apply<<<(total + 255) / 256, 256>>>(qkv, trig);
    }

    // 4. attention (BM=128)
    {
        dim3 ga(T_TOK / 128, N_HEADS, BATCH);
        attn_tf32<<<ga, 256, AT_SMEM_FLOATS * (int)sizeof(float)>>>(qkv, ab, attn);
    }

    // 5. out-proj + residual(hs)  (M64)
    dim3 gP64(D_MODEL / 128, M_ROWS / 64);
    gemm_tf32_m64<false><<<gP64, 256, G64_SMEM_BYTES>>>(attn, woT, bo, hs, res1, M_ROWS, D_MODEL, D_MODEL);

    // 6. LN3
    ln_kernel<<<M_ROWS, 256>>>(res1, g3, be3, ffin);

    // 7. FFN1 + exact GELU
    dim3 gF1(FFN_DIM / 128, M_ROWS / 128);
    gemm_tf32<true><<<gF1, 256, G128_SMEM_BYTES>>>(ffin, w1T, b1, nullptr, hbuf, M_ROWS, FFN_DIM, D_MODEL);

    // 8. FFN2 + residual(res1) -> out  (M64)
    gemm_tf32_m64<false><<<gP64, 256, G64_SMEM_BYTES>>>(hbuf, w2T, b2, res1, out, M_ROWS, D_MODEL, FFN_DIM);
}

// round 11
// speedup vs baseline: 1.5969x; 1.2794x over previous
#include <cuda_runtime.h>
#include <cuda_fp16.h>
#include <math.h>
#include <stdint.h>

#define D_MODEL 768
#define N_HEADS 12
#define HEAD_DIM 64
#define FFN_DIM 3072
#define T_TOK 2048
#define BATCH 2
#define M_ROWS (BATCH * T_TOK)   // 4096
#define QKV_N 2304               // 3 * D_MODEL

// -------------------- scratch ---------------------------------------------
__device__ __half g_ni[M_ROWS * D_MODEL];
__device__ __half g_qkv[M_ROWS * QKV_N];
__device__ __half g_wqkvT[QKV_N * D_MODEL];
__device__ float  g_bqkv[QKV_N];
__device__ __half g_woT[D_MODEL * D_MODEL];
__device__ __half g_w1T[FFN_DIM * D_MODEL];
__device__ __half g_w2T[D_MODEL * FFN_DIM];
__device__ __half g_attn[M_ROWS * D_MODEL];
__device__ float  g_res1[M_ROWS * D_MODEL];
__device__ __half g_ffin[M_ROWS * D_MODEL];
__device__ __half g_h[M_ROWS * FFN_DIM];
__device__ float  g_trig[T_TOK * 16 * 2];

// -------------------- helpers ---------------------------------------------
__device__ __forceinline__ unsigned su32(const void* p) {
    return (unsigned)__cvta_generic_to_shared(p);
}
__device__ __forceinline__ void cp16(void* smem_dst, const void* gptr) {
    asm volatile("cp.async.cg.shared.global [%0], [%1], 16;" :: "r"(su32(smem_dst)), "l"(gptr));
}
__device__ __forceinline__ void cp_commit() { asm volatile("cp.async.commit_group;"); }
template <int NN>
__device__ __forceinline__ void cp_wait() { asm volatile("cp.async.wait_group %0;" :: "n"(NN)); }

// fp16 mma: C(fp32) += A(fp16) * B(fp16)
__device__ __forceinline__ void mma_f16(float* c, const unsigned* a, unsigned b0, unsigned b1) {
    asm volatile(
        "mma.sync.aligned.m16n8k16.row.col.f32.f16.f16.f32 "
        "{%0,%1,%2,%3}, {%4,%5,%6,%7}, {%8,%9}, {%0,%1,%2,%3};"
        : "+f"(c[0]), "+f"(c[1]), "+f"(c[2]), "+f"(c[3])
        : "r"(a[0]), "r"(a[1]), "r"(a[2]), "r"(a[3]), "r"(b0), "r"(b1));
}
__device__ __forceinline__ void ldsm4(unsigned* r, unsigned addr) {
    asm volatile("ldmatrix.sync.aligned.m8n8.x4.shared.b16 {%0,%1,%2,%3}, [%4];"
                 : "=r"(r[0]), "=r"(r[1]), "=r"(r[2]), "=r"(r[3]) : "r"(addr));
}
__device__ __forceinline__ void ldsm4t(unsigned* r, unsigned addr) {
    asm volatile("ldmatrix.sync.aligned.m8n8.x4.trans.shared.b16 {%0,%1,%2,%3}, [%4];"
                 : "=r"(r[0]), "=r"(r[1]), "=r"(r[2]), "=r"(r[3]) : "r"(addr));
}

// -------------------- block reduction -------------------------------------
__device__ __forceinline__ float block_sum_256(float val) {
    __shared__ float red[8];
    int lane = threadIdx.x & 31, w = threadIdx.x >> 5;
#pragma unroll
    for (int o = 16; o; o >>= 1) val += __shfl_xor_sync(0xffffffffu, val, o);
    if (lane == 0) red[w] = val;
    __syncthreads();
    if (w == 0) {
        float t = (lane < 8) ? red[lane] : 0.f;
#pragma unroll
        for (int o = 4; o; o >>= 1) t += __shfl_xor_sync(0xffffffffu, t, o);
        if (lane == 0) red[0] = t;
    }
    __syncthreads();
    float r = red[0];
    __syncthreads();
    return r;
}

// -------------------- LayerNorm (fp32 in, fp16 out) ------------------------
__global__ void ln_kernel(const float* __restrict__ x, const float* __restrict__ g,
                          const float* __restrict__ bta, __half* __restrict__ y) {
    size_t row = blockIdx.x;
    int tid = threadIdx.x;
    const float* xr = x + row * D_MODEL;
    float v0 = xr[tid], v1 = xr[tid + 256], v2 = xr[tid + 512];
    float mu = block_sum_256(v0 + v1 + v2) * (1.f / 768.f);
    float d0 = v0 - mu, d1 = v1 - mu, d2 = v2 - mu;
    float var = block_sum_256(d0 * d0 + d1 * d1 + d2 * d2) * (1.f / 768.f);
    float rs = rsqrtf(var + 1e-5f);
    __half* yr = y + row * D_MODEL;
    yr[tid]       = __float2half(d0 * rs * g[tid]       + bta[tid]);
    yr[tid + 256] = __float2half(d1 * rs * g[tid + 256] + bta[tid + 256]);
    yr[tid + 512] = __float2half(d2 * rs * g[tid + 512] + bta[tid + 512]);
}

// -------------------- weight transpose + fp16 convert ----------------------
__global__ void transpose_w(const float* __restrict__ src, __half* __restrict__ dst,
                            int R, int C, float scale) {
    __shared__ float t[32][33];
    int bx = blockIdx.x * 32;
    int by = blockIdx.y * 32;
    int x = threadIdx.x, y = threadIdx.y;
#pragma unroll
    for (int i = 0; i < 32; i += 8)
        t[y + i][x] = src[(size_t)(by + y + i) * C + bx + x] * scale;
    __syncthreads();
#pragma unroll
    for (int i = 0; i < 32; i += 8)
        dst[(size_t)(bx + y + i) * R + by + x] = __float2half(t[x][y + i]);
}

// -------------------- bias concat -----------------------------------------
__global__ void concat_bias(const float* __restrict__ bq, const float* __restrict__ bk,
                            const float* __restrict__ bv, float* __restrict__ Bo) {
    int j = blockIdx.x * 256 + threadIdx.x;
    if (j < 768) Bo[j] = bq[j] * 0.125f;
    else if (j < 1536) Bo[j] = bk[j - 768];
    else if (j < 2304) Bo[j] = bv[j - 1536];
}

// -------------------- trig table ------------------------------------------
__global__ void trig_kernel(float* __restrict__ trig) {
    int idx = blockIdx.x * 256 + threadIdx.x;
    if (idx >= T_TOK * 16) return;
    int t = idx >> 4, i = idx & 15;
    double ts = pow(10000.0, (double)i / 32.0);
    double ang = (double)t / ts;
    double sd, cd;
    sincos(ang, &sd, &cd);
    trig[idx * 2]     = (float)cd;
    trig[idx * 2 + 1] = (float)sd;
}

// -------------------- p-RoPE apply on fp16 qkv -----------------------------
__global__ void rope_apply(__half* __restrict__ qkv, const float* __restrict__ trig) {
    int idx = blockIdx.x * blockDim.x + threadIdx.x;
    const int total = BATCH * T_TOK * N_HEADS * 16;
    if (idx >= total) return;
    int i = idx & 15;
    int h = (idx >> 4) % N_HEADS;
    int t = (idx / (16 * N_HEADS)) % T_TOK;
    int b = idx / (16 * N_HEADS * T_TOK);
    size_t base = ((size_t)(b * T_TOK + t)) * QKV_N + h * HEAD_DIM + i;
    float cf = trig[(t * 16 + i) * 2];
    float sf = trig[(t * 16 + i) * 2 + 1];
    float x1 = __half2float(qkv[base]), x2 = __half2float(qkv[base + 32]);
    qkv[base]      = __float2half(x1 * cf - x2 * sf);
    qkv[base + 32] = __float2half(x2 * cf + x1 * sf);
    x1 = __half2float(qkv[base + 768]); x2 = __half2float(qkv[base + 800]);
    qkv[base + 768] = __float2half(x1 * cf - x2 * sf);
    qkv[base + 800] = __float2half(x2 * cf + x1 * sf);
}

// ==================== fp16 GEMM 128x128, BK=32, 3-stage ====================
// C = epi(A[M,K]h @ B^T, bias) (+res fp32). B supplied transposed [N][K] fp16.
#define HST 40                                 // halves; 80B rows: conflict-free ldsm
#define AH_SZ (128 * HST)
#define BH_SZ (128 * HST)
#define G128_SMEM_BYTES (3 * (AH_SZ + BH_SZ) * 2)    // 61440
#define AH64_SZ (64 * HST)
#define G64_SMEM_BYTES (3 * (AH64_SZ + BH_SZ) * 2)   // 46080

template <bool GELU, bool OUTH>
__global__ __launch_bounds__(256, 2)
void gemm_f16(const __half* __restrict__ A, const __half* __restrict__ BmT,
              const float* __restrict__ bias, const float* __restrict__ res,
              void* __restrict__ Cv, int M, int N, int K) {
    extern __shared__ __half hsm[];
    __half* AsB = hsm;
    __half* BsB = hsm + 3 * AH_SZ;
    int tid = threadIdx.x;
    int wid = tid >> 5, lane = tid & 31;
    int g = lane >> 2, tig = lane & 3;
    int wm = wid & 3, wn = wid >> 2;
    int brow = blockIdx.y * 128, bcol = blockIdx.x * 128;

    // staging: tile 128 rows x 32 halves (4 chunks of 8 halves); 2 chunks/thread each of A,B
    const __half* apre[2];
    const __half* bpre[2];
    int aso[2];
#pragma unroll
    for (int i = 0; i < 2; i++) {
        int idx = tid + i * 256;
        int row = idx >> 2, ch = (idx & 3) * 8;
        aso[i] = row * HST + ch;
        apre[i] = A + (size_t)(brow + row) * K + ch;
        bpre[i] = BmT + (size_t)(bcol + row) * K + ch;
    }

    int nIter = K >> 5;

#define GF_ISSUE(KT, STG) do {                                                \
        __half* asd_ = AsB + (STG) * AH_SZ;                                   \
        __half* bsd_ = BsB + (STG) * BH_SZ;                                   \
        _Pragma("unroll")                                                     \
        for (int i = 0; i < 2; i++) {                                         \
            cp16(&asd_[aso[i]], apre[i] + (KT) * 32);                         \
            cp16(&bsd_[aso[i]], bpre[i] + (KT) * 32);                         \
        }                                                                     \
        cp_commit();                                                           \
    } while (0)

    GF_ISSUE(0, 0);
    GF_ISSUE(1, 1);

    float acc[2][8][4];
#pragma unroll
    for (int i = 0; i < 2; i++)
#pragma unroll
        for (int j = 0; j < 8; j++)
#pragma unroll
            for (int r = 0; r < 4; r++) acc[i][j][r] = 0.f;

    int l15 = lane & 15, lkh8 = (lane >> 4) << 3;

    int cur = 0, nxt = 2;
    for (int kt = 0; kt < nIter; ++kt) {
        if (kt + 1 < nIter) cp_wait<1>(); else cp_wait<0>();
        __syncthreads();
        if (kt + 2 < nIter) GF_ISSUE(kt + 2, nxt);
        const __half* As = AsB + cur * AH_SZ;
        const __half* Bs = BsB + cur * BH_SZ;
#pragma unroll
        for (int ks = 0; ks < 32; ks += 16) {
            unsigned af[2][4];
#pragma unroll
            for (int mt = 0; mt < 2; mt++) {
                int R = wm * 32 + mt * 16;
                ldsm4(af[mt], su32(&As[(R + l15) * HST + ks + lkh8]));
            }
#pragma unroll
            for (int p = 0; p < 4; p++) {
                unsigned bf[4];
                int nr = wn * 64 + p * 16;
                ldsm4(bf, su32(&Bs[(nr + l15) * HST + ks + lkh8]));
                // r0=(n0-7,k0-7) r1=(n8-15,k0-7) r2=(n0-7,k8-15) r3=(n8-15,k8-15)
                mma_f16(acc[0][2 * p],     af[0], bf[0], bf[2]);
                mma_f16(acc[1][2 * p],     af[1], bf[0], bf[2]);
                mma_f16(acc[0][2 * p + 1], af[0], bf[1], bf[3]);
                mma_f16(acc[1][2 * p + 1], af[1], bf[1], bf[3]);
            }
        }
        cur = cur + 1; if (cur == 3) cur = 0;
        nxt = nxt + 1; if (nxt == 3) nxt = 0;
    }
#undef GF_ISSUE

#pragma unroll
    for (int mt = 0; mt < 2; mt++) {
        int row0 = brow + wm * 32 + mt * 16 + g;
#pragma unroll
        for (int nt = 0; nt < 8; nt++) {
            int col = bcol + wn * 64 + nt * 8 + tig * 2;
            float b0 = bias[col], b1 = bias[col + 1];
            float v00 = acc[mt][nt][0] + b0;
            float v01 = acc[mt][nt][1] + b1;
            float v10 = acc[mt][nt][2] + b0;
            float v11 = acc[mt][nt][3] + b1;
            if (GELU) {
                v00 *= normcdff(v00); v01 *= normcdff(v01);
                v10 *= normcdff(v10); v11 *= normcdff(v11);
            }
            if (res) {
                const float* r0p = res + (size_t)row0 * N + col;
                const float* r1p = res + (size_t)(row0 + 8) * N + col;
                v00 += r0p[0]; v01 += r0p[1];
                v10 += r1p[0]; v11 += r1p[1];
            }
            if (OUTH) {
                __half* Ch = (__half*)Cv;
                *(__half2*)(Ch + (size_t)row0 * N + col) = __floats2half2_rn(v00, v01);
                *(__half2*)(Ch + (size_t)(row0 + 8) * N + col) = __floats2half2_rn(v10, v11);
            } else {
                float* Cf = (float*)Cv;
                *(float2*)(Cf + (size_t)row0 * N + col) = make_float2(v00, v01);
                *(float2*)(Cf + (size_t)(row0 + 8) * N + col) = make_float2(v10, v11);
            }
        }
    }
}

// ==================== fp16 GEMM 64x128 (more blocks for N=768) =============
template <bool GELU, bool OUTH>
__global__ __launch_bounds__(256, 3)
void gemm_f16_m64(const __half* __restrict__ A, const __half* __restrict__ BmT,
                  const float* __restrict__ bias, const float* __restrict__ res,
                  void* __restrict__ Cv, int M, int N, int K) {
    extern __shared__ __half hsm[];
    __half* AsB = hsm;
    __half* BsB = hsm + 3 * AH64_SZ;
    int tid = threadIdx.x;
    int wid = tid >> 5, lane = tid & 31;
    int g = lane >> 2, tig = lane & 3;
    int wm = wid & 1, wn = wid >> 1;
    int brow = blockIdx.y * 64, bcol = blockIdx.x * 128;

    int arow = tid >> 2, ach = (tid & 3) * 8;   // A: 1 chunk/thread (64 rows x 4)
    const __half* apre = A + (size_t)(brow + arow) * K + ach;
    int asoA = arow * HST + ach;
    const __half* bpre[2];
    int bso[2];
#pragma unroll
    for (int i = 0; i < 2; i++) {
        int idx = tid + i * 256;
        int row = idx >> 2, ch = (idx & 3) * 8;
        bso[i] = row * HST + ch;
        bpre[i] = BmT + (size_t)(bcol + row) * K + ch;
    }

    int nIter = K >> 5;

#define GF_ISSUE64(KT, STG) do {                                              \
        cp16(&AsB[(STG) * AH64_SZ + asoA], apre + (KT) * 32);                 \
        __half* bsd_ = BsB + (STG) * BH_SZ;                                   \
        _Pragma("unroll")                                                     \
        for (int i = 0; i < 2; i++)                                           \
            cp16(&bsd_[bso[i]], bpre[i] + (KT) * 32);                         \
        cp_commit();                                                           \
    } while (0)

    GF_ISSUE64(0, 0);
    GF_ISSUE64(1, 1);

    float acc[2][4][4];
#pragma unroll
    for (int i = 0; i < 2; i++)
#pragma unroll
        for (int j = 0; j < 4; j++)
#pragma unroll
            for (int r = 0; r < 4; r++) acc[i][j][r] = 0.f;

    int l15 = lane & 15, lkh8 = (lane >> 4) << 3;

    int cur = 0, nxt = 2;
    for (int kt = 0; kt < nIter; ++kt) {
        if (kt + 1 < nIter) cp_wait<1>(); else cp_wait<0>();
        __syncthreads();
        if (kt + 2 < nIter) GF_ISSUE64(kt + 2, nxt);
        const __half* As = AsB + cur * AH64_SZ;
        const __half* Bs = BsB + cur * BH_SZ;
#pragma unroll
        for (int ks = 0; ks < 32; ks += 16) {
            unsigned af[2][4];
#pragma unroll
            for (int mt = 0; mt < 2; mt++) {
                int R = wm * 32 + mt * 16;
                ldsm4(af[mt], su32(&As[(R + l15) * HST + ks + lkh8]));
            }
#pragma unroll
            for (int p = 0; p < 2; p++) {
                unsigned bf[4];
                int nr = wn * 32 + p * 16;
                ldsm4(bf, su32(&Bs[(nr + l15) * HST + ks + lkh8]));
                mma_f16(acc[0][2 * p],     af[0], bf[0], bf[2]);
                mma_f16(acc[1][2 * p],     af[1], bf[0], bf[2]);
                mma_f16(acc[0][2 * p + 1], af[0], bf[1], bf[3]);
                mma_f16(acc[1][2 * p + 1], af[1], bf[1], bf[3]);
            }
        }
        cur = cur + 1; if (cur == 3) cur = 0;
        nxt = nxt + 1; if (nxt == 3) nxt = 0;
    }
#undef GF_ISSUE64

#pragma unroll
    for (int mt = 0; mt < 2; mt++) {
        int row0 = brow + wm * 32 + mt * 16 + g;
#pragma unroll
        for (int nt = 0; nt < 4; nt++) {
            int col = bcol + wn * 32 + nt * 8 + tig * 2;
            float b0 = bias[col], b1 = bias[col + 1];
            float v00 = acc[mt][nt][0] + b0;
            float v01 = acc[mt][nt][1] + b1;
            float v10 = acc[mt][nt][2] + b0;
            float v11 = acc[mt][nt][3] + b1;
            if (GELU) {
                v00 *= normcdff(v00); v01 *= normcdff(v01);
                v10 *= normcdff(v10); v11 *= normcdff(v11);
            }
            if (res) {
                const float* r0p = res + (size_t)row0 * N + col;
                const float* r1p = res + (size_t)(row0 + 8) * N + col;
                v00 += r0p[0]; v01 += r0p[1];
                v10 += r1p[0]; v11 += r1p[1];
            }
            if (OUTH) {
                __half* Ch = (__half*)Cv;
                *(__half2*)(Ch + (size_t)row0 * N + col) = __floats2half2_rn(v00, v01);
                *(__half2*)(Ch + (size_t)(row0 + 8) * N + col) = __floats2half2_rn(v10, v11);
            } else {
                float* Cf = (float*)Cv;
                *(float2*)(Cf + (size_t)row0 * N + col) = make_float2(v00, v01);
                *(float2*)(Cf + (size_t)(row0 + 8) * N + col) = make_float2(v10, v11);
            }
        }
    }
}

// ==================== fp16 flash attention, BM=128 =========================
#define QHS 72
#define SC_STRIDE 68
// halves: Qh 128*72, Kh 64*72, Vh 64*72 ; fp32: Sc 128*68 ; halves: Ph 128*72 ; fp32 misc 384
#define AT_SMEM_BYTES ((128*QHS + 64*QHS + 64*QHS + 128*QHS) * 2 + 128*SC_STRIDE*4 + 384*4)

__global__ __launch_bounds__(256, 2)
void attn_f16(const __half* __restrict__ QKV, const float* __restrict__ ab,
              __half* __restrict__ O) {
    extern __shared__ __half hsm[];
    __half* Qh = hsm;                         // [128][72]
    __half* Kh = Qh + 128 * QHS;              // [64][72]
    __half* Vh = Kh + 64 * QHS;               // [64][72]
    float* Sc = (float*)(Vh + 64 * QHS);      // [128][68]
    __half* Ph = (__half*)(Sc + 128 * SC_STRIDE);   // [128][72]
    float* mrow = (float*)(Ph + 128 * QHS);
    float* lrow = mrow + 128;
    float* srow = lrow + 128;

    int tid = threadIdx.x;
    int wid = tid >> 5, lane = tid & 31;
    int g = lane >> 2, tig = lane & 3;
    int wm = wid >> 1, wn = wid & 1;
    int m0 = wm * 32, n0 = wn * 32;
    int l15 = lane & 15, lkh8 = (lane >> 4) << 3;

    int qb = blockIdx.x * 128;
    int h = blockIdx.y, b = blockIdx.z;
    size_t bh = (size_t)b * T_TOK * QKV_N + h * HEAD_DIM;
    const __half* qp = QKV + bh;
    const __half* kp = QKV + bh + 768;
    const __half* vp = QKV + bh + 1536;

#define K_ISSUE(KT) do {                                                      \
        int kb_ = (KT) * 64;                                                  \
        _Pragma("unroll")                                                     \
        for (int it = 0; it < 2; it++) {                                      \
            int idx_ = tid + it * 256;                                        \
            int r_ = idx_ >> 3, c_ = (idx_ & 7) * 8;                          \
            cp16(&Kh[r_ * QHS + c_], kp + (size_t)(kb_ + r_) * QKV_N + c_);   \
        }                                                                     \
        cp_commit();                                                          \
    } while (0)
#define V_ISSUE(KT) do {                                                      \
        int kb_ = (KT) * 64;                                                  \
        _Pragma("unroll")                                                     \
        for (int it = 0; it < 2; it++) {                                      \
            int idx_ = tid + it * 256;                                        \
            int r_ = idx_ >> 3, c_ = (idx_ & 7) * 8;                          \
            cp16(&Vh[r_ * QHS + c_], vp + (size_t)(kb_ + r_) * QKV_N + c_);   \
        }                                                                     \
        cp_commit();                                                          \
    } while (0)

    // prologue: Q (4 chunks/thread), K0, V0
#pragma unroll
    for (int it = 0; it < 4; it++) {
        int idx = tid + it * 256;
        int r = idx >> 3, c = (idx & 7) * 8;
        cp16(&Qh[r * QHS + c], qp + (size_t)(qb + r) * QKV_N + c);
    }
    cp_commit();
    K_ISSUE(0);
    V_ISSUE(0);
    if (tid < 128) { mrow[tid] = -1e30f; lrow[tid] = 0.f; }

    float o[2][4][4];
#pragma unroll
    for (int mt = 0; mt < 2; mt++)
#pragma unroll
        for (int nt = 0; nt < 4; nt++)
#pragma unroll
            for (int r = 0; r < 4; r++) o[mt][nt][r] = 0.f;

    float bias0 = ab[h * 2 + 0], bias1 = ab[h * 2 + 1];
    int qvar = qb >> 7;

    for (int kt = 0; kt < 32; kt++) {
        cp_wait<0>();
        __syncthreads();
        if (kt > 0) V_ISSUE(kt);

        // ---- S = Q @ K^T ----
        float s[2][4][4];
#pragma unroll
        for (int mt = 0; mt < 2; mt++)
#pragma unroll
            for (int nt = 0; nt < 4; nt++)
#pragma unroll
                for (int r = 0; r < 4; r++) s[mt][nt][r] = 0.f;
#pragma unroll
        for (int ks = 0; ks < 64; ks += 16) {
            unsigned af[2][4];
#pragma unroll
            for (int mt = 0; mt < 2; mt++) {
                int R = m0 + mt * 16;
                ldsm4(af[mt], su32(&Qh[(R + l15) * QHS + ks + lkh8]));
            }
#pragma unroll
            for (int p = 0; p < 2; p++) {
                unsigned bf[4];
                int nr = n0 + p * 16;
                ldsm4(bf, su32(&Kh[(nr + l15) * QHS + ks + lkh8]));
                mma_f16(s[0][2 * p],     af[0], bf[0], bf[2]);
                mma_f16(s[1][2 * p],     af[1], bf[0], bf[2]);
                mma_f16(s[0][2 * p + 1], af[0], bf[1], bf[3]);
                mma_f16(s[1][2 * p + 1], af[1], bf[1], bf[3]);
            }
        }
        float bias = (((kt * 64) >> 7) == qvar) ? bias0 : bias1;
#pragma unroll
        for (int mt = 0; mt < 2; mt++) {
            int r0 = m0 + mt * 16 + g;
#pragma unroll
            for (int nt = 0; nt < 4; nt++) {
                int col = n0 + nt * 8 + tig * 2;
                Sc[r0 * SC_STRIDE + col]     = s[mt][nt][0] + bias;
                Sc[r0 * SC_STRIDE + col + 1] = s[mt][nt][1] + bias;
                Sc[(r0 + 8) * SC_STRIDE + col]     = s[mt][nt][2] + bias;
                Sc[(r0 + 8) * SC_STRIDE + col + 1] = s[mt][nt][3] + bias;
            }
        }
        __syncthreads();
        if (kt + 1 < 32) K_ISSUE(kt + 1);

        // ---- online softmax: read Sc (fp32), write Ph (fp16) ----
        {
            int r = tid >> 1, seg = tid & 1;
            const float* sr = &Sc[r * SC_STRIDE + seg * 32];
            __half* pr = &Ph[r * QHS + seg * 32];
            float mo = mrow[r];
            float mx = -1e30f;
#pragma unroll
            for (int j = 0; j < 32; j++) mx = fmaxf(mx, sr[j]);
            mx = fmaxf(mx, __shfl_xor_sync(0xffffffffu, mx, 1));
            mx = fmaxf(mx, mo);
            float sum = 0.f;
#pragma unroll
            for (int j = 0; j < 32; j++) {
                float p = __expf(sr[j] - mx);
                pr[j] = __float2half(p);
                sum += p;
            }
            sum += __shfl_xor_sync(0xffffffffu, sum, 1);
            if (seg == 0) {
                float scl = __expf(mo - mx);
                mrow[r] = mx;
                lrow[r] = lrow[r] * scl + sum;
                srow[r] = scl;
            }
        }
        if (kt + 1 < 32) cp_wait<1>(); else cp_wait<0>();
        __syncthreads();

        // ---- rescale + O += P @ V ----
#pragma unroll
        for (int mt = 0; mt < 2; mt++) {
            int r0 = m0 + mt * 16 + g;
            float scl0 = srow[r0], scl1 = srow[r0 + 8];
#pragma unroll
            for (int nt = 0; nt < 4; nt++) {
                o[mt][nt][0] *= scl0; o[mt][nt][1] *= scl0;
                o[mt][nt][2] *= scl1; o[mt][nt][3] *= scl1;
            }
        }
#pragma unroll
        for (int ks = 0; ks < 64; ks += 16) {
            unsigned af[2][4];
#pragma unroll
            for (int mt = 0; mt < 2; mt++) {
                int R = m0 + mt * 16;
                ldsm4(af[mt], su32(&Ph[(R + l15) * QHS + ks + lkh8]));
            }
#pragma unroll
            for (int p = 0; p < 2; p++) {
                unsigned bf[4];
                int cb = n0 + p * 16;
                // trans ldmatrix: rows = k (token), cols = n (dim)
                ldsm4t(bf, su32(&Vh[(ks + l15) * QHS + cb + lkh8]));
                // r0=b0(n cb..+7), r1=b1(n cb..+7), r2=b0(n cb+8..), r3=b1
                mma_f16(o[0][2 * p],     af[0], bf[0], bf[1]);
                mma_f16(o[1][2 * p],     af[1], bf[0], bf[1]);
                mma_f16(o[0][2 * p + 1], af[0], bf[2], bf[3]);
                mma_f16(o[1][2 * p + 1], af[1], bf[2], bf[3]);
            }
        }
    }
#undef K_ISSUE
#undef V_ISSUE

    // ---- normalize + write fp16 ----
#pragma unroll
    for (int mt = 0; mt < 2; mt++) {
        int r0 = m0 + mt * 16 + g;
        float inv0 = 1.f / lrow[r0], inv1 = 1.f / lrow[r0 + 8];
        int row0 = qb + r0;
#pragma unroll
        for (int nt = 0; nt < 4; nt++) {
            int col = n0 + nt * 8 + tig * 2;
            __half* o0 = O + (size_t)(b * T_TOK + row0) * D_MODEL + h * HEAD_DIM + col;
            __half* o1 = O + (size_t)(b * T_TOK + row0 + 8) * D_MODEL + h * HEAD_DIM + col;
            *(__half2*)o0 = __floats2half2_rn(o[mt][nt][0] * inv0, o[mt][nt][1] * inv0);
            *(__half2*)o1 = __floats2half2_rn(o[mt][nt][2] * inv1, o[mt][nt][3] * inv1);
        }
    }
}

// -------------------- launch ----------------------------------------------
extern "C" void kernel_launch(void* const* d_in, const int* in_sizes, int n_in,
                              void* d_out, int out_size) {
    const float* hs  = (const float*)d_in[0];
    const float* wq  = (const float*)d_in[1];
    const float* bq  = (const float*)d_in[2];
    const float* wk  = (const float*)d_in[3];
    const float* bk  = (const float*)d_in[4];
    const float* wv  = (const float*)d_in[5];
    const float* bv  = (const float*)d_in[6];
    const float* wo  = (const float*)d_in[7];
    const float* bo  = (const float*)d_in[8];
    const float* ab  = (const float*)d_in[9];
    const float* g1  = (const float*)d_in[10];
    const float* be1 = (const float*)d_in[11];
    const float* g3  = (const float*)d_in[12];
    const float* be3 = (const float*)d_in[13];
    const float* w1  = (const float*)d_in[14];
    const float* b1  = (const float*)d_in[15];
    const float* w2  = (const float*)d_in[16];
    const float* b2  = (const float*)d_in[17];
    float* out = (float*)d_out;

    __half *ni, *qkv, *wqkvT, *woT, *w1T, *w2T, *attn, *ffin, *hbuf;
    float *bqkv, *res1, *trig;
    cudaGetSymbolAddress((void**)&ni,    g_ni);
    cudaGetSymbolAddress((void**)&qkv,   g_qkv);
    cudaGetSymbolAddress((void**)&wqkvT, g_wqkvT);
    cudaGetSymbolAddress((void**)&bqkv,  g_bqkv);
    cudaGetSymbolAddress((void**)&woT,   g_woT);
    cudaGetSymbolAddress((void**)&w1T,   g_w1T);
    cudaGetSymbolAddress((void**)&w2T,   g_w2T);
    cudaGetSymbolAddress((void**)&attn,  g_attn);
    cudaGetSymbolAddress((void**)&res1,  g_res1);
    cudaGetSymbolAddress((void**)&ffin,  g_ffin);
    cudaGetSymbolAddress((void**)&hbuf,  g_h);
    cudaGetSymbolAddress((void**)&trig,  g_trig);

    static bool attr_set = false;
    if (!attr_set) {
        cudaFuncSetAttribute(attn_f16, cudaFuncAttributeMaxDynamicSharedMemorySize,
                             AT_SMEM_BYTES);
        cudaFuncSetAttribute((gemm_f16<false, true>), cudaFuncAttributeMaxDynamicSharedMemorySize,
                             G128_SMEM_BYTES);
        cudaFuncSetAttribute((gemm_f16<true, true>), cudaFuncAttributeMaxDynamicSharedMemorySize,
                             G128_SMEM_BYTES);
        cudaFuncSetAttribute((gemm_f16_m64<false, false>), cudaFuncAttributeMaxDynamicSharedMemorySize,
                             G64_SMEM_BYTES);
        attr_set = true;
    }

    // 0. prep: trig, bias concat, weight transposes (fp16)
    trig_kernel<<<(T_TOK * 16 + 255) / 256, 256>>>(trig);
    concat_bias<<<(QKV_N + 255) / 256, 256>>>(bq, bk, bv, bqkv);
    {
        dim3 blk(32, 8);
        transpose_w<<<dim3(24, 24), blk>>>(wq, wqkvT, 768, 768, 0.125f);
        transpose_w<<<dim3(24, 24), blk>>>(wk, wqkvT + 768 * 768, 768, 768, 1.f);
        transpose_w<<<dim3(24, 24), blk>>>(wv, wqkvT + 1536 * 768, 768, 768, 1.f);
        transpose_w<<<dim3(24, 24), blk>>>(wo, woT, 768, 768, 1.f);
        transpose_w<<<dim3(96, 24), blk>>>(w1, w1T, 768, 3072, 1.f);
        transpose_w<<<dim3(24, 96), blk>>>(w2, w2T, 3072, 768, 1.f);
    }

    // 1. LN1 -> fp16
    ln_kernel<<<M_ROWS, 256>>>(hs, g1, be1, ni);

    // 2. fused QKV projection -> fp16 qkv
    gemm_f16<false, true><<<dim3(QKV_N / 128, M_ROWS / 128), 256, G128_SMEM_BYTES>>>(
        ni, wqkvT, bqkv, nullptr, qkv, M_ROWS, QKV_N, D_MODEL);

    // 3. RoPE (fp16 in-place)
    {
        int total = BATCH * T_TOK * N_HEADS * 16;
        rope_apply<<<(total + 255) / 256, 256>>>(qkv, trig);
    }

    // 4. attention (fp16) -> fp16 attn
    {
        dim3 ga(T_TOK / 128, N_HEADS, BATCH);
        attn_f16<<<ga, 256, AT_SMEM_BYTES>>>(qkv, ab, attn);
    }

    // 5. out-proj + residual(hs fp32) -> fp32 res1
    gemm_f16_m64<false, false><<<dim3(D_MODEL / 128, M_ROWS / 64), 256, G64_SMEM_BYTES>>>(
        attn, woT, bo, hs, res1, M_ROWS, D_MODEL, D_MODEL);

    // 6. LN3 -> fp16 ffin
    ln_kernel<<<M_ROWS, 256>>>(res1, g3, be3, ffin);

    // 7. FFN1 + exact GELU -> fp16 hbuf
    gemm_f16<true, true><<<dim3(FFN_DIM / 128, M_ROWS / 128), 256, G128_SMEM_BYTES>>>(
        ffin, w1T, b1, nullptr, hbuf, M_ROWS, FFN_DIM, D_MODEL);

    // 8. FFN2 + residual(res1) -> fp32 out
    gemm_f16_m64<false, false><<<dim3(D_MODEL / 128, M_ROWS / 64), 256, G64_SMEM_BYTES>>>(
        hbuf, w2T, b2, res1, out, M_ROWS, D_MODEL, FFN_DIM);
}

// round 12
// speedup vs baseline: 2.0842x; 1.3051x over previous
#include <cuda_runtime.h>
#include <cuda_fp16.h>
#include <math.h>
#include <stdint.h>

#define D_MODEL 768
#define N_HEADS 12
#define HEAD_DIM 64
#define FFN_DIM 3072
#define T_TOK 2048
#define BATCH 2
#define M_ROWS (BATCH * T_TOK)   // 4096
#define QKV_N 2304               // 3 * D_MODEL

// -------------------- scratch ---------------------------------------------
__device__ __half g_ni[M_ROWS * D_MODEL];
__device__ __half g_qkv[M_ROWS * QKV_N];
__device__ __half g_wqkvT[QKV_N * D_MODEL];
__device__ float  g_bqkv[QKV_N];
__device__ __half g_woT[D_MODEL * D_MODEL];
__device__ __half g_w1T[FFN_DIM * D_MODEL];
__device__ __half g_w2T[D_MODEL * FFN_DIM];
__device__ __half g_attn[M_ROWS * D_MODEL];
__device__ float  g_res1[M_ROWS * D_MODEL];
__device__ __half g_ffin[M_ROWS * D_MODEL];
__device__ __half g_h[M_ROWS * FFN_DIM];
__device__ float  g_trig[T_TOK * 16 * 2];

// -------------------- helpers ---------------------------------------------
__device__ __forceinline__ unsigned su32(const void* p) {
    return (unsigned)__cvta_generic_to_shared(p);
}
__device__ __forceinline__ void cp16(void* smem_dst, const void* gptr) {
    asm volatile("cp.async.cg.shared.global [%0], [%1], 16;" :: "r"(su32(smem_dst)), "l"(gptr));
}
__device__ __forceinline__ void cp_commit() { asm volatile("cp.async.commit_group;"); }
template <int NN>
__device__ __forceinline__ void cp_wait() { asm volatile("cp.async.wait_group %0;" :: "n"(NN)); }

__device__ __forceinline__ void mma_f16(float* c, const unsigned* a, unsigned b0, unsigned b1) {
    asm volatile(
        "mma.sync.aligned.m16n8k16.row.col.f32.f16.f16.f32 "
        "{%0,%1,%2,%3}, {%4,%5,%6,%7}, {%8,%9}, {%0,%1,%2,%3};"
        : "+f"(c[0]), "+f"(c[1]), "+f"(c[2]), "+f"(c[3])
        : "r"(a[0]), "r"(a[1]), "r"(a[2]), "r"(a[3]), "r"(b0), "r"(b1));
}
__device__ __forceinline__ void ldsm4(unsigned* r, unsigned addr) {
    asm volatile("ldmatrix.sync.aligned.m8n8.x4.shared.b16 {%0,%1,%2,%3}, [%4];"
                 : "=r"(r[0]), "=r"(r[1]), "=r"(r[2]), "=r"(r[3]) : "r"(addr));
}
__device__ __forceinline__ void ldsm4t(unsigned* r, unsigned addr) {
    asm volatile("ldmatrix.sync.aligned.m8n8.x4.trans.shared.b16 {%0,%1,%2,%3}, [%4];"
                 : "=r"(r[0]), "=r"(r[1]), "=r"(r[2]), "=r"(r[3]) : "r"(addr));
}
__device__ __forceinline__ unsigned pack2(float lo, float hi) {
    __half2 h = __floats2half2_rn(lo, hi);
    return *(unsigned*)&h;
}

// -------------------- block reduction -------------------------------------
__device__ __forceinline__ float block_sum_256(float val) {
    __shared__ float red[8];
    int lane = threadIdx.x & 31, w = threadIdx.x >> 5;
#pragma unroll
    for (int o = 16; o; o >>= 1) val += __shfl_xor_sync(0xffffffffu, val, o);
    if (lane == 0) red[w] = val;
    __syncthreads();
    if (w == 0) {
        float t = (lane < 8) ? red[lane] : 0.f;
#pragma unroll
        for (int o = 4; o; o >>= 1) t += __shfl_xor_sync(0xffffffffu, t, o);
        if (lane == 0) red[0] = t;
    }
    __syncthreads();
    float r = red[0];
    __syncthreads();
    return r;
}

// -------------------- LayerNorm (fp32 in, fp16 out) ------------------------
__global__ void ln_kernel(const float* __restrict__ x, const float* __restrict__ g,
                          const float* __restrict__ bta, __half* __restrict__ y) {
    size_t row = blockIdx.x;
    int tid = threadIdx.x;
    const float* xr = x + row * D_MODEL;
    float v0 = xr[tid], v1 = xr[tid + 256], v2 = xr[tid + 512];
    float mu = block_sum_256(v0 + v1 + v2) * (1.f / 768.f);
    float d0 = v0 - mu, d1 = v1 - mu, d2 = v2 - mu;
    float var = block_sum_256(d0 * d0 + d1 * d1 + d2 * d2) * (1.f / 768.f);
    float rs = rsqrtf(var + 1e-5f);
    __half* yr = y + row * D_MODEL;
    yr[tid]       = __float2half(d0 * rs * g[tid]       + bta[tid]);
    yr[tid + 256] = __float2half(d1 * rs * g[tid + 256] + bta[tid + 256]);
    yr[tid + 512] = __float2half(d2 * rs * g[tid + 512] + bta[tid + 512]);
}

// -------------------- weight transpose + fp16 convert ----------------------
__global__ void transpose_w(const float* __restrict__ src, __half* __restrict__ dst,
                            int R, int C, float scale) {
    __shared__ float t[32][33];
    int bx = blockIdx.x * 32;
    int by = blockIdx.y * 32;
    int x = threadIdx.x, y = threadIdx.y;
#pragma unroll
    for (int i = 0; i < 32; i += 8)
        t[y + i][x] = src[(size_t)(by + y + i) * C + bx + x] * scale;
    __syncthreads();
#pragma unroll
    for (int i = 0; i < 32; i += 8)
        dst[(size_t)(bx + y + i) * R + by + x] = __float2half(t[x][y + i]);
}

// -------------------- bias concat -----------------------------------------
__global__ void concat_bias(const float* __restrict__ bq, const float* __restrict__ bk,
                            const float* __restrict__ bv, float* __restrict__ Bo) {
    int j = blockIdx.x * 256 + threadIdx.x;
    if (j < 768) Bo[j] = bq[j] * 0.125f;
    else if (j < 1536) Bo[j] = bk[j - 768];
    else if (j < 2304) Bo[j] = bv[j - 1536];
}

// -------------------- trig table ------------------------------------------
__global__ void trig_kernel(float* __restrict__ trig) {
    int idx = blockIdx.x * 256 + threadIdx.x;
    if (idx >= T_TOK * 16) return;
    int t = idx >> 4, i = idx & 15;
    double ts = pow(10000.0, (double)i / 32.0);
    double ang = (double)t / ts;
    double sd, cd;
    sincos(ang, &sd, &cd);
    trig[idx * 2]     = (float)cd;
    trig[idx * 2 + 1] = (float)sd;
}

// ==================== fp16 GEMM 128x128, BK=32, 3-stage ====================
// ROPE: rotate q/k bands in-epilogue (QKV projection only).
#define HST 40
#define AH_SZ (128 * HST)
#define BH_SZ (128 * HST)
#define G128_SMEM_BYTES (3 * (AH_SZ + BH_SZ) * 2)
#define AH64_SZ (64 * HST)
#define G64_SMEM_BYTES (3 * (AH64_SZ + BH_SZ) * 2)

template <bool GELU, bool OUTH, bool ROPE>
__global__ __launch_bounds__(256, 2)
void gemm_f16(const __half* __restrict__ A, const __half* __restrict__ BmT,
              const float* __restrict__ bias, const float* __restrict__ res,
              void* __restrict__ Cv, const float* __restrict__ trig,
              int M, int N, int K) {
    extern __shared__ __half hsm[];
    __half* AsB = hsm;
    __half* BsB = hsm + 3 * AH_SZ;
    int tid = threadIdx.x;
    int wid = tid >> 5, lane = tid & 31;
    int g = lane >> 2, tig = lane & 3;
    int wm = wid & 3, wn = wid >> 2;
    int brow = blockIdx.y * 128, bcol = blockIdx.x * 128;

    const __half* apre[2];
    const __half* bpre[2];
    int aso[2];
#pragma unroll
    for (int i = 0; i < 2; i++) {
        int idx = tid + i * 256;
        int row = idx >> 2, ch = (idx & 3) * 8;
        aso[i] = row * HST + ch;
        apre[i] = A + (size_t)(brow + row) * K + ch;
        bpre[i] = BmT + (size_t)(bcol + row) * K + ch;
    }

    int nIter = K >> 5;

#define GF_ISSUE(KT, STG) do {                                                \
        __half* asd_ = AsB + (STG) * AH_SZ;                                   \
        __half* bsd_ = BsB + (STG) * BH_SZ;                                   \
        _Pragma("unroll")                                                     \
        for (int i = 0; i < 2; i++) {                                         \
            cp16(&asd_[aso[i]], apre[i] + (KT) * 32);                         \
            cp16(&bsd_[aso[i]], bpre[i] + (KT) * 32);                         \
        }                                                                     \
        cp_commit();                                                           \
    } while (0)

    GF_ISSUE(0, 0);
    GF_ISSUE(1, 1);

    float acc[2][8][4];
#pragma unroll
    for (int i = 0; i < 2; i++)
#pragma unroll
        for (int j = 0; j < 8; j++)
#pragma unroll
            for (int r = 0; r < 4; r++) acc[i][j][r] = 0.f;

    int l15 = lane & 15, lkh8 = (lane >> 4) << 3;

    int cur = 0, nxt = 2;
    for (int kt = 0; kt < nIter; ++kt) {
        if (kt + 1 < nIter) cp_wait<1>(); else cp_wait<0>();
        __syncthreads();
        if (kt + 2 < nIter) GF_ISSUE(kt + 2, nxt);
        const __half* As = AsB + cur * AH_SZ;
        const __half* Bs = BsB + cur * BH_SZ;
#pragma unroll
        for (int ks = 0; ks < 32; ks += 16) {
            unsigned af[2][4];
#pragma unroll
            for (int mt = 0; mt < 2; mt++) {
                int R = wm * 32 + mt * 16;
                ldsm4(af[mt], su32(&As[(R + l15) * HST + ks + lkh8]));
            }
#pragma unroll
            for (int p = 0; p < 4; p++) {
                unsigned bf[4];
                int nr = wn * 64 + p * 16;
                ldsm4(bf, su32(&Bs[(nr + l15) * HST + ks + lkh8]));
                mma_f16(acc[0][2 * p],     af[0], bf[0], bf[2]);
                mma_f16(acc[1][2 * p],     af[1], bf[0], bf[2]);
                mma_f16(acc[0][2 * p + 1], af[0], bf[1], bf[3]);
                mma_f16(acc[1][2 * p + 1], af[1], bf[1], bf[3]);
            }
        }
        cur = cur + 1; if (cur == 3) cur = 0;
        nxt = nxt + 1; if (nxt == 3) nxt = 0;
    }
#undef GF_ISSUE

#pragma unroll
    for (int mt = 0; mt < 2; mt++) {
        int row0 = brow + wm * 32 + mt * 16 + g;
        int t0 = row0 & (T_TOK - 1);
        int t1 = (row0 + 8) & (T_TOK - 1);
        bool doRope = ROPE && (bcol + wn * 64) < 1536;
#pragma unroll
        for (int nt2 = 0; nt2 < 4; nt2++) {
            int ntA = nt2, ntB = nt2 + 4;
            int colA = bcol + wn * 64 + ntA * 8 + tig * 2;
            int colB = colA + 32;
            float bA0 = bias[colA], bA1 = bias[colA + 1];
            float bB0 = bias[colB], bB1 = bias[colB + 1];
            float vA00 = acc[mt][ntA][0] + bA0, vA01 = acc[mt][ntA][1] + bA1;
            float vA10 = acc[mt][ntA][2] + bA0, vA11 = acc[mt][ntA][3] + bA1;
            float vB00 = acc[mt][ntB][0] + bB0, vB01 = acc[mt][ntB][1] + bB1;
            float vB10 = acc[mt][ntB][2] + bB0, vB11 = acc[mt][ntB][3] + bB1;
            if (doRope && nt2 < 2) {
                int i0 = ntA * 8 + tig * 2;     // 0..15
                float c00 = trig[(t0 * 16 + i0) * 2],     s00 = trig[(t0 * 16 + i0) * 2 + 1];
                float c01 = trig[(t0 * 16 + i0 + 1) * 2], s01 = trig[(t0 * 16 + i0 + 1) * 2 + 1];
                float c10 = trig[(t1 * 16 + i0) * 2],     s10 = trig[(t1 * 16 + i0) * 2 + 1];
                float c11 = trig[(t1 * 16 + i0 + 1) * 2], s11 = trig[(t1 * 16 + i0 + 1) * 2 + 1];
                float x1, x2;
                x1 = vA00; x2 = vB00; vA00 = x1 * c00 - x2 * s00; vB00 = x2 * c00 + x1 * s00;
                x1 = vA01; x2 = vB01; vA01 = x1 * c01 - x2 * s01; vB01 = x2 * c01 + x1 * s01;
                x1 = vA10; x2 = vB10; vA10 = x1 * c10 - x2 * s10; vB10 = x2 * c10 + x1 * s10;
                x1 = vA11; x2 = vB11; vA11 = x1 * c11 - x2 * s11; vB11 = x2 * c11 + x1 * s11;
            }
            if (GELU) {
                vA00 *= normcdff(vA00); vA01 *= normcdff(vA01);
                vA10 *= normcdff(vA10); vA11 *= normcdff(vA11);
                vB00 *= normcdff(vB00); vB01 *= normcdff(vB01);
                vB10 *= normcdff(vB10); vB11 *= normcdff(vB11);
            }
            if (res) {
                const float* r0A = res + (size_t)row0 * N + colA;
                const float* r1A = res + (size_t)(row0 + 8) * N + colA;
                vA00 += r0A[0]; vA01 += r0A[1]; vA10 += r1A[0]; vA11 += r1A[1];
                const float* r0B = res + (size_t)row0 * N + colB;
                const float* r1B = res + (size_t)(row0 + 8) * N + colB;
                vB00 += r0B[0]; vB01 += r0B[1]; vB10 += r1B[0]; vB11 += r1B[1];
            }
            if (OUTH) {
                __half* Ch = (__half*)Cv;
                *(__half2*)(Ch + (size_t)row0 * N + colA) = __floats2half2_rn(vA00, vA01);
                *(__half2*)(Ch + (size_t)(row0 + 8) * N + colA) = __floats2half2_rn(vA10, vA11);
                *(__half2*)(Ch + (size_t)row0 * N + colB) = __floats2half2_rn(vB00, vB01);
                *(__half2*)(Ch + (size_t)(row0 + 8) * N + colB) = __floats2half2_rn(vB10, vB11);
            } else {
                float* Cf = (float*)Cv;
                *(float2*)(Cf + (size_t)row0 * N + colA) = make_float2(vA00, vA01);
                *(float2*)(Cf + (size_t)(row0 + 8) * N + colA) = make_float2(vA10, vA11);
                *(float2*)(Cf + (size_t)row0 * N + colB) = make_float2(vB00, vB01);
                *(float2*)(Cf + (size_t)(row0 + 8) * N + colB) = make_float2(vB10, vB11);
            }
        }
    }
}

// ==================== fp16 GEMM 64x128 (N=768 GEMMs) =======================
template <bool GELU, bool OUTH>
__global__ __launch_bounds__(256, 3)
void gemm_f16_m64(const __half* __restrict__ A, const __half* __restrict__ BmT,
                  const float* __restrict__ bias, const float* __restrict__ res,
                  void* __restrict__ Cv, int M, int N, int K) {
    extern __shared__ __half hsm[];
    __half* AsB = hsm;
    __half* BsB = hsm + 3 * AH64_SZ;
    int tid = threadIdx.x;
    int wid = tid >> 5, lane = tid & 31;
    int g = lane >> 2, tig = lane & 3;
    int wm = wid & 1, wn = wid >> 1;
    int brow = blockIdx.y * 64, bcol = blockIdx.x * 128;

    int arow = tid >> 2, ach = (tid & 3) * 8;
    const __half* apre = A + (size_t)(brow + arow) * K + ach;
    int asoA = arow * HST + ach;
    const __half* bpre[2];
    int bso[2];
#pragma unroll
    for (int i = 0; i < 2; i++) {
        int idx = tid + i * 256;
        int row = idx >> 2, ch = (idx & 3) * 8;
        bso[i] = row * HST + ch;
        bpre[i] = BmT + (size_t)(bcol + row) * K + ch;
    }

    int nIter = K >> 5;

#define GF_ISSUE64(KT, STG) do {                                              \
        cp16(&AsB[(STG) * AH64_SZ + asoA], apre + (KT) * 32);                 \
        __half* bsd_ = BsB + (STG) * BH_SZ;                                   \
        _Pragma("unroll")                                                     \
        for (int i = 0; i < 2; i++)                                           \
            cp16(&bsd_[bso[i]], bpre[i] + (KT) * 32);                         \
        cp_commit();                                                           \
    } while (0)

    GF_ISSUE64(0, 0);
    GF_ISSUE64(1, 1);

    float acc[2][4][4];
#pragma unroll
    for (int i = 0; i < 2; i++)
#pragma unroll
        for (int j = 0; j < 4; j++)
#pragma unroll
            for (int r = 0; r < 4; r++) acc[i][j][r] = 0.f;

    int l15 = lane & 15, lkh8 = (lane >> 4) << 3;

    int cur = 0, nxt = 2;
    for (int kt = 0; kt < nIter; ++kt) {
        if (kt + 1 < nIter) cp_wait<1>(); else cp_wait<0>();
        __syncthreads();
        if (kt + 2 < nIter) GF_ISSUE64(kt + 2, nxt);
        const __half* As = AsB + cur * AH64_SZ;
        const __half* Bs = BsB + cur * BH_SZ;
#pragma unroll
        for (int ks = 0; ks < 32; ks += 16) {
            unsigned af[2][4];
#pragma unroll
            for (int mt = 0; mt < 2; mt++) {
                int R = wm * 32 + mt * 16;
                ldsm4(af[mt], su32(&As[(R + l15) * HST + ks + lkh8]));
            }
#pragma unroll
            for (int p = 0; p < 2; p++) {
                unsigned bf[4];
                int nr = wn * 32 + p * 16;
                ldsm4(bf, su32(&Bs[(nr + l15) * HST + ks + lkh8]));
                mma_f16(acc[0][2 * p],     af[0], bf[0], bf[2]);
                mma_f16(acc[1][2 * p],     af[1], bf[0], bf[2]);
                mma_f16(acc[0][2 * p + 1], af[0], bf[1], bf[3]);
                mma_f16(acc[1][2 * p + 1], af[1], bf[1], bf[3]);
            }
        }
        cur = cur + 1; if (cur == 3) cur = 0;
        nxt = nxt + 1; if (nxt == 3) nxt = 0;
    }
#undef GF_ISSUE64

#pragma unroll
    for (int mt = 0; mt < 2; mt++) {
        int row0 = brow + wm * 32 + mt * 16 + g;
#pragma unroll
        for (int nt = 0; nt < 4; nt++) {
            int col = bcol + wn * 32 + nt * 8 + tig * 2;
            float b0 = bias[col], b1 = bias[col + 1];
            float v00 = acc[mt][nt][0] + b0;
            float v01 = acc[mt][nt][1] + b1;
            float v10 = acc[mt][nt][2] + b0;
            float v11 = acc[mt][nt][3] + b1;
            if (GELU) {
                v00 *= normcdff(v00); v01 *= normcdff(v01);
                v10 *= normcdff(v10); v11 *= normcdff(v11);
            }
            if (res) {
                const float* r0p = res + (size_t)row0 * N + col;
                const float* r1p = res + (size_t)(row0 + 8) * N + col;
                v00 += r0p[0]; v01 += r0p[1];
                v10 += r1p[0]; v11 += r1p[1];
            }
            if (OUTH) {
                __half* Ch = (__half*)Cv;
                *(__half2*)(Ch + (size_t)row0 * N + col) = __floats2half2_rn(v00, v01);
                *(__half2*)(Ch + (size_t)(row0 + 8) * N + col) = __floats2half2_rn(v10, v11);
            } else {
                float* Cf = (float*)Cv;
                *(float2*)(Cf + (size_t)row0 * N + col) = make_float2(v00, v01);
                *(float2*)(Cf + (size_t)(row0 + 8) * N + col) = make_float2(v10, v11);
            }
        }
    }
}

// ==================== fp16 flash attention: register P, 1 sync/iter ========
#define QHS 72
#define KV_SZ (64 * QHS)
#define AT_SMEM_BYTES ((128 * QHS + 4 * KV_SZ) * 2)

__global__ __launch_bounds__(256, 2)
void attn_f16(const __half* __restrict__ QKV, const float* __restrict__ ab,
              __half* __restrict__ O) {
    extern __shared__ __half hsm[];
    __half* Qh = hsm;                      // [128][72]
    __half* KhB = Qh + 128 * QHS;          // [2][64][72]
    __half* VhB = KhB + 2 * KV_SZ;         // [2][64][72]

    int tid = threadIdx.x;
    int wid = tid >> 5, lane = tid & 31;
    int g = lane >> 2, tig = lane & 3;
    int m0 = wid * 16;                     // warp tile: 16 rows x 64 cols
    int l15 = lane & 15, lkh8 = (lane >> 4) << 3;

    int qb = blockIdx.x * 128;
    int h = blockIdx.y, b = blockIdx.z;
    size_t bh = (size_t)b * T_TOK * QKV_N + h * HEAD_DIM;
    const __half* qp = QKV + bh;
    const __half* kp = QKV + bh + 768;
    const __half* vp = QKV + bh + 1536;

#define G_ISSUE(KT, BUF) do {                                                 \
        int kb_ = (KT) * 64;                                                  \
        __half* kd_ = KhB + (BUF) * KV_SZ;                                    \
        __half* vd_ = VhB + (BUF) * KV_SZ;                                    \
        _Pragma("unroll")                                                     \
        for (int it = 0; it < 2; it++) {                                      \
            int idx_ = tid + it * 256;                                        \
            int r_ = idx_ >> 3, c_ = (idx_ & 7) * 8;                          \
            cp16(&kd_[r_ * QHS + c_], kp + (size_t)(kb_ + r_) * QKV_N + c_);  \
            cp16(&vd_[r_ * QHS + c_], vp + (size_t)(kb_ + r_) * QKV_N + c_);  \
        }                                                                     \
        cp_commit();                                                          \
    } while (0)

    // prologue: Q (4 chunks/thread) + K0/V0
#pragma unroll
    for (int it = 0; it < 4; it++) {
        int idx = tid + it * 256;
        int r = idx >> 3, c = (idx & 7) * 8;
        cp16(&Qh[r * QHS + c], qp + (size_t)(qb + r) * QKV_N + c);
    }
    cp_commit();
    G_ISSUE(0, 0);

    float mo0 = -1e30f, mo1 = -1e30f, l0 = 0.f, l1 = 0.f;
    float o[8][4];
#pragma unroll
    for (int nt = 0; nt < 8; nt++)
#pragma unroll
        for (int r = 0; r < 4; r++) o[nt][r] = 0.f;

    float bias0 = ab[h * 2 + 0], bias1 = ab[h * 2 + 1];
    int qvar = qb >> 7;

    for (int kt = 0; kt < 32; kt++) {
        cp_wait<0>();
        __syncthreads();              // K/V(kt) visible; buf cur^1 free (readers of kt-1 done)
        int cur = kt & 1;
        if (kt + 1 < 32) G_ISSUE(kt + 1, cur ^ 1);
        const __half* Kh = KhB + cur * KV_SZ;
        const __half* Vh = VhB + cur * KV_SZ;

        // ---- S = Q @ K^T : warp owns 16 rows x 64 cols ----
        float s[8][4];
#pragma unroll
        for (int nt = 0; nt < 8; nt++)
#pragma unroll
            for (int r = 0; r < 4; r++) s[nt][r] = 0.f;
#pragma unroll
        for (int ks = 0; ks < 64; ks += 16) {
            unsigned af[4];
            ldsm4(af, su32(&Qh[(m0 + l15) * QHS + ks + lkh8]));
#pragma unroll
            for (int p = 0; p < 4; p++) {
                unsigned bf[4];
                ldsm4(bf, su32(&Kh[(p * 16 + l15) * QHS + ks + lkh8]));
                mma_f16(s[2 * p],     af, bf[0], bf[2]);
                mma_f16(s[2 * p + 1], af, bf[1], bf[3]);
            }
        }

        // ---- softmax entirely in registers (rows m0+g, m0+g+8) ----
        float bias = (((kt * 64) >> 7) == qvar) ? bias0 : bias1;
        float mx0 = mo0, mx1 = mo1;
#pragma unroll
        for (int nt = 0; nt < 8; nt++) {
            s[nt][0] += bias; s[nt][1] += bias; s[nt][2] += bias; s[nt][3] += bias;
            mx0 = fmaxf(mx0, fmaxf(s[nt][0], s[nt][1]));
            mx1 = fmaxf(mx1, fmaxf(s[nt][2], s[nt][3]));
        }
        mx0 = fmaxf(mx0, __shfl_xor_sync(0xffffffffu, mx0, 1));
        mx0 = fmaxf(mx0, __shfl_xor_sync(0xffffffffu, mx0, 2));
        mx1 = fmaxf(mx1, __shfl_xor_sync(0xffffffffu, mx1, 1));
        mx1 = fmaxf(mx1, __shfl_xor_sync(0xffffffffu, mx1, 2));
        float scl0 = __expf(mo0 - mx0), scl1 = __expf(mo1 - mx1);
        float sum0 = 0.f, sum1 = 0.f;
#pragma unroll
        for (int nt = 0; nt < 8; nt++) {
            s[nt][0] = __expf(s[nt][0] - mx0); sum0 += s[nt][0];
            s[nt][1] = __expf(s[nt][1] - mx0); sum0 += s[nt][1];
            s[nt][2] = __expf(s[nt][2] - mx1); sum1 += s[nt][2];
            s[nt][3] = __expf(s[nt][3] - mx1); sum1 += s[nt][3];
        }
        sum0 += __shfl_xor_sync(0xffffffffu, sum0, 1);
        sum0 += __shfl_xor_sync(0xffffffffu, sum0, 2);
        sum1 += __shfl_xor_sync(0xffffffffu, sum1, 1);
        sum1 += __shfl_xor_sync(0xffffffffu, sum1, 2);
        l0 = l0 * scl0 + sum0; mo0 = mx0;
        l1 = l1 * scl1 + sum1; mo1 = mx1;
#pragma unroll
        for (int nt = 0; nt < 8; nt++) {
            o[nt][0] *= scl0; o[nt][1] *= scl0;
            o[nt][2] *= scl1; o[nt][3] *= scl1;
        }

        // ---- O += P @ V : P from registers (S frag == A frag layout) ----
#pragma unroll
        for (int p = 0; p < 4; p++) {
            unsigned af2[4];
            af2[0] = pack2(s[2 * p][0],     s[2 * p][1]);       // (row g,   k 16p+2tig)
            af2[1] = pack2(s[2 * p][2],     s[2 * p][3]);       // (row g+8, k 16p+2tig)
            af2[2] = pack2(s[2 * p + 1][0], s[2 * p + 1][1]);   // (row g,   k 16p+8+2tig)
            af2[3] = pack2(s[2 * p + 1][2], s[2 * p + 1][3]);   // (row g+8, ...)
#pragma unroll
            for (int cbt = 0; cbt < 4; cbt++) {
                unsigned bf[4];
                ldsm4t(bf, su32(&Vh[(p * 16 + l15) * QHS + cbt * 16 + lkh8]));
                mma_f16(o[2 * cbt],     af2, bf[0], bf[1]);
                mma_f16(o[2 * cbt + 1], af2, bf[2], bf[3]);
            }
        }
    }
#undef G_ISSUE

    // ---- normalize + write fp16 ----
    float inv0 = 1.f / l0, inv1 = 1.f / l1;
    int row0 = qb + m0 + g;
#pragma unroll
    for (int nt = 0; nt < 8; nt++) {
        int col = nt * 8 + tig * 2;
        __half* o0 = O + (size_t)(b * T_TOK + row0) * D_MODEL + h * HEAD_DIM + col;
        __half* o1 = O + (size_t)(b * T_TOK + row0 + 8) * D_MODEL + h * HEAD_DIM + col;
        *(__half2*)o0 = __floats2half2_rn(o[nt][0] * inv0, o[nt][1] * inv0);
        *(__half2*)o1 = __floats2half2_rn(o[nt][2] * inv1, o[nt][3] * inv1);
    }
}

// -------------------- launch ----------------------------------------------
extern "C" void kernel_launch(void* const* d_in, const int* in_sizes, int n_in,
                              void* d_out, int out_size) {
    const float* hs  = (const float*)d_in[0];
    const float* wq  = (const float*)d_in[1];
    const float* bq  = (const float*)d_in[2];
    const float* wk  = (const float*)d_in[3];
    const float* bk  = (const float*)d_in[4];
    const float* wv  = (const float*)d_in[5];
    const float* bv  = (const float*)d_in[6];
    const float* wo  = (const float*)d_in[7];
    const float* bo  = (const float*)d_in[8];
    const float* ab  = (const float*)d_in[9];
    const float* g1  = (const float*)d_in[10];
    const float* be1 = (const float*)d_in[11];
    const float* g3  = (const float*)d_in[12];
    const float* be3 = (const float*)d_in[13];
    const float* w1  = (const float*)d_in[14];
    const float* b1  = (const float*)d_in[15];
    const float* w2  = (const float*)d_in[16];
    const float* b2  = (const float*)d_in[17];
    float* out = (float*)d_out;

    __half *ni, *qkv, *wqkvT, *woT, *w1T, *w2T, *attn, *ffin, *hbuf;
    float *bqkv, *res1, *trig;
    cudaGetSymbolAddress((void**)&ni,    g_ni);
    cudaGetSymbolAddress((void**)&qkv,   g_qkv);
    cudaGetSymbolAddress((void**)&wqkvT, g_wqkvT);
    cudaGetSymbolAddress((void**)&bqkv,  g_bqkv);
    cudaGetSymbolAddress((void**)&woT,   g_woT);
    cudaGetSymbolAddress((void**)&w1T,   g_w1T);
    cudaGetSymbolAddress((void**)&w2T,   g_w2T);
    cudaGetSymbolAddress((void**)&attn,  g_attn);
    cudaGetSymbolAddress((void**)&res1,  g_res1);
    cudaGetSymbolAddress((void**)&ffin,  g_ffin);
    cudaGetSymbolAddress((void**)&hbuf,  g_h);
    cudaGetSymbolAddress((void**)&trig,  g_trig);

    static bool attr_set = false;
    if (!attr_set) {
        cudaFuncSetAttribute(attn_f16, cudaFuncAttributeMaxDynamicSharedMemorySize,
                             AT_SMEM_BYTES);
        cudaFuncSetAttribute((gemm_f16<false, true, true>), cudaFuncAttributeMaxDynamicSharedMemorySize,
                             G128_SMEM_BYTES);
        cudaFuncSetAttribute((gemm_f16<true, true, false>), cudaFuncAttributeMaxDynamicSharedMemorySize,
                             G128_SMEM_BYTES);
        cudaFuncSetAttribute((gemm_f16_m64<false, false>), cudaFuncAttributeMaxDynamicSharedMemorySize,
                             G64_SMEM_BYTES);
        attr_set = true;
    }

    // 0. prep
    trig_kernel<<<(T_TOK * 16 + 255) / 256, 256>>>(trig);
    concat_bias<<<(QKV_N + 255) / 256, 256>>>(bq, bk, bv, bqkv);
    {
        dim3 blk(32, 8);
        transpose_w<<<dim3(24, 24), blk>>>(wq, wqkvT, 768, 768, 0.125f);
        transpose_w<<<dim3(24, 24), blk>>>(wk, wqkvT + 768 * 768, 768, 768, 1.f);
        transpose_w<<<dim3(24, 24), blk>>>(wv, wqkvT + 1536 * 768, 768, 768, 1.f);
        transpose_w<<<dim3(24, 24), blk>>>(wo, woT, 768, 768, 1.f);
        transpose_w<<<dim3(96, 24), blk>>>(w1, w1T, 768, 3072, 1.f);
        transpose_w<<<dim3(24, 96), blk>>>(w2, w2T, 3072, 768, 1.f);
    }

    // 1. LN1 -> fp16
    ln_kernel<<<M_ROWS, 256>>>(hs, g1, be1, ni);

    // 2. fused QKV projection with fused RoPE -> fp16 qkv
    gemm_f16<false, true, true><<<dim3(QKV_N / 128, M_ROWS / 128), 256, G128_SMEM_BYTES>>>(
        ni, wqkvT, bqkv, nullptr, qkv, trig, M_ROWS, QKV_N, D_MODEL);

    // 3. attention (register-P flash) -> fp16 attn
    {
        dim3 ga(T_TOK / 128, N_HEADS, BATCH);
        attn_f16<<<ga, 256, AT_SMEM_BYTES>>>(qkv, ab, attn);
    }

    // 4. out-proj + residual(hs fp32) -> fp32 res1
    gemm_f16_m64<false, false><<<dim3(D_MODEL / 128, M_ROWS / 64), 256, G64_SMEM_BYTES>>>(
        attn, woT, bo, hs, res1, M_ROWS, D_MODEL, D_MODEL);

    // 5. LN3 -> fp16 ffin
    ln_kernel<<<M_ROWS, 256>>>(res1, g3, be3, ffin);

    // 6. FFN1 + exact GELU -> fp16 hbuf
    gemm_f16<true, true, false><<<dim3(FFN_DIM / 128, M_ROWS / 128), 256, G128_SMEM_BYTES>>>(
        ffin, w1T, b1, nullptr, hbuf, nullptr, M_ROWS, FFN_DIM, D_MODEL);

    // 7. FFN2 + residual(res1) -> fp32 out
    gemm_f16_m64<false, false><<<dim3(D_MODEL / 128, M_ROWS / 64), 256, G64_SMEM_BYTES>>>(
        hbuf, w2T, b2, res1, out, M_ROWS, D_MODEL, FFN_DIM);
}

// round 13
// speedup vs baseline: 2.1420x; 1.0278x over previous
#include <cuda_runtime.h>
#include <cuda_fp16.h>
#include <math.h>
#include <stdint.h>

#define D_MODEL 768
#define N_HEADS 12
#define HEAD_DIM 64
#define FFN_DIM 3072
#define T_TOK 2048
#define BATCH 2
#define M_ROWS (BATCH * T_TOK)   // 4096
#define QKV_N 2304               // 3 * D_MODEL

// -------------------- scratch ---------------------------------------------
__device__ __half g_ni[M_ROWS * D_MODEL];
__device__ __half g_qkv[M_ROWS * QKV_N];
__device__ __half g_wqkvT[QKV_N * D_MODEL];
__device__ float  g_bqkv[QKV_N];
__device__ __half g_woT[D_MODEL * D_MODEL];
__device__ __half g_w1T[FFN_DIM * D_MODEL];
__device__ __half g_w2T[D_MODEL * FFN_DIM];
__device__ __half g_attn[M_ROWS * D_MODEL];
__device__ float  g_res1[M_ROWS * D_MODEL];
__device__ __half g_ffin[M_ROWS * D_MODEL];
__device__ __half g_h[M_ROWS * FFN_DIM];
__device__ float  g_trig[T_TOK * 16 * 2];

// -------------------- helpers ---------------------------------------------
__device__ __forceinline__ unsigned su32(const void* p) {
    return (unsigned)__cvta_generic_to_shared(p);
}
__device__ __forceinline__ void cp16(void* smem_dst, const void* gptr) {
    asm volatile("cp.async.cg.shared.global [%0], [%1], 16;" :: "r"(su32(smem_dst)), "l"(gptr));
}
__device__ __forceinline__ void cp_commit() { asm volatile("cp.async.commit_group;"); }
template <int NN>
__device__ __forceinline__ void cp_wait() { asm volatile("cp.async.wait_group %0;" :: "n"(NN)); }

__device__ __forceinline__ void mma_f16(float* c, const unsigned* a, unsigned b0, unsigned b1) {
    asm volatile(
        "mma.sync.aligned.m16n8k16.row.col.f32.f16.f16.f32 "
        "{%0,%1,%2,%3}, {%4,%5,%6,%7}, {%8,%9}, {%0,%1,%2,%3};"
        : "+f"(c[0]), "+f"(c[1]), "+f"(c[2]), "+f"(c[3])
        : "r"(a[0]), "r"(a[1]), "r"(a[2]), "r"(a[3]), "r"(b0), "r"(b1));
}
__device__ __forceinline__ void ldsm4(unsigned* r, unsigned addr) {
    asm volatile("ldmatrix.sync.aligned.m8n8.x4.shared.b16 {%0,%1,%2,%3}, [%4];"
                 : "=r"(r[0]), "=r"(r[1]), "=r"(r[2]), "=r"(r[3]) : "r"(addr));
}
__device__ __forceinline__ void ldsm4t(unsigned* r, unsigned addr) {
    asm volatile("ldmatrix.sync.aligned.m8n8.x4.trans.shared.b16 {%0,%1,%2,%3}, [%4];"
                 : "=r"(r[0]), "=r"(r[1]), "=r"(r[2]), "=r"(r[3]) : "r"(addr));
}
__device__ __forceinline__ unsigned pack2(float lo, float hi) {
    __half2 h = __floats2half2_rn(lo, hi);
    return *(unsigned*)&h;
}

// -------------------- warp-per-row LayerNorm (fp32 in, fp16 out) ----------
__global__ void ln_warp(const float* __restrict__ x, const float* __restrict__ g,
                        const float* __restrict__ bta, __half* __restrict__ y) {
    int w = (blockIdx.x * blockDim.x + threadIdx.x) >> 5;
    int lane = threadIdx.x & 31;
    if (w >= M_ROWS) return;
    const float* xr = x + (size_t)w * D_MODEL;
    float4 v[6];
    float sum = 0.f;
#pragma unroll
    for (int i = 0; i < 6; i++) {
        v[i] = *(const float4*)(xr + i * 128 + lane * 4);
        sum += v[i].x + v[i].y + v[i].z + v[i].w;
    }
#pragma unroll
    for (int o = 16; o; o >>= 1) sum += __shfl_xor_sync(0xffffffffu, sum, o);
    float mu = sum * (1.f / 768.f);
    float var = 0.f;
#pragma unroll
    for (int i = 0; i < 6; i++) {
        v[i].x -= mu; v[i].y -= mu; v[i].z -= mu; v[i].w -= mu;
        var += v[i].x * v[i].x + v[i].y * v[i].y + v[i].z * v[i].z + v[i].w * v[i].w;
    }
#pragma unroll
    for (int o = 16; o; o >>= 1) var += __shfl_xor_sync(0xffffffffu, var, o);
    float rs = rsqrtf(var * (1.f / 768.f) + 1e-5f);
    __half* yr = y + (size_t)w * D_MODEL;
#pragma unroll
    for (int i = 0; i < 6; i++) {
        int col = i * 128 + lane * 4;
        float4 gv = *(const float4*)(g + col);
        float4 bv = *(const float4*)(bta + col);
        __half2 h0 = __floats2half2_rn(v[i].x * rs * gv.x + bv.x, v[i].y * rs * gv.y + bv.y);
        __half2 h1 = __floats2half2_rn(v[i].z * rs * gv.z + bv.z, v[i].w * rs * gv.w + bv.w);
        *(__half2*)(yr + col) = h0;
        *(__half2*)(yr + col + 2) = h1;
    }
}

// -------------------- merged weight transposes (one launch) ----------------
// segments: [0,576) wq | [576,1152) wk | [1152,1728) wv | [1728,2304) wo
//           [2304,4608) w1 (96x24) | [4608,6912) w2 (24x96)
__global__ void transpose_all(const float* __restrict__ wq, const float* __restrict__ wk,
                              const float* __restrict__ wv, const float* __restrict__ wo,
                              const float* __restrict__ w1, const float* __restrict__ w2,
                              __half* __restrict__ wqkvT, __half* __restrict__ woT,
                              __half* __restrict__ w1T, __half* __restrict__ w2T) {
    __shared__ float t[32][33];
    int bid = blockIdx.x;
    const float* src;
    __half* dst;
    int R, C, bx, by;
    float scale = 1.f;
    if (bid < 2304) {
        int seg = bid / 576, r = bid % 576;
        bx = r % 24; by = r / 24; R = 768; C = 768;
        if (seg == 0)      { src = wq; dst = wqkvT; scale = 0.125f; }
        else if (seg == 1) { src = wk; dst = wqkvT + 768 * 768; }
        else if (seg == 2) { src = wv; dst = wqkvT + 1536 * 768; }
        else               { src = wo; dst = woT; }
    } else if (bid < 4608) {
        int r = bid - 2304;
        bx = r % 96; by = r / 96; R = 768; C = 3072;
        src = w1; dst = w1T;
    } else {
        int r = bid - 4608;
        bx = r % 24; by = r / 24; R = 3072; C = 768;
        src = w2; dst = w2T;
    }
    int X = bx * 32, Y = by * 32;
    int x = threadIdx.x, y = threadIdx.y;
#pragma unroll
    for (int i = 0; i < 32; i += 8)
        t[y + i][x] = src[(size_t)(Y + y + i) * C + X + x] * scale;
    __syncthreads();
#pragma unroll
    for (int i = 0; i < 32; i += 8)
        dst[(size_t)(X + y + i) * R + Y + x] = __float2half(t[x][y + i]);
}

// -------------------- bias concat -----------------------------------------
__global__ void concat_bias(const float* __restrict__ bq, const float* __restrict__ bk,
                            const float* __restrict__ bv, float* __restrict__ Bo) {
    int j = blockIdx.x * 256 + threadIdx.x;
    if (j < 768) Bo[j] = bq[j] * 0.125f;
    else if (j < 1536) Bo[j] = bk[j - 768];
    else if (j < 2304) Bo[j] = bv[j - 1536];
}

// -------------------- trig table ------------------------------------------
__global__ void trig_kernel(float* __restrict__ trig) {
    int idx = blockIdx.x * 256 + threadIdx.x;
    if (idx >= T_TOK * 16) return;
    int t = idx >> 4, i = idx & 15;
    double ts = pow(10000.0, (double)i / 32.0);
    double ang = (double)t / ts;
    double sd, cd;
    sincos(ang, &sd, &cd);
    trig[idx * 2]     = (float)cd;
    trig[idx * 2 + 1] = (float)sd;
}

// ==================== fp16 GEMM 128x128, BK=32, 3-stage ====================
#define HST 40
#define AH_SZ (128 * HST)
#define BH_SZ (128 * HST)
#define G128_SMEM_BYTES (3 * (AH_SZ + BH_SZ) * 2)
#define AH64_SZ (64 * HST)
#define G64_SMEM_BYTES (3 * (AH64_SZ + BH_SZ) * 2)

template <bool GELU, bool OUTH, bool ROPE>
__global__ __launch_bounds__(256, 2)
void gemm_f16(const __half* __restrict__ A, const __half* __restrict__ BmT,
              const float* __restrict__ bias, const float* __restrict__ res,
              void* __restrict__ Cv, const float* __restrict__ trig,
              int M, int N, int K) {
    extern __shared__ __half hsm[];
    __half* AsB = hsm;
    __half* BsB = hsm + 3 * AH_SZ;
    int tid = threadIdx.x;
    int wid = tid >> 5, lane = tid & 31;
    int g = lane >> 2, tig = lane & 3;
    int wm = wid & 3, wn = wid >> 2;
    int brow = blockIdx.y * 128, bcol = blockIdx.x * 128;

    const __half* apre[2];
    const __half* bpre[2];
    int aso[2];
#pragma unroll
    for (int i = 0; i < 2; i++) {
        int idx = tid + i * 256;
        int row = idx >> 2, ch = (idx & 3) * 8;
        aso[i] = row * HST + ch;
        apre[i] = A + (size_t)(brow + row) * K + ch;
        bpre[i] = BmT + (size_t)(bcol + row) * K + ch;
    }

    int nIter = K >> 5;

#define GF_ISSUE(KT, STG) do {                                                \
        __half* asd_ = AsB + (STG) * AH_SZ;                                   \
        __half* bsd_ = BsB + (STG) * BH_SZ;                                   \
        _Pragma("unroll")                                                     \
        for (int i = 0; i < 2; i++) {                                         \
            cp16(&asd_[aso[i]], apre[i] + (KT) * 32);                         \
            cp16(&bsd_[aso[i]], bpre[i] + (KT) * 32);                         \
        }                                                                     \
        cp_commit();                                                           \
    } while (0)

    GF_ISSUE(0, 0);
    GF_ISSUE(1, 1);

    float acc[2][8][4];
#pragma unroll
    for (int i = 0; i < 2; i++)
#pragma unroll
        for (int j = 0; j < 8; j++)
#pragma unroll
            for (int r = 0; r < 4; r++) acc[i][j][r] = 0.f;

    int l15 = lane & 15, lkh8 = (lane >> 4) << 3;

    int cur = 0, nxt = 2;
    for (int kt = 0; kt < nIter; ++kt) {
        if (kt + 1 < nIter) cp_wait<1>(); else cp_wait<0>();
        __syncthreads();
        if (kt + 2 < nIter) GF_ISSUE(kt + 2, nxt);
        const __half* As = AsB + cur * AH_SZ;
        const __half* Bs = BsB + cur * BH_SZ;
#pragma unroll
        for (int ks = 0; ks < 32; ks += 16) {
            unsigned af[2][4];
#pragma unroll
            for (int mt = 0; mt < 2; mt++) {
                int R = wm * 32 + mt * 16;
                ldsm4(af[mt], su32(&As[(R + l15) * HST + ks + lkh8]));
            }
#pragma unroll
            for (int p = 0; p < 4; p++) {
                unsigned bf[4];
                int nr = wn * 64 + p * 16;
                ldsm4(bf, su32(&Bs[(nr + l15) * HST + ks + lkh8]));
                mma_f16(acc[0][2 * p],     af[0], bf[0], bf[2]);
                mma_f16(acc[1][2 * p],     af[1], bf[0], bf[2]);
                mma_f16(acc[0][2 * p + 1], af[0], bf[1], bf[3]);
                mma_f16(acc[1][2 * p + 1], af[1], bf[1], bf[3]);
            }
        }
        cur = cur + 1; if (cur == 3) cur = 0;
        nxt = nxt + 1; if (nxt == 3) nxt = 0;
    }
#undef GF_ISSUE

#pragma unroll
    for (int mt = 0; mt < 2; mt++) {
        int row0 = brow + wm * 32 + mt * 16 + g;
        int t0 = row0 & (T_TOK - 1);
        int t1 = (row0 + 8) & (T_TOK - 1);
        bool doRope = ROPE && (bcol + wn * 64) < 1536;
#pragma unroll
        for (int nt2 = 0; nt2 < 4; nt2++) {
            int ntA = nt2, ntB = nt2 + 4;
            int colA = bcol + wn * 64 + ntA * 8 + tig * 2;
            int colB = colA + 32;
            float bA0 = bias[colA], bA1 = bias[colA + 1];
            float bB0 = bias[colB], bB1 = bias[colB + 1];
            float vA00 = acc[mt][ntA][0] + bA0, vA01 = acc[mt][ntA][1] + bA1;
            float vA10 = acc[mt][ntA][2] + bA0, vA11 = acc[mt][ntA][3] + bA1;
            float vB00 = acc[mt][ntB][0] + bB0, vB01 = acc[mt][ntB][1] + bB1;
            float vB10 = acc[mt][ntB][2] + bB0, vB11 = acc[mt][ntB][3] + bB1;
            if (doRope && nt2 < 2) {
                int i0 = ntA * 8 + tig * 2;
                float c00 = trig[(t0 * 16 + i0) * 2],     s00 = trig[(t0 * 16 + i0) * 2 + 1];
                float c01 = trig[(t0 * 16 + i0 + 1) * 2], s01 = trig[(t0 * 16 + i0 + 1) * 2 + 1];
                float c10 = trig[(t1 * 16 + i0) * 2],     s10 = trig[(t1 * 16 + i0) * 2 + 1];
                float c11 = trig[(t1 * 16 + i0 + 1) * 2], s11 = trig[(t1 * 16 + i0 + 1) * 2 + 1];
                float x1, x2;
                x1 = vA00; x2 = vB00; vA00 = x1 * c00 - x2 * s00; vB00 = x2 * c00 + x1 * s00;
                x1 = vA01; x2 = vB01; vA01 = x1 * c01 - x2 * s01; vB01 = x2 * c01 + x1 * s01;
                x1 = vA10; x2 = vB10; vA10 = x1 * c10 - x2 * s10; vB10 = x2 * c10 + x1 * s10;
                x1 = vA11; x2 = vB11; vA11 = x1 * c11 - x2 * s11; vB11 = x2 * c11 + x1 * s11;
            }
            if (GELU) {
                vA00 *= normcdff(vA00); vA01 *= normcdff(vA01);
                vA10 *= normcdff(vA10); vA11 *= normcdff(vA11);
                vB00 *= normcdff(vB00); vB01 *= normcdff(vB01);
                vB10 *= normcdff(vB10); vB11 *= normcdff(vB11);
            }
            if (res) {
                const float* r0A = res + (size_t)row0 * N + colA;
                const float* r1A = res + (size_t)(row0 + 8) * N + colA;
                vA00 += r0A[0]; vA01 += r0A[1]; vA10 += r1A[0]; vA11 += r1A[1];
                const float* r0B = res + (size_t)row0 * N + colB;
                const float* r1B = res + (size_t)(row0 + 8) * N + colB;
                vB00 += r0B[0]; vB01 += r0B[1]; vB10 += r1B[0]; vB11 += r1B[1];
            }
            if (OUTH) {
                __half* Ch = (__half*)Cv;
                *(__half2*)(Ch + (size_t)row0 * N + colA) = __floats2half2_rn(vA00, vA01);
                *(__half2*)(Ch + (size_t)(row0 + 8) * N + colA) = __floats2half2_rn(vA10, vA11);
                *(__half2*)(Ch + (size_t)row0 * N + colB) = __floats2half2_rn(vB00, vB01);
                *(__half2*)(Ch + (size_t)(row0 + 8) * N + colB) = __floats2half2_rn(vB10, vB11);
            } else {
                float* Cf = (float*)Cv;
                *(float2*)(Cf + (size_t)row0 * N + colA) = make_float2(vA00, vA01);
                *(float2*)(Cf + (size_t)(row0 + 8) * N + colA) = make_float2(vA10, vA11);
                *(float2*)(Cf + (size_t)row0 * N + colB) = make_float2(vB00, vB01);
                *(float2*)(Cf + (size_t)(row0 + 8) * N + colB) = make_float2(vB10, vB11);
            }
        }
    }
}

// ==================== fp16 GEMM 64x128 (N=768 GEMMs) =======================
template <bool GELU, bool OUTH>
__global__ __launch_bounds__(256, 3)
void gemm_f16_m64(const __half* __restrict__ A, const __half* __restrict__ BmT,
                  const float* __restrict__ bias, const float* __restrict__ res,
                  void* __restrict__ Cv, int M, int N, int K) {
    extern __shared__ __half hsm[];
    __half* AsB = hsm;
    __half* BsB = hsm + 3 * AH64_SZ;
    int tid = threadIdx.x;
    int wid = tid >> 5, lane = tid & 31;
    int g = lane >> 2, tig = lane & 3;
    int wm = wid & 1, wn = wid >> 1;
    int brow = blockIdx.y * 64, bcol = blockIdx.x * 128;

    int arow = tid >> 2, ach = (tid & 3) * 8;
    const __half* apre = A + (size_t)(brow + arow) * K + ach;
    int asoA = arow * HST + ach;
    const __half* bpre[2];
    int bso[2];
#pragma unroll
    for (int i = 0; i < 2; i++) {
        int idx = tid + i * 256;
        int row = idx >> 2, ch = (idx & 3) * 8;
        bso[i] = row * HST + ch;
        bpre[i] = BmT + (size_t)(bcol + row) * K + ch;
    }

    int nIter = K >> 5;

#define GF_ISSUE64(KT, STG) do {                                              \
        cp16(&AsB[(STG) * AH64_SZ + asoA], apre + (KT) * 32);                 \
        __half* bsd_ = BsB + (STG) * BH_SZ;                                   \
        _Pragma("unroll")                                                     \
        for (int i = 0; i < 2; i++)                                           \
            cp16(&bsd_[bso[i]], bpre[i] + (KT) * 32);                         \
        cp_commit();                                                           \
    } while (0)

    GF_ISSUE64(0, 0);
    GF_ISSUE64(1, 1);

    float acc[2][4][4];
#pragma unroll
    for (int i = 0; i < 2; i++)
#pragma unroll
        for (int j = 0; j < 4; j++)
#pragma unroll
            for (int r = 0; r < 4; r++) acc[i][j][r] = 0.f;

    int l15 = lane & 15, lkh8 = (lane >> 4) << 3;

    int cur = 0, nxt = 2;
    for (int kt = 0; kt < nIter; ++kt) {
        if (kt + 1 < nIter) cp_wait<1>(); else cp_wait<0>();
        __syncthreads();
        if (kt + 2 < nIter) GF_ISSUE64(kt + 2, nxt);
        const __half* As = AsB + cur * AH64_SZ;
        const __half* Bs = BsB + cur * BH_SZ;
#pragma unroll
        for (int ks = 0; ks < 32; ks += 16) {
            unsigned af[2][4];
#pragma unroll
            for (int mt = 0; mt < 2; mt++) {
                int R = wm * 32 + mt * 16;
                ldsm4(af[mt], su32(&As[(R + l15) * HST + ks + lkh8]));
            }
#pragma unroll
            for (int p = 0; p < 2; p++) {
                unsigned bf[4];
                int nr = wn * 32 + p * 16;
                ldsm4(bf, su32(&Bs[(nr + l15) * HST + ks + lkh8]));
                mma_f16(acc[0][2 * p],     af[0], bf[0], bf[2]);
                mma_f16(acc[1][2 * p],     af[1], bf[0], bf[2]);
                mma_f16(acc[0][2 * p + 1], af[0], bf[1], bf[3]);
                mma_f16(acc[1][2 * p + 1], af[1], bf[1], bf[3]);
            }
        }
        cur = cur + 1; if (cur == 3) cur = 0;
        nxt = nxt + 1; if (nxt == 3) nxt = 0;
    }
#undef GF_ISSUE64

#pragma unroll
    for (int mt = 0; mt < 2; mt++) {
        int row0 = brow + wm * 32 + mt * 16 + g;
#pragma unroll
        for (int nt = 0; nt < 4; nt++) {
            int col = bcol + wn * 32 + nt * 8 + tig * 2;
            float b0 = bias[col], b1 = bias[col + 1];
            float v00 = acc[mt][nt][0] + b0;
            float v01 = acc[mt][nt][1] + b1;
            float v10 = acc[mt][nt][2] + b0;
            float v11 = acc[mt][nt][3] + b1;
            if (GELU) {
                v00 *= normcdff(v00); v01 *= normcdff(v01);
                v10 *= normcdff(v10); v11 *= normcdff(v11);
            }
            if (res) {
                const float* r0p = res + (size_t)row0 * N + col;
                const float* r1p = res + (size_t)(row0 + 8) * N + col;
                v00 += r0p[0]; v01 += r0p[1];
                v10 += r1p[0]; v11 += r1p[1];
            }
            if (OUTH) {
                __half* Ch = (__half*)Cv;
                *(__half2*)(Ch + (size_t)row0 * N + col) = __floats2half2_rn(v00, v01);
                *(__half2*)(Ch + (size_t)(row0 + 8) * N + col) = __floats2half2_rn(v10, v11);
            } else {
                float* Cf = (float*)Cv;
                *(float2*)(Cf + (size_t)row0 * N + col) = make_float2(v00, v01);
                *(float2*)(Cf + (size_t)(row0 + 8) * N + col) = make_float2(v10, v11);
            }
        }
    }
}

// ==================== fp16 flash attention: register P, 1 sync/iter ========
#define QHS 72
#define KV_SZ (64 * QHS)
#define AT_SMEM_BYTES ((128 * QHS + 4 * KV_SZ) * 2)

__global__ __launch_bounds__(256, 2)
void attn_f16(const __half* __restrict__ QKV, const float* __restrict__ ab,
              __half* __restrict__ O) {
    extern __shared__ __half hsm[];
    __half* Qh = hsm;
    __half* KhB = Qh + 128 * QHS;
    __half* VhB = KhB + 2 * KV_SZ;

    int tid = threadIdx.x;
    int wid = tid >> 5, lane = tid & 31;
    int g = lane >> 2, tig = lane & 3;
    int m0 = wid * 16;
    int l15 = lane & 15, lkh8 = (lane >> 4) << 3;

    int qb = blockIdx.x * 128;
    int h = blockIdx.y, b = blockIdx.z;
    size_t bh = (size_t)b * T_TOK * QKV_N + h * HEAD_DIM;
    const __half* qp = QKV + bh;
    const __half* kp = QKV + bh + 768;
    const __half* vp = QKV + bh + 1536;

#define G_ISSUE(KT, BUF) do {                                                 \
        int kb_ = (KT) * 64;                                                  \
        __half* kd_ = KhB + (BUF) * KV_SZ;                                    \
        __half* vd_ = VhB + (BUF) * KV_SZ;                                    \
        _Pragma("unroll")                                                     \
        for (int it = 0; it < 2; it++) {                                      \
            int idx_ = tid + it * 256;                                        \
            int r_ = idx_ >> 3, c_ = (idx_ & 7) * 8;                          \
            cp16(&kd_[r_ * QHS + c_], kp + (size_t)(kb_ + r_) * QKV_N + c_);  \
            cp16(&vd_[r_ * QHS + c_], vp + (size_t)(kb_ + r_) * QKV_N + c_);  \
        }                                                                     \
        cp_commit();                                                          \
    } while (0)

#pragma unroll
    for (int it = 0; it < 4; it++) {
        int idx = tid + it * 256;
        int r = idx >> 3, c = (idx & 7) * 8;
        cp16(&Qh[r * QHS + c], qp + (size_t)(qb + r) * QKV_N + c);
    }
    cp_commit();
    G_ISSUE(0, 0);

    float mo0 = -1e30f, mo1 = -1e30f, l0 = 0.f, l1 = 0.f;
    float o[8][4];
#pragma unroll
    for (int nt = 0; nt < 8; nt++)
#pragma unroll
        for (int r = 0; r < 4; r++) o[nt][r] = 0.f;

    float bias0 = ab[h * 2 + 0], bias1 = ab[h * 2 + 1];
    int qvar = qb >> 7;

    for (int kt = 0; kt < 32; kt++) {
        cp_wait<0>();
        __syncthreads();
        int cur = kt & 1;
        if (kt + 1 < 32) G_ISSUE(kt + 1, cur ^ 1);
        const __half* Kh = KhB + cur * KV_SZ;
        const __half* Vh = VhB + cur * KV_SZ;

        float s[8][4];
#pragma unroll
        for (int nt = 0; nt < 8; nt++)
#pragma unroll
            for (int r = 0; r < 4; r++) s[nt][r] = 0.f;
#pragma unroll
        for (int ks = 0; ks < 64; ks += 16) {
            unsigned af[4];
            ldsm4(af, su32(&Qh[(m0 + l15) * QHS + ks + lkh8]));
#pragma unroll
            for (int p = 0; p < 4; p++) {
                unsigned bf[4];
                ldsm4(bf, su32(&Kh[(p * 16 + l15) * QHS + ks + lkh8]));
                mma_f16(s[2 * p],     af, bf[0], bf[2]);
                mma_f16(s[2 * p + 1], af, bf[1], bf[3]);
            }
        }

        float bias = (((kt * 64) >> 7) == qvar) ? bias0 : bias1;
        float mx0 = mo0, mx1 = mo1;
#pragma unroll
        for (int nt = 0; nt < 8; nt++) {
            s[nt][0] += bias; s[nt][1] += bias; s[nt][2] += bias; s[nt][3] += bias;
            mx0 = fmaxf(mx0, fmaxf(s[nt][0], s[nt][1]));
            mx1 = fmaxf(mx1, fmaxf(s[nt][2], s[nt][3]));
        }
        mx0 = fmaxf(mx0, __shfl_xor_sync(0xffffffffu, mx0, 1));
        mx0 = fmaxf(mx0, __shfl_xor_sync(0xffffffffu, mx0, 2));
        mx1 = fmaxf(mx1, __shfl_xor_sync(0xffffffffu, mx1, 1));
        mx1 = fmaxf(mx1, __shfl_xor_sync(0xffffffffu, mx1, 2));
        float scl0 = __expf(mo0 - mx0), scl1 = __expf(mo1 - mx1);
        float sum0 = 0.f, sum1 = 0.f;
#pragma unroll
        for (int nt = 0; nt < 8; nt++) {
            s[nt][0] = __expf(s[nt][0] - mx0); sum0 += s[nt][0];
            s[nt][1] = __expf(s[nt][1] - mx0); sum0 += s[nt][1];
            s[nt][2] = __expf(s[nt][2] - mx1); sum1 += s[nt][2];
            s[nt][3] = __expf(s[nt][3] - mx1); sum1 += s[nt][3];
        }
        sum0 += __shfl_xor_sync(0xffffffffu, sum0, 1);
        sum0 += __shfl_xor_sync(0xffffffffu, sum0, 2);
        sum1 += __shfl_xor_sync(0xffffffffu, sum1, 1);
        sum1 += __shfl_xor_sync(0xffffffffu, sum1, 2);
        l0 = l0 * scl0 + sum0; mo0 = mx0;
        l1 = l1 * scl1 + sum1; mo1 = mx1;
#pragma unroll
        for (int nt = 0; nt < 8; nt++) {
            o[nt][0] *= scl0; o[nt][1] *= scl0;
            o[nt][2] *= scl1; o[nt][3] *= scl1;
        }

#pragma unroll
        for (int p = 0; p < 4; p++) {
            unsigned af2[4];
            af2[0] = pack2(s[2 * p][0],     s[2 * p][1]);
            af2[1] = pack2(s[2 * p][2],     s[2 * p][3]);
            af2[2] = pack2(s[2 * p + 1][0], s[2 * p + 1][1]);
            af2[3] = pack2(s[2 * p + 1][2], s[2 * p + 1][3]);
#pragma unroll
            for (int cbt = 0; cbt < 4; cbt++) {
                unsigned bf[4];
                ldsm4t(bf, su32(&Vh[(p * 16 + l15) * QHS + cbt * 16 + lkh8]));
                mma_f16(o[2 * cbt],     af2, bf[0], bf[1]);
                mma_f16(o[2 * cbt + 1], af2, bf[2], bf[3]);
            }
        }
    }
#undef G_ISSUE

    float inv0 = 1.f / l0, inv1 = 1.f / l1;
    int row0 = qb + m0 + g;
#pragma unroll
    for (int nt = 0; nt < 8; nt++) {
        int col = nt * 8 + tig * 2;
        __half* o0 = O + (size_t)(b * T_TOK + row0) * D_MODEL + h * HEAD_DIM + col;
        __half* o1 = O + (size_t)(b * T_TOK + row0 + 8) * D_MODEL + h * HEAD_DIM + col;
        *(__half2*)o0 = __floats2half2_rn(o[nt][0] * inv0, o[nt][1] * inv0);
        *(__half2*)o1 = __floats2half2_rn(o[nt][2] * inv1, o[nt][3] * inv1);
    }
}

// -------------------- launch ----------------------------------------------
extern "C" void kernel_launch(void* const* d_in, const int* in_sizes, int n_in,
                              void* d_out, int out_size) {
    const float* hs  = (const float*)d_in[0];
    const float* wq  = (const float*)d_in[1];
    const float* bq  = (const float*)d_in[2];
    const float* wk  = (const float*)d_in[3];
    const float* bk  = (const float*)d_in[4];
    const float* wv  = (const float*)d_in[5];
    const float* bv  = (const float*)d_in[6];
    const float* wo  = (const float*)d_in[7];
    const float* bo  = (const float*)d_in[8];
    const float* ab  = (const float*)d_in[9];
    const float* g1  = (const float*)d_in[10];
    const float* be1 = (const float*)d_in[11];
    const float* g3  = (const float*)d_in[12];
    const float* be3 = (const float*)d_in[13];
    const float* w1  = (const float*)d_in[14];
    const float* b1  = (const float*)d_in[15];
    const float* w2  = (const float*)d_in[16];
    const float* b2  = (const float*)d_in[17];
    float* out = (float*)d_out;

    __half *ni, *qkv, *wqkvT, *woT, *w1T, *w2T, *attn, *ffin, *hbuf;
    float *bqkv, *res1, *trig;
    cudaGetSymbolAddress((void**)&ni,    g_ni);
    cudaGetSymbolAddress((void**)&qkv,   g_qkv);
    cudaGetSymbolAddress((void**)&wqkvT, g_wqkvT);
    cudaGetSymbolAddress((void**)&bqkv,  g_bqkv);
    cudaGetSymbolAddress((void**)&woT,   g_woT);
    cudaGetSymbolAddress((void**)&w1T,   g_w1T);
    cudaGetSymbolAddress((void**)&w2T,   g_w2T);
    cudaGetSymbolAddress((void**)&attn,  g_attn);
    cudaGetSymbolAddress((void**)&res1,  g_res1);
    cudaGetSymbolAddress((void**)&ffin,  g_ffin);
    cudaGetSymbolAddress((void**)&hbuf,  g_h);
    cudaGetSymbolAddress((void**)&trig,  g_trig);

    static bool attr_set = false;
    if (!attr_set) {
        cudaFuncSetAttribute(attn_f16, cudaFuncAttributeMaxDynamicSharedMemorySize,
                             AT_SMEM_BYTES);
        cudaFuncSetAttribute((gemm_f16<false, true, true>), cudaFuncAttributeMaxDynamicSharedMemorySize,
                             G128_SMEM_BYTES);
        cudaFuncSetAttribute((gemm_f16<true, true, false>), cudaFuncAttributeMaxDynamicSharedMemorySize,
                             G128_SMEM_BYTES);
        cudaFuncSetAttribute((gemm_f16_m64<false, false>), cudaFuncAttributeMaxDynamicSharedMemorySize,
                             G64_SMEM_BYTES);
        attr_set = true;
    }

    // 0. prep: trig + bias + ALL weight transposes in one launch
    trig_kernel<<<(T_TOK * 16 + 255) / 256, 256>>>(trig);
    concat_bias<<<(QKV_N + 255) / 256, 256>>>(bq, bk, bv, bqkv);
    transpose_all<<<6912, dim3(32, 8)>>>(wq, wk, wv, wo, w1, w2, wqkvT, woT, w1T, w2T);

    // 1. LN1 -> fp16 (warp per row)
    ln_warp<<<M_ROWS / 8, 256>>>(hs, g1, be1, ni);

    // 2. fused QKV projection with fused RoPE -> fp16 qkv
    gemm_f16<false, true, true><<<dim3(QKV_N / 128, M_ROWS / 128), 256, G128_SMEM_BYTES>>>(
        ni, wqkvT, bqkv, nullptr, qkv, trig, M_ROWS, QKV_N, D_MODEL);

    // 3. attention (register-P flash) -> fp16 attn
    {
        dim3 ga(T_TOK / 128, N_HEADS, BATCH);
        attn_f16<<<ga, 256, AT_SMEM_BYTES>>>(qkv, ab, attn);
    }

    // 4. out-proj + residual(hs fp32) -> fp32 res1
    gemm_f16_m64<false, false><<<dim3(D_MODEL / 128, M_ROWS / 64), 256, G64_SMEM_BYTES>>>(
        attn, woT, bo, hs, res1, M_ROWS, D_MODEL, D_MODEL);

    // 5. LN3 -> fp16 ffin (warp per row)
    ln_warp<<<M_ROWS / 8, 256>>>(res1, g3, be3, ffin);

    // 6. FFN1 + exact GELU -> fp16 hbuf
    gemm_f16<true, true, false><<<dim3(FFN_DIM / 128, M_ROWS / 128), 256, G128_SMEM_BYTES>>>(
        ffin, w1T, b1, nullptr, hbuf, nullptr, M_ROWS, FFN_DIM, D_MODEL);

    // 7. FFN2 + residual(res1) -> fp32 out
    gemm_f16_m64<false, false><<<dim3(D_MODEL / 128, M_ROWS / 64), 256, G64_SMEM_BYTES>>>(
        hbuf, w2T, b2, res1, out, M_ROWS, D_MODEL, FFN_DIM);
}

// round 14
// speedup vs baseline: 2.2579x; 1.0541x over previous
#include <cuda_runtime.h>
#include <cuda_fp16.h>
#include <math.h>
#include <stdint.h>

#define D_MODEL 768
#define N_HEADS 12
#define HEAD_DIM 64
#define FFN_DIM 3072
#define T_TOK 2048
#define BATCH 2
#define M_ROWS (BATCH * T_TOK)   // 4096
#define QKV_N 2304               // 3 * D_MODEL

// -------------------- scratch ---------------------------------------------
__device__ __half g_ni[M_ROWS * D_MODEL];
__device__ __half g_qkv[M_ROWS * QKV_N];
__device__ __half g_wqkvT[QKV_N * D_MODEL];
__device__ float  g_bqkv[QKV_N];
__device__ __half g_woT[D_MODEL * D_MODEL];
__device__ __half g_w1T[FFN_DIM * D_MODEL];
__device__ __half g_w2T[D_MODEL * FFN_DIM];
__device__ __half g_attn[M_ROWS * D_MODEL];
__device__ float  g_res1[M_ROWS * D_MODEL];
__device__ __half g_ffin[M_ROWS * D_MODEL];
__device__ __half g_h[M_ROWS * FFN_DIM];
__device__ float  g_trig[T_TOK * 16 * 2];

// -------------------- helpers ---------------------------------------------
__device__ __forceinline__ unsigned su32(const void* p) {
    return (unsigned)__cvta_generic_to_shared(p);
}
__device__ __forceinline__ void cp16(void* smem_dst, const void* gptr) {
    asm volatile("cp.async.cg.shared.global [%0], [%1], 16;" :: "r"(su32(smem_dst)), "l"(gptr));
}
__device__ __forceinline__ void cp_commit() { asm volatile("cp.async.commit_group;"); }
template <int NN>
__device__ __forceinline__ void cp_wait() { asm volatile("cp.async.wait_group %0;" :: "n"(NN)); }

__device__ __forceinline__ void mma_f16(float* c, const unsigned* a, unsigned b0, unsigned b1) {
    asm volatile(
        "mma.sync.aligned.m16n8k16.row.col.f32.f16.f16.f32 "
        "{%0,%1,%2,%3}, {%4,%5,%6,%7}, {%8,%9}, {%0,%1,%2,%3};"
        : "+f"(c[0]), "+f"(c[1]), "+f"(c[2]), "+f"(c[3])
        : "r"(a[0]), "r"(a[1]), "r"(a[2]), "r"(a[3]), "r"(b0), "r"(b1));
}
__device__ __forceinline__ void ldsm4(unsigned* r, unsigned addr) {
    asm volatile("ldmatrix.sync.aligned.m8n8.x4.shared.b16 {%0,%1,%2,%3}, [%4];"
                 : "=r"(r[0]), "=r"(r[1]), "=r"(r[2]), "=r"(r[3]) : "r"(addr));
}
__device__ __forceinline__ void ldsm4t(unsigned* r, unsigned addr) {
    asm volatile("ldmatrix.sync.aligned.m8n8.x4.trans.shared.b16 {%0,%1,%2,%3}, [%4];"
                 : "=r"(r[0]), "=r"(r[1]), "=r"(r[2]), "=r"(r[3]) : "r"(addr));
}
__device__ __forceinline__ unsigned pack2(float lo, float hi) {
    __half2 h = __floats2half2_rn(lo, hi);
    return *(unsigned*)&h;
}

// -------------------- warp-per-row LayerNorm ------------------------------
__global__ void ln_warp(const float* __restrict__ x, const float* __restrict__ g,
                        const float* __restrict__ bta, __half* __restrict__ y) {
    int w = (blockIdx.x * blockDim.x + threadIdx.x) >> 5;
    int lane = threadIdx.x & 31;
    if (w >= M_ROWS) return;
    const float* xr = x + (size_t)w * D_MODEL;
    float4 v[6];
    float sum = 0.f;
#pragma unroll
    for (int i = 0; i < 6; i++) {
        v[i] = *(const float4*)(xr + i * 128 + lane * 4);
        sum += v[i].x + v[i].y + v[i].z + v[i].w;
    }
#pragma unroll
    for (int o = 16; o; o >>= 1) sum += __shfl_xor_sync(0xffffffffu, sum, o);
    float mu = sum * (1.f / 768.f);
    float var = 0.f;
#pragma unroll
    for (int i = 0; i < 6; i++) {
        v[i].x -= mu; v[i].y -= mu; v[i].z -= mu; v[i].w -= mu;
        var += v[i].x * v[i].x + v[i].y * v[i].y + v[i].z * v[i].z + v[i].w * v[i].w;
    }
#pragma unroll
    for (int o = 16; o; o >>= 1) var += __shfl_xor_sync(0xffffffffu, var, o);
    float rs = rsqrtf(var * (1.f / 768.f) + 1e-5f);
    __half* yr = y + (size_t)w * D_MODEL;
#pragma unroll
    for (int i = 0; i < 6; i++) {
        int col = i * 128 + lane * 4;
        float4 gv = *(const float4*)(g + col);
        float4 bv = *(const float4*)(bta + col);
        __half2 h0 = __floats2half2_rn(v[i].x * rs * gv.x + bv.x, v[i].y * rs * gv.y + bv.y);
        __half2 h1 = __floats2half2_rn(v[i].z * rs * gv.z + bv.z, v[i].w * rs * gv.w + bv.w);
        *(__half2*)(yr + col) = h0;
        *(__half2*)(yr + col + 2) = h1;
    }
}

// -------------------- merged weight transposes ----------------------------
__global__ void transpose_all(const float* __restrict__ wq, const float* __restrict__ wk,
                              const float* __restrict__ wv, const float* __restrict__ wo,
                              const float* __restrict__ w1, const float* __restrict__ w2,
                              __half* __restrict__ wqkvT, __half* __restrict__ woT,
                              __half* __restrict__ w1T, __half* __restrict__ w2T) {
    __shared__ float t[32][33];
    int bid = blockIdx.x;
    const float* src;
    __half* dst;
    int R, C, bx, by;
    float scale = 1.f;
    if (bid < 2304) {
        int seg = bid / 576, r = bid % 576;
        bx = r % 24; by = r / 24; R = 768; C = 768;
        if (seg == 0)      { src = wq; dst = wqkvT; scale = 0.125f; }
        else if (seg == 1) { src = wk; dst = wqkvT + 768 * 768; }
        else if (seg == 2) { src = wv; dst = wqkvT + 1536 * 768; }
        else               { src = wo; dst = woT; }
    } else if (bid < 4608) {
        int r = bid - 2304;
        bx = r % 96; by = r / 96; R = 768; C = 3072;
        src = w1; dst = w1T;
    } else {
        int r = bid - 4608;
        bx = r % 24; by = r / 24; R = 3072; C = 768;
        src = w2; dst = w2T;
    }
    int X = bx * 32, Y = by * 32;
    int x = threadIdx.x, y = threadIdx.y;
#pragma unroll
    for (int i = 0; i < 32; i += 8)
        t[y + i][x] = src[(size_t)(Y + y + i) * C + X + x] * scale;
    __syncthreads();
#pragma unroll
    for (int i = 0; i < 32; i += 8)
        dst[(size_t)(X + y + i) * R + Y + x] = __float2half(t[x][y + i]);
}

// -------------------- bias concat -----------------------------------------
__global__ void concat_bias(const float* __restrict__ bq, const float* __restrict__ bk,
                            const float* __restrict__ bv, float* __restrict__ Bo) {
    int j = blockIdx.x * 256 + threadIdx.x;
    if (j < 768) Bo[j] = bq[j] * 0.125f;
    else if (j < 1536) Bo[j] = bk[j - 768];
    else if (j < 2304) Bo[j] = bv[j - 1536];
}

// -------------------- trig table ------------------------------------------
__global__ void trig_kernel(float* __restrict__ trig) {
    int idx = blockIdx.x * 256 + threadIdx.x;
    if (idx >= T_TOK * 16) return;
    int t = idx >> 4, i = idx & 15;
    double ts = pow(10000.0, (double)i / 32.0);
    double ang = (double)t / ts;
    double sd, cd;
    sincos(ang, &sd, &cd);
    trig[idx * 2]     = (float)cd;
    trig[idx * 2 + 1] = (float)sd;
}

// ==================== fp16 GEMM 128x128, BK=64, 3-stage ====================
#define HSTB 72                                // 64 + 8 pad; 36-word stride, conflict-free
#define AHB_SZ (128 * HSTB)
#define G128_SMEM_BYTES (3 * 2 * AHB_SZ * 2)   // 110592
// m64 variant keeps BK=32
#define HSTS 40
#define AH64_SZ (64 * HSTS)
#define BH64_SZ (128 * HSTS)
#define G64_SMEM_BYTES (3 * (AH64_SZ + BH64_SZ) * 2)

template <bool GELU, bool OUTH, bool ROPE>
__global__ __launch_bounds__(256, 2)
void gemm_f16(const __half* __restrict__ A, const __half* __restrict__ BmT,
              const float* __restrict__ bias, const float* __restrict__ res,
              void* __restrict__ Cv, const float* __restrict__ trig,
              int M, int N, int K) {
    extern __shared__ __half hsm[];
    __half* AsB = hsm;
    __half* BsB = hsm + 3 * AHB_SZ;
    int tid = threadIdx.x;
    int wid = tid >> 5, lane = tid & 31;
    int g = lane >> 2, tig = lane & 3;
    int wm = wid & 3, wn = wid >> 2;
    int brow = blockIdx.y * 128, bcol = blockIdx.x * 128;

    // staging: 128 rows x 64 halves, 8 chunks/row -> 4 chunks/thread each A,B
    const __half* apre[4];
    const __half* bpre[4];
    int aso[4];
#pragma unroll
    for (int i = 0; i < 4; i++) {
        int idx = tid + i * 256;
        int row = idx >> 3, ch = (idx & 7) * 8;
        aso[i] = row * HSTB + ch;
        apre[i] = A + (size_t)(brow + row) * K + ch;
        bpre[i] = BmT + (size_t)(bcol + row) * K + ch;
    }

    int nIter = K >> 6;

#define GF_ISSUE(KT, STG) do {                                                \
        __half* asd_ = AsB + (STG) * AHB_SZ;                                  \
        __half* bsd_ = BsB + (STG) * AHB_SZ;                                  \
        _Pragma("unroll")                                                     \
        for (int i = 0; i < 4; i++) {                                         \
            cp16(&asd_[aso[i]], apre[i] + (KT) * 64);                         \
            cp16(&bsd_[aso[i]], bpre[i] + (KT) * 64);                         \
        }                                                                     \
        cp_commit();                                                           \
    } while (0)

    GF_ISSUE(0, 0);
    GF_ISSUE(1, 1);

    float acc[2][8][4];
#pragma unroll
    for (int i = 0; i < 2; i++)
#pragma unroll
        for (int j = 0; j < 8; j++)
#pragma unroll
            for (int r = 0; r < 4; r++) acc[i][j][r] = 0.f;

    int l15 = lane & 15, lkh8 = (lane >> 4) << 3;

    int cur = 0, nxt = 2;
    for (int kt = 0; kt < nIter; ++kt) {
        if (kt + 1 < nIter) cp_wait<1>(); else cp_wait<0>();
        __syncthreads();
        if (kt + 2 < nIter) GF_ISSUE(kt + 2, nxt);
        const __half* As = AsB + cur * AHB_SZ;
        const __half* Bs = BsB + cur * AHB_SZ;
#pragma unroll
        for (int ks = 0; ks < 64; ks += 16) {
            unsigned af[2][4];
#pragma unroll
            for (int mt = 0; mt < 2; mt++) {
                int R = wm * 32 + mt * 16;
                ldsm4(af[mt], su32(&As[(R + l15) * HSTB + ks + lkh8]));
            }
#pragma unroll
            for (int p = 0; p < 4; p++) {
                unsigned bf[4];
                int nr = wn * 64 + p * 16;
                ldsm4(bf, su32(&Bs[(nr + l15) * HSTB + ks + lkh8]));
                mma_f16(acc[0][2 * p],     af[0], bf[0], bf[2]);
                mma_f16(acc[1][2 * p],     af[1], bf[0], bf[2]);
                mma_f16(acc[0][2 * p + 1], af[0], bf[1], bf[3]);
                mma_f16(acc[1][2 * p + 1], af[1], bf[1], bf[3]);
            }
        }
        cur = cur + 1; if (cur == 3) cur = 0;
        nxt = nxt + 1; if (nxt == 3) nxt = 0;
    }
#undef GF_ISSUE

#pragma unroll
    for (int mt = 0; mt < 2; mt++) {
        int row0 = brow + wm * 32 + mt * 16 + g;
        int t0 = row0 & (T_TOK - 1);
        int t1 = (row0 + 8) & (T_TOK - 1);
        bool doRope = ROPE && (bcol + wn * 64) < 1536;
#pragma unroll
        for (int nt2 = 0; nt2 < 4; nt2++) {
            int ntA = nt2, ntB = nt2 + 4;
            int colA = bcol + wn * 64 + ntA * 8 + tig * 2;
            int colB = colA + 32;
            float bA0 = bias[colA], bA1 = bias[colA + 1];
            float bB0 = bias[colB], bB1 = bias[colB + 1];
            float vA00 = acc[mt][ntA][0] + bA0, vA01 = acc[mt][ntA][1] + bA1;
            float vA10 = acc[mt][ntA][2] + bA0, vA11 = acc[mt][ntA][3] + bA1;
            float vB00 = acc[mt][ntB][0] + bB0, vB01 = acc[mt][ntB][1] + bB1;
            float vB10 = acc[mt][ntB][2] + bB0, vB11 = acc[mt][ntB][3] + bB1;
            if (doRope && nt2 < 2) {
                int i0 = ntA * 8 + tig * 2;
                float c00 = trig[(t0 * 16 + i0) * 2],     s00 = trig[(t0 * 16 + i0) * 2 + 1];
                float c01 = trig[(t0 * 16 + i0 + 1) * 2], s01 = trig[(t0 * 16 + i0 + 1) * 2 + 1];
                float c10 = trig[(t1 * 16 + i0) * 2],     s10 = trig[(t1 * 16 + i0) * 2 + 1];
                float c11 = trig[(t1 * 16 + i0 + 1) * 2], s11 = trig[(t1 * 16 + i0 + 1) * 2 + 1];
                float x1, x2;
                x1 = vA00; x2 = vB00; vA00 = x1 * c00 - x2 * s00; vB00 = x2 * c00 + x1 * s00;
                x1 = vA01; x2 = vB01; vA01 = x1 * c01 - x2 * s01; vB01 = x2 * c01 + x1 * s01;
                x1 = vA10; x2 = vB10; vA10 = x1 * c10 - x2 * s10; vB10 = x2 * c10 + x1 * s10;
                x1 = vA11; x2 = vB11; vA11 = x1 * c11 - x2 * s11; vB11 = x2 * c11 + x1 * s11;
            }
            if (GELU) {
                vA00 *= normcdff(vA00); vA01 *= normcdff(vA01);
                vA10 *= normcdff(vA10); vA11 *= normcdff(vA11);
                vB00 *= normcdff(vB00); vB01 *= normcdff(vB01);
                vB10 *= normcdff(vB10); vB11 *= normcdff(vB11);
            }
            if (res) {
                const float* r0A = res + (size_t)row0 * N + colA;
                const float* r1A = res + (size_t)(row0 + 8) * N + colA;
                vA00 += r0A[0]; vA01 += r0A[1]; vA10 += r1A[0]; vA11 += r1A[1];
                const float* r0B = res + (size_t)row0 * N + colB;
                const float* r1B = res + (size_t)(row0 + 8) * N + colB;
                vB00 += r0B[0]; vB01 += r0B[1]; vB10 += r1B[0]; vB11 += r1B[1];
            }
            if (OUTH) {
                __half* Ch = (__half*)Cv;
                *(__half2*)(Ch + (size_t)row0 * N + colA) = __floats2half2_rn(vA00, vA01);
                *(__half2*)(Ch + (size_t)(row0 + 8) * N + colA) = __floats2half2_rn(vA10, vA11);
                *(__half2*)(Ch + (size_t)row0 * N + colB) = __floats2half2_rn(vB00, vB01);
                *(__half2*)(Ch + (size_t)(row0 + 8) * N + colB) = __floats2half2_rn(vB10, vB11);
            } else {
                float* Cf = (float*)Cv;
                *(float2*)(Cf + (size_t)row0 * N + colA) = make_float2(vA00, vA01);
                *(float2*)(Cf + (size_t)(row0 + 8) * N + colA) = make_float2(vA10, vA11);
                *(float2*)(Cf + (size_t)row0 * N + colB) = make_float2(vB00, vB01);
                *(float2*)(Cf + (size_t)(row0 + 8) * N + colB) = make_float2(vB10, vB11);
            }
        }
    }
}

// ==================== fp16 GEMM 64x128, BK=32 (N=768 GEMMs) ================
template <bool GELU, bool OUTH>
__global__ __launch_bounds__(256, 3)
void gemm_f16_m64(const __half* __restrict__ A, const __half* __restrict__ BmT,
                  const float* __restrict__ bias, const float* __restrict__ res,
                  void* __restrict__ Cv, int M, int N, int K) {
    extern __shared__ __half hsm[];
    __half* AsB = hsm;
    __half* BsB = hsm + 3 * AH64_SZ;
    int tid = threadIdx.x;
    int wid = tid >> 5, lane = tid & 31;
    int g = lane >> 2, tig = lane & 3;
    int wm = wid & 1, wn = wid >> 1;
    int brow = blockIdx.y * 64, bcol = blockIdx.x * 128;

    int arow = tid >> 2, ach = (tid & 3) * 8;
    const __half* apre = A + (size_t)(brow + arow) * K + ach;
    int asoA = arow * HSTS + ach;
    const __half* bpre[2];
    int bso[2];
#pragma unroll
    for (int i = 0; i < 2; i++) {
        int idx = tid + i * 256;
        int row = idx >> 2, ch = (idx & 3) * 8;
        bso[i] = row * HSTS + ch;
        bpre[i] = BmT + (size_t)(bcol + row) * K + ch;
    }

    int nIter = K >> 5;

#define GF_ISSUE64(KT, STG) do {                                              \
        cp16(&AsB[(STG) * AH64_SZ + asoA], apre + (KT) * 32);                 \
        __half* bsd_ = BsB + (STG) * BH64_SZ;                                 \
        _Pragma("unroll")                                                     \
        for (int i = 0; i < 2; i++)                                           \
            cp16(&bsd_[bso[i]], bpre[i] + (KT) * 32);                         \
        cp_commit();                                                           \
    } while (0)

    GF_ISSUE64(0, 0);
    GF_ISSUE64(1, 1);

    float acc[2][4][4];
#pragma unroll
    for (int i = 0; i < 2; i++)
#pragma unroll
        for (int j = 0; j < 4; j++)
#pragma unroll
            for (int r = 0; r < 4; r++) acc[i][j][r] = 0.f;

    int l15 = lane & 15, lkh8 = (lane >> 4) << 3;

    int cur = 0, nxt = 2;
    for (int kt = 0; kt < nIter; ++kt) {
        if (kt + 1 < nIter) cp_wait<1>(); else cp_wait<0>();
        __syncthreads();
        if (kt + 2 < nIter) GF_ISSUE64(kt + 2, nxt);
        const __half* As = AsB + cur * AH64_SZ;
        const __half* Bs = BsB + cur * BH64_SZ;
#pragma unroll
        for (int ks = 0; ks < 32; ks += 16) {
            unsigned af[2][4];
#pragma unroll
            for (int mt = 0; mt < 2; mt++) {
                int R = wm * 32 + mt * 16;
                ldsm4(af[mt], su32(&As[(R + l15) * HSTS + ks + lkh8]));
            }
#pragma unroll
            for (int p = 0; p < 2; p++) {
                unsigned bf[4];
                int nr = wn * 32 + p * 16;
                ldsm4(bf, su32(&Bs[(nr + l15) * HSTS + ks + lkh8]));
                mma_f16(acc[0][2 * p],     af[0], bf[0], bf[2]);
                mma_f16(acc[1][2 * p],     af[1], bf[0], bf[2]);
                mma_f16(acc[0][2 * p + 1], af[0], bf[1], bf[3]);
                mma_f16(acc[1][2 * p + 1], af[1], bf[1], bf[3]);
            }
        }
        cur = cur + 1; if (cur == 3) cur = 0;
        nxt = nxt + 1; if (nxt == 3) nxt = 0;
    }
#undef GF_ISSUE64

#pragma unroll
    for (int mt = 0; mt < 2; mt++) {
        int row0 = brow + wm * 32 + mt * 16 + g;
#pragma unroll
        for (int nt = 0; nt < 4; nt++) {
            int col = bcol + wn * 32 + nt * 8 + tig * 2;
            float b0 = bias[col], b1 = bias[col + 1];
            float v00 = acc[mt][nt][0] + b0;
            float v01 = acc[mt][nt][1] + b1;
            float v10 = acc[mt][nt][2] + b0;
            float v11 = acc[mt][nt][3] + b1;
            if (GELU) {
                v00 *= normcdff(v00); v01 *= normcdff(v01);
                v10 *= normcdff(v10); v11 *= normcdff(v11);
            }
            if (res) {
                const float* r0p = res + (size_t)row0 * N + col;
                const float* r1p = res + (size_t)(row0 + 8) * N + col;
                v00 += r0p[0]; v01 += r0p[1];
                v10 += r1p[0]; v11 += r1p[1];
            }
            if (OUTH) {
                __half* Ch = (__half*)Cv;
                *(__half2*)(Ch + (size_t)row0 * N + col) = __floats2half2_rn(v00, v01);
                *(__half2*)(Ch + (size_t)(row0 + 8) * N + col) = __floats2half2_rn(v10, v11);
            } else {
                float* Cf = (float*)Cv;
                *(float2*)(Cf + (size_t)row0 * N + col) = make_float2(v00, v01);
                *(float2*)(Cf + (size_t)(row0 + 8) * N + col) = make_float2(v10, v11);
            }
        }
    }
}

// ==================== fp16 flash attention: KV tile 128, 1 sync/tile =======
#define QHS 72
#define KV_SZ (128 * QHS)
#define AT_SMEM_BYTES ((128 * QHS + 4 * KV_SZ) * 2)   // 92160

__global__ __launch_bounds__(256, 2)
void attn_f16(const __half* __restrict__ QKV, const float* __restrict__ ab,
              __half* __restrict__ O) {
    extern __shared__ __half hsm[];
    __half* Qh = hsm;                      // [128][72]
    __half* KhB = Qh + 128 * QHS;          // [2][128][72]
    __half* VhB = KhB + 2 * KV_SZ;         // [2][128][72]

    int tid = threadIdx.x;
    int wid = tid >> 5, lane = tid & 31;
    int g = lane >> 2, tig = lane & 3;
    int m0 = wid * 16;
    int l15 = lane & 15, lkh8 = (lane >> 4) << 3;

    int qb = blockIdx.x * 128;
    int h = blockIdx.y, b = blockIdx.z;
    size_t bh = (size_t)b * T_TOK * QKV_N + h * HEAD_DIM;
    const __half* qp = QKV + bh;
    const __half* kp = QKV + bh + 768;
    const __half* vp = QKV + bh + 1536;

#define G_ISSUE(KT, BUF) do {                                                 \
        int kb_ = (KT) * 128;                                                 \
        __half* kd_ = KhB + (BUF) * KV_SZ;                                    \
        __half* vd_ = VhB + (BUF) * KV_SZ;                                    \
        _Pragma("unroll")                                                     \
        for (int it = 0; it < 4; it++) {                                      \
            int idx_ = tid + it * 256;                                        \
            int r_ = idx_ >> 3, c_ = (idx_ & 7) * 8;                          \
            cp16(&kd_[r_ * QHS + c_], kp + (size_t)(kb_ + r_) * QKV_N + c_);  \
            cp16(&vd_[r_ * QHS + c_], vp + (size_t)(kb_ + r_) * QKV_N + c_);  \
        }                                                                     \
        cp_commit();                                                          \
    } while (0)

#pragma unroll
    for (int it = 0; it < 4; it++) {
        int idx = tid + it * 256;
        int r = idx >> 3, c = (idx & 7) * 8;
        cp16(&Qh[r * QHS + c], qp + (size_t)(qb + r) * QKV_N + c);
    }
    cp_commit();
    G_ISSUE(0, 0);

    float mo0 = -1e30f, mo1 = -1e30f, l0 = 0.f, l1 = 0.f;
    float o[8][4];
#pragma unroll
    for (int nt = 0; nt < 8; nt++)
#pragma unroll
        for (int r = 0; r < 4; r++) o[nt][r] = 0.f;

    float bias0 = ab[h * 2 + 0], bias1 = ab[h * 2 + 1];
    int qvar = qb >> 7;

    for (int kt = 0; kt < 16; kt++) {
        cp_wait<0>();
        __syncthreads();
        int cur = kt & 1;
        if (kt + 1 < 16) G_ISSUE(kt + 1, cur ^ 1);
        float bias = (kt == qvar) ? bias0 : bias1;    // 128-token tile == one variate

#pragma unroll
        for (int hh = 0; hh < 2; hh++) {
            const __half* Kh = KhB + cur * KV_SZ + hh * 64 * QHS;
            const __half* Vh = VhB + cur * KV_SZ + hh * 64 * QHS;

            float s[8][4];
#pragma unroll
            for (int nt = 0; nt < 8; nt++)
#pragma unroll
                for (int r = 0; r < 4; r++) s[nt][r] = 0.f;
#pragma unroll
            for (int ks = 0; ks < 64; ks += 16) {
                unsigned af[4];
                ldsm4(af, su32(&Qh[(m0 + l15) * QHS + ks + lkh8]));
#pragma unroll
                for (int p = 0; p < 4; p++) {
                    unsigned bf[4];
                    ldsm4(bf, su32(&Kh[(p * 16 + l15) * QHS + ks + lkh8]));
                    mma_f16(s[2 * p],     af, bf[0], bf[2]);
                    mma_f16(s[2 * p + 1], af, bf[1], bf[3]);
                }
            }

            float mx0 = mo0, mx1 = mo1;
#pragma unroll
            for (int nt = 0; nt < 8; nt++) {
                s[nt][0] += bias; s[nt][1] += bias; s[nt][2] += bias; s[nt][3] += bias;
                mx0 = fmaxf(mx0, fmaxf(s[nt][0], s[nt][1]));
                mx1 = fmaxf(mx1, fmaxf(s[nt][2], s[nt][3]));
            }
            mx0 = fmaxf(mx0, __shfl_xor_sync(0xffffffffu, mx0, 1));
            mx0 = fmaxf(mx0, __shfl_xor_sync(0xffffffffu, mx0, 2));
            mx1 = fmaxf(mx1, __shfl_xor_sync(0xffffffffu, mx1, 1));
            mx1 = fmaxf(mx1, __shfl_xor_sync(0xffffffffu, mx1, 2));
            float scl0 = __expf(mo0 - mx0), scl1 = __expf(mo1 - mx1);
            float sum0 = 0.f, sum1 = 0.f;
#pragma unroll
            for (int nt = 0; nt < 8; nt++) {
                s[nt][0] = __expf(s[nt][0] - mx0); sum0 += s[nt][0];
                s[nt][1] = __expf(s[nt][1] - mx0); sum0 += s[nt][1];
                s[nt][2] = __expf(s[nt][2] - mx1); sum1 += s[nt][2];
                s[nt][3] = __expf(s[nt][3] - mx1); sum1 += s[nt][3];
            }
            sum0 += __shfl_xor_sync(0xffffffffu, sum0, 1);
            sum0 += __shfl_xor_sync(0xffffffffu, sum0, 2);
            sum1 += __shfl_xor_sync(0xffffffffu, sum1, 1);
            sum1 += __shfl_xor_sync(0xffffffffu, sum1, 2);
            l0 = l0 * scl0 + sum0; mo0 = mx0;
            l1 = l1 * scl1 + sum1; mo1 = mx1;
#pragma unroll
            for (int nt = 0; nt < 8; nt++) {
                o[nt][0] *= scl0; o[nt][1] *= scl0;
                o[nt][2] *= scl1; o[nt][3] *= scl1;
            }

#pragma unroll
            for (int p = 0; p < 4; p++) {
                unsigned af2[4];
                af2[0] = pack2(s[2 * p][0],     s[2 * p][1]);
                af2[1] = pack2(s[2 * p][2],     s[2 * p][3]);
                af2[2] = pack2(s[2 * p + 1][0], s[2 * p + 1][1]);
                af2[3] = pack2(s[2 * p + 1][2], s[2 * p + 1][3]);
#pragma unroll
                for (int cbt = 0; cbt < 4; cbt++) {
                    unsigned bf[4];
                    ldsm4t(bf, su32(&Vh[(p * 16 + l15) * QHS + cbt * 16 + lkh8]));
                    mma_f16(o[2 * cbt],     af2, bf[0], bf[1]);
                    mma_f16(o[2 * cbt + 1], af2, bf[2], bf[3]);
                }
            }
        }
    }
#undef G_ISSUE

    float inv0 = 1.f / l0, inv1 = 1.f / l1;
    int row0 = qb + m0 + g;
#pragma unroll
    for (int nt = 0; nt < 8; nt++) {
        int col = nt * 8 + tig * 2;
        __half* o0 = O + (size_t)(b * T_TOK + row0) * D_MODEL + h * HEAD_DIM + col;
        __half* o1 = O + (size_t)(b * T_TOK + row0 + 8) * D_MODEL + h * HEAD_DIM + col;
        *(__half2*)o0 = __floats2half2_rn(o[nt][0] * inv0, o[nt][1] * inv0);
        *(__half2*)o1 = __floats2half2_rn(o[nt][2] * inv1, o[nt][3] * inv1);
    }
}

// -------------------- launch ----------------------------------------------
extern "C" void kernel_launch(void* const* d_in, const int* in_sizes, int n_in,
                              void* d_out, int out_size) {
    const float* hs  = (const float*)d_in[0];
    const float* wq  = (const float*)d_in[1];
    const float* bq  = (const float*)d_in[2];
    const float* wk  = (const float*)d_in[3];
    const float* bk  = (const float*)d_in[4];
    const float* wv  = (const float*)d_in[5];
    const float* bv  = (const float*)d_in[6];
    const float* wo  = (const float*)d_in[7];
    const float* bo  = (const float*)d_in[8];
    const float* ab  = (const float*)d_in[9];
    const float* g1  = (const float*)d_in[10];
    const float* be1 = (const float*)d_in[11];
    const float* g3  = (const float*)d_in[12];
    const float* be3 = (const float*)d_in[13];
    const float* w1  = (const float*)d_in[14];
    const float* b1  = (const float*)d_in[15];
    const float* w2  = (const float*)d_in[16];
    const float* b2  = (const float*)d_in[17];
    float* out = (float*)d_out;

    __half *ni, *qkv, *wqkvT, *woT, *w1T, *w2T, *attn, *ffin, *hbuf;
    float *bqkv, *res1, *trig;
    cudaGetSymbolAddress((void**)&ni,    g_ni);
    cudaGetSymbolAddress((void**)&qkv,   g_qkv);
    cudaGetSymbolAddress((void**)&wqkvT, g_wqkvT);
    cudaGetSymbolAddress((void**)&bqkv,  g_bqkv);
    cudaGetSymbolAddress((void**)&woT,   g_woT);
    cudaGetSymbolAddress((void**)&w1T,   g_w1T);
    cudaGetSymbolAddress((void**)&w2T,   g_w2T);
    cudaGetSymbolAddress((void**)&attn,  g_attn);
    cudaGetSymbolAddress((void**)&res1,  g_res1);
    cudaGetSymbolAddress((void**)&ffin,  g_ffin);
    cudaGetSymbolAddress((void**)&hbuf,  g_h);
    cudaGetSymbolAddress((void**)&trig,  g_trig);

    static bool attr_set = false;
    if (!attr_set) {
        cudaFuncSetAttribute(attn_f16, cudaFuncAttributeMaxDynamicSharedMemorySize,
                             AT_SMEM_BYTES);
        cudaFuncSetAttribute((gemm_f16<false, true, true>), cudaFuncAttributeMaxDynamicSharedMemorySize,
                             G128_SMEM_BYTES);
        cudaFuncSetAttribute((gemm_f16<true, true, false>), cudaFuncAttributeMaxDynamicSharedMemorySize,
                             G128_SMEM_BYTES);
        cudaFuncSetAttribute((gemm_f16_m64<false, false>), cudaFuncAttributeMaxDynamicSharedMemorySize,
                             G64_SMEM_BYTES);
        attr_set = true;
    }

    // 0. prep
    trig_kernel<<<(T_TOK * 16 + 255) / 256, 256>>>(trig);
    concat_bias<<<(QKV_N + 255) / 256, 256>>>(bq, bk, bv, bqkv);
    transpose_all<<<6912, dim3(32, 8)>>>(wq, wk, wv, wo, w1, w2, wqkvT, woT, w1T, w2T);

    // 1. LN1 -> fp16
    ln_warp<<<M_ROWS / 8, 256>>>(hs, g1, be1, ni);

    // 2. fused QKV projection + RoPE
    gemm_f16<false, true, true><<<dim3(QKV_N / 128, M_ROWS / 128), 256, G128_SMEM_BYTES>>>(
        ni, wqkvT, bqkv, nullptr, qkv, trig, M_ROWS, QKV_N, D_MODEL);

    // 3. attention
    {
        dim3 ga(T_TOK / 128, N_HEADS, BATCH);
        attn_f16<<<ga, 256, AT_SMEM_BYTES>>>(qkv, ab, attn);
    }

    // 4. out-proj + residual(hs)
    gemm_f16_m64<false, false><<<dim3(D_MODEL / 128, M_ROWS / 64), 256, G64_SMEM_BYTES>>>(
        attn, woT, bo, hs, res1, M_ROWS, D_MODEL, D_MODEL);

    // 5. LN3 -> fp16
    ln_warp<<<M_ROWS / 8, 256>>>(res1, g3, be3, ffin);

    // 6. FFN1 + GELU
    gemm_f16<true, true, false><<<dim3(FFN_DIM / 128, M_ROWS / 128), 256, G128_SMEM_BYTES>>>(
        ffin, w1T, b1, nullptr, hbuf, nullptr, M_ROWS, FFN_DIM, D_MODEL);

    // 7. FFN2 + residual(res1)
    gemm_f16_m64<false, false><<<dim3(D_MODEL / 128, M_ROWS / 64), 256, G64_SMEM_BYTES>>>(
        hbuf, w2T, b2, res1, out, M_ROWS, D_MODEL, FFN_DIM);
}

// round 15
// speedup vs baseline: 2.3309x; 1.0324x over previous
#include <cuda_runtime.h>
#include <cuda_fp16.h>
#include <math.h>
#include <stdint.h>

#define D_MODEL 768
#define N_HEADS 12
#define HEAD_DIM 64
#define FFN_DIM 3072
#define T_TOK 2048
#define BATCH 2
#define M_ROWS (BATCH * T_TOK)   // 4096
#define QKV_N 2304               // 3 * D_MODEL

// -------------------- scratch ---------------------------------------------
__device__ __half g_ni[M_ROWS * D_MODEL];
__device__ __half g_qkv[M_ROWS * QKV_N];
__device__ __half g_wqkvT[QKV_N * D_MODEL];
__device__ float  g_bqkv[QKV_N];
__device__ __half g_woT[D_MODEL * D_MODEL];
__device__ __half g_w1T[FFN_DIM * D_MODEL];
__device__ __half g_w2T[D_MODEL * FFN_DIM];
__device__ __half g_attn[M_ROWS * D_MODEL];
__device__ float  g_res1[M_ROWS * D_MODEL];
__device__ __half g_ffin[M_ROWS * D_MODEL];
__device__ __half g_h[M_ROWS * FFN_DIM];
__device__ float  g_trig[T_TOK * 16 * 2];

// -------------------- helpers ---------------------------------------------
__device__ __forceinline__ unsigned su32(const void* p) {
    return (unsigned)__cvta_generic_to_shared(p);
}
__device__ __forceinline__ void cp16(void* smem_dst, const void* gptr) {
    asm volatile("cp.async.cg.shared.global [%0], [%1], 16;" :: "r"(su32(smem_dst)), "l"(gptr));
}
__device__ __forceinline__ void cp_commit() { asm volatile("cp.async.commit_group;"); }
template <int NN>
__device__ __forceinline__ void cp_wait() { asm volatile("cp.async.wait_group %0;" :: "n"(NN)); }

__device__ __forceinline__ void mma_f16(float* c, const unsigned* a, unsigned b0, unsigned b1) {
    asm volatile(
        "mma.sync.aligned.m16n8k16.row.col.f32.f16.f16.f32 "
        "{%0,%1,%2,%3}, {%4,%5,%6,%7}, {%8,%9}, {%0,%1,%2,%3};"
        : "+f"(c[0]), "+f"(c[1]), "+f"(c[2]), "+f"(c[3])
        : "r"(a[0]), "r"(a[1]), "r"(a[2]), "r"(a[3]), "r"(b0), "r"(b1));
}
__device__ __forceinline__ void ldsm4(unsigned* r, unsigned addr) {
    asm volatile("ldmatrix.sync.aligned.m8n8.x4.shared.b16 {%0,%1,%2,%3}, [%4];"
                 : "=r"(r[0]), "=r"(r[1]), "=r"(r[2]), "=r"(r[3]) : "r"(addr));
}
__device__ __forceinline__ void ldsm4t(unsigned* r, unsigned addr) {
    asm volatile("ldmatrix.sync.aligned.m8n8.x4.trans.shared.b16 {%0,%1,%2,%3}, [%4];"
                 : "=r"(r[0]), "=r"(r[1]), "=r"(r[2]), "=r"(r[3]) : "r"(addr));
}
__device__ __forceinline__ unsigned pack2(float lo, float hi) {
    __half2 h = __floats2half2_rn(lo, hi);
    return *(unsigned*)&h;
}

// -------------------- warp-per-row LayerNorm ------------------------------
__global__ void ln_warp(const float* __restrict__ x, const float* __restrict__ g,
                        const float* __restrict__ bta, __half* __restrict__ y) {
    int w = (blockIdx.x * blockDim.x + threadIdx.x) >> 5;
    int lane = threadIdx.x & 31;
    if (w >= M_ROWS) return;
    const float* xr = x + (size_t)w * D_MODEL;
    float4 v[6];
    float sum = 0.f;
#pragma unroll
    for (int i = 0; i < 6; i++) {
        v[i] = *(const float4*)(xr + i * 128 + lane * 4);
        sum += v[i].x + v[i].y + v[i].z + v[i].w;
    }
#pragma unroll
    for (int o = 16; o; o >>= 1) sum += __shfl_xor_sync(0xffffffffu, sum, o);
    float mu = sum * (1.f / 768.f);
    float var = 0.f;
#pragma unroll
    for (int i = 0; i < 6; i++) {
        v[i].x -= mu; v[i].y -= mu; v[i].z -= mu; v[i].w -= mu;
        var += v[i].x * v[i].x + v[i].y * v[i].y + v[i].z * v[i].z + v[i].w * v[i].w;
    }
#pragma unroll
    for (int o = 16; o; o >>= 1) var += __shfl_xor_sync(0xffffffffu, var, o);
    float rs = rsqrtf(var * (1.f / 768.f) + 1e-5f);
    __half* yr = y + (size_t)w * D_MODEL;
#pragma unroll
    for (int i = 0; i < 6; i++) {
        int col = i * 128 + lane * 4;
        float4 gv = *(const float4*)(g + col);
        float4 bv = *(const float4*)(bta + col);
        __half2 h0 = __floats2half2_rn(v[i].x * rs * gv.x + bv.x, v[i].y * rs * gv.y + bv.y);
        __half2 h1 = __floats2half2_rn(v[i].z * rs * gv.z + bv.z, v[i].w * rs * gv.w + bv.w);
        *(__half2*)(yr + col) = h0;
        *(__half2*)(yr + col + 2) = h1;
    }
}

// -------------------- merged weight transposes ----------------------------
__global__ void transpose_all(const float* __restrict__ wq, const float* __restrict__ wk,
                              const float* __restrict__ wv, const float* __restrict__ wo,
                              const float* __restrict__ w1, const float* __restrict__ w2,
                              __half* __restrict__ wqkvT, __half* __restrict__ woT,
                              __half* __restrict__ w1T, __half* __restrict__ w2T) {
    __shared__ float t[32][33];
    int bid = blockIdx.x;
    const float* src;
    __half* dst;
    int R, C, bx, by;
    float scale = 1.f;
    if (bid < 2304) {
        int seg = bid / 576, r = bid % 576;
        bx = r % 24; by = r / 24; R = 768; C = 768;
        if (seg == 0)      { src = wq; dst = wqkvT; scale = 0.125f; }
        else if (seg == 1) { src = wk; dst = wqkvT + 768 * 768; }
        else if (seg == 2) { src = wv; dst = wqkvT + 1536 * 768; }
        else               { src = wo; dst = woT; }
    } else if (bid < 4608) {
        int r = bid - 2304;
        bx = r % 96; by = r / 96; R = 768; C = 3072;
        src = w1; dst = w1T;
    } else {
        int r = bid - 4608;
        bx = r % 24; by = r / 24; R = 3072; C = 768;
        src = w2; dst = w2T;
    }
    int X = bx * 32, Y = by * 32;
    int x = threadIdx.x, y = threadIdx.y;
#pragma unroll
    for (int i = 0; i < 32; i += 8)
        t[y + i][x] = src[(size_t)(Y + y + i) * C + X + x] * scale;
    __syncthreads();
#pragma unroll
    for (int i = 0; i < 32; i += 8)
        dst[(size_t)(X + y + i) * R + Y + x] = __float2half(t[x][y + i]);
}

// -------------------- bias concat -----------------------------------------
__global__ void concat_bias(const float* __restrict__ bq, const float* __restrict__ bk,
                            const float* __restrict__ bv, float* __restrict__ Bo) {
    int j = blockIdx.x * 256 + threadIdx.x;
    if (j < 768) Bo[j] = bq[j] * 0.125f;
    else if (j < 1536) Bo[j] = bk[j - 768];
    else if (j < 2304) Bo[j] = bv[j - 1536];
}

// -------------------- trig table ------------------------------------------
__global__ void trig_kernel(float* __restrict__ trig) {
    int idx = blockIdx.x * 256 + threadIdx.x;
    if (idx >= T_TOK * 16) return;
    int t = idx >> 4, i = idx & 15;
    double ts = pow(10000.0, (double)i / 32.0);
    double ang = (double)t / ts;
    double sd, cd;
    sincos(ang, &sd, &cd);
    trig[idx * 2]     = (float)cd;
    trig[idx * 2 + 1] = (float)sd;
}

// ==================== fp16 GEMM 128x128, BK=64, 3-stage ====================
#define HSTB 72
#define AHB_SZ (128 * HSTB)
#define G128_SMEM_BYTES (3 * 2 * AHB_SZ * 2)
// m64 variant: BK=64, 2-stage
#define AH64B_SZ (64 * HSTB)
#define G64_SMEM_BYTES (2 * (AH64B_SZ + AHB_SZ) * 2)   // 55296

template <bool GELU, bool OUTH, bool ROPE>
__global__ __launch_bounds__(256, 2)
void gemm_f16(const __half* __restrict__ A, const __half* __restrict__ BmT,
              const float* __restrict__ bias, const float* __restrict__ res,
              void* __restrict__ Cv, const float* __restrict__ trig,
              int M, int N, int K) {
    extern __shared__ __half hsm[];
    __half* AsB = hsm;
    __half* BsB = hsm + 3 * AHB_SZ;
    int tid = threadIdx.x;
    int wid = tid >> 5, lane = tid & 31;
    int g = lane >> 2, tig = lane & 3;
    int wm = wid & 3, wn = wid >> 2;
    int brow = blockIdx.y * 128, bcol = blockIdx.x * 128;

    const __half* apre[4];
    const __half* bpre[4];
    int aso[4];
#pragma unroll
    for (int i = 0; i < 4; i++) {
        int idx = tid + i * 256;
        int row = idx >> 3, ch = (idx & 7) * 8;
        aso[i] = row * HSTB + ch;
        apre[i] = A + (size_t)(brow + row) * K + ch;
        bpre[i] = BmT + (size_t)(bcol + row) * K + ch;
    }

    int nIter = K >> 6;

#define GF_ISSUE(KT, STG) do {                                                \
        __half* asd_ = AsB + (STG) * AHB_SZ;                                  \
        __half* bsd_ = BsB + (STG) * AHB_SZ;                                  \
        _Pragma("unroll")                                                     \
        for (int i = 0; i < 4; i++) {                                         \
            cp16(&asd_[aso[i]], apre[i] + (KT) * 64);                         \
            cp16(&bsd_[aso[i]], bpre[i] + (KT) * 64);                         \
        }                                                                     \
        cp_commit();                                                           \
    } while (0)

    GF_ISSUE(0, 0);
    GF_ISSUE(1, 1);

    float acc[2][8][4];
#pragma unroll
    for (int i = 0; i < 2; i++)
#pragma unroll
        for (int j = 0; j < 8; j++)
#pragma unroll
            for (int r = 0; r < 4; r++) acc[i][j][r] = 0.f;

    int l15 = lane & 15, lkh8 = (lane >> 4) << 3;

    int cur = 0, nxt = 2;
    for (int kt = 0; kt < nIter; ++kt) {
        if (kt + 1 < nIter) cp_wait<1>(); else cp_wait<0>();
        __syncthreads();
        if (kt + 2 < nIter) GF_ISSUE(kt + 2, nxt);
        const __half* As = AsB + cur * AHB_SZ;
        const __half* Bs = BsB + cur * AHB_SZ;
#pragma unroll
        for (int ks = 0; ks < 64; ks += 16) {
            unsigned af[2][4];
#pragma unroll
            for (int mt = 0; mt < 2; mt++) {
                int R = wm * 32 + mt * 16;
                ldsm4(af[mt], su32(&As[(R + l15) * HSTB + ks + lkh8]));
            }
#pragma unroll
            for (int p = 0; p < 4; p++) {
                unsigned bf[4];
                int nr = wn * 64 + p * 16;
                ldsm4(bf, su32(&Bs[(nr + l15) * HSTB + ks + lkh8]));
                mma_f16(acc[0][2 * p],     af[0], bf[0], bf[2]);
                mma_f16(acc[1][2 * p],     af[1], bf[0], bf[2]);
                mma_f16(acc[0][2 * p + 1], af[0], bf[1], bf[3]);
                mma_f16(acc[1][2 * p + 1], af[1], bf[1], bf[3]);
            }
        }
        cur = cur + 1; if (cur == 3) cur = 0;
        nxt = nxt + 1; if (nxt == 3) nxt = 0;
    }
#undef GF_ISSUE

#pragma unroll
    for (int mt = 0; mt < 2; mt++) {
        int row0 = brow + wm * 32 + mt * 16 + g;
        int t0 = row0 & (T_TOK - 1);
        int t1 = (row0 + 8) & (T_TOK - 1);
        bool doRope = ROPE && (bcol + wn * 64) < 1536;
#pragma unroll
        for (int nt2 = 0; nt2 < 4; nt2++) {
            int ntA = nt2, ntB = nt2 + 4;
            int colA = bcol + wn * 64 + ntA * 8 + tig * 2;
            int colB = colA + 32;
            float bA0 = bias[colA], bA1 = bias[colA + 1];
            float bB0 = bias[colB], bB1 = bias[colB + 1];
            float vA00 = acc[mt][ntA][0] + bA0, vA01 = acc[mt][ntA][1] + bA1;
            float vA10 = acc[mt][ntA][2] + bA0, vA11 = acc[mt][ntA][3] + bA1;
            float vB00 = acc[mt][ntB][0] + bB0, vB01 = acc[mt][ntB][1] + bB1;
            float vB10 = acc[mt][ntB][2] + bB0, vB11 = acc[mt][ntB][3] + bB1;
            if (doRope && nt2 < 2) {
                int i0 = ntA * 8 + tig * 2;
                float c00 = trig[(t0 * 16 + i0) * 2],     s00 = trig[(t0 * 16 + i0) * 2 + 1];
                float c01 = trig[(t0 * 16 + i0 + 1) * 2], s01 = trig[(t0 * 16 + i0 + 1) * 2 + 1];
                float c10 = trig[(t1 * 16 + i0) * 2],     s10 = trig[(t1 * 16 + i0) * 2 + 1];
                float c11 = trig[(t1 * 16 + i0 + 1) * 2], s11 = trig[(t1 * 16 + i0 + 1) * 2 + 1];
                float x1, x2;
                x1 = vA00; x2 = vB00; vA00 = x1 * c00 - x2 * s00; vB00 = x2 * c00 + x1 * s00;
                x1 = vA01; x2 = vB01; vA01 = x1 * c01 - x2 * s01; vB01 = x2 * c01 + x1 * s01;
                x1 = vA10; x2 = vB10; vA10 = x1 * c10 - x2 * s10; vB10 = x2 * c10 + x1 * s10;
                x1 = vA11; x2 = vB11; vA11 = x1 * c11 - x2 * s11; vB11 = x2 * c11 + x1 * s11;
            }
            if (GELU) {
                vA00 *= normcdff(vA00); vA01 *= normcdff(vA01);
                vA10 *= normcdff(vA10); vA11 *= normcdff(vA11);
                vB00 *= normcdff(vB00); vB01 *= normcdff(vB01);
                vB10 *= normcdff(vB10); vB11 *= normcdff(vB11);
            }
            if (res) {
                const float* r0A = res + (size_t)row0 * N + colA;
                const float* r1A = res + (size_t)(row0 + 8) * N + colA;
                vA00 += r0A[0]; vA01 += r0A[1]; vA10 += r1A[0]; vA11 += r1A[1];
                const float* r0B = res + (size_t)row0 * N + colB;
                const float* r1B = res + (size_t)(row0 + 8) * N + colB;
                vB00 += r0B[0]; vB01 += r0B[1]; vB10 += r1B[0]; vB11 += r1B[1];
            }
            if (OUTH) {
                __half* Ch = (__half*)Cv;
                *(__half2*)(Ch + (size_t)row0 * N + colA) = __floats2half2_rn(vA00, vA01);
                *(__half2*)(Ch + (size_t)(row0 + 8) * N + colA) = __floats2half2_rn(vA10, vA11);
                *(__half2*)(Ch + (size_t)row0 * N + colB) = __floats2half2_rn(vB00, vB01);
                *(__half2*)(Ch + (size_t)(row0 + 8) * N + colB) = __floats2half2_rn(vB10, vB11);
            } else {
                float* Cf = (float*)Cv;
                *(float2*)(Cf + (size_t)row0 * N + colA) = make_float2(vA00, vA01);
                *(float2*)(Cf + (size_t)(row0 + 8) * N + colA) = make_float2(vA10, vA11);
                *(float2*)(Cf + (size_t)row0 * N + colB) = make_float2(vB00, vB01);
                *(float2*)(Cf + (size_t)(row0 + 8) * N + colB) = make_float2(vB10, vB11);
            }
        }
    }
}

// ==================== fp16 GEMM 64x128, BK=64, 2-stage (N=768 GEMMs) =======
template <bool GELU, bool OUTH>
__global__ __launch_bounds__(256, 3)
void gemm_f16_m64(const __half* __restrict__ A, const __half* __restrict__ BmT,
                  const float* __restrict__ bias, const float* __restrict__ res,
                  void* __restrict__ Cv, int M, int N, int K) {
    extern __shared__ __half hsm[];
    __half* AsB = hsm;                       // 2 stages of [64][72]
    __half* BsB = hsm + 2 * AH64B_SZ;        // 2 stages of [128][72]
    int tid = threadIdx.x;
    int wid = tid >> 5, lane = tid & 31;
    int g = lane >> 2, tig = lane & 3;
    int wm = wid & 1, wn = wid >> 1;
    int brow = blockIdx.y * 64, bcol = blockIdx.x * 128;

    // A: 64 rows x 8 chunks = 512 -> 2/thread ; B: 128 x 8 = 1024 -> 4/thread
    const __half* apre[2];
    int aso[2];
#pragma unroll
    for (int i = 0; i < 2; i++) {
        int idx = tid + i * 256;
        int row = idx >> 3, ch = (idx & 7) * 8;
        aso[i] = row * HSTB + ch;
        apre[i] = A + (size_t)(brow + row) * K + ch;
    }
    const __half* bpre[4];
    int bso[4];
#pragma unroll
    for (int i = 0; i < 4; i++) {
        int idx = tid + i * 256;
        int row = idx >> 3, ch = (idx & 7) * 8;
        bso[i] = row * HSTB + ch;
        bpre[i] = BmT + (size_t)(bcol + row) * K + ch;
    }

    int nIter = K >> 6;

#define GF_ISSUE64(KT, STG) do {                                              \
        __half* asd_ = AsB + (STG) * AH64B_SZ;                                \
        __half* bsd_ = BsB + (STG) * AHB_SZ;                                  \
        _Pragma("unroll")                                                     \
        for (int i = 0; i < 2; i++)                                           \
            cp16(&asd_[aso[i]], apre[i] + (KT) * 64);                         \
        _Pragma("unroll")                                                     \
        for (int i = 0; i < 4; i++)                                           \
            cp16(&bsd_[bso[i]], bpre[i] + (KT) * 64);                         \
        cp_commit();                                                           \
    } while (0)

    GF_ISSUE64(0, 0);

    float acc[2][4][4];
#pragma unroll
    for (int i = 0; i < 2; i++)
#pragma unroll
        for (int j = 0; j < 4; j++)
#pragma unroll
            for (int r = 0; r < 4; r++) acc[i][j][r] = 0.f;

    int l15 = lane & 15, lkh8 = (lane >> 4) << 3;

    for (int kt = 0; kt < nIter; ++kt) {
        int cur = kt & 1;
        cp_wait<0>();
        __syncthreads();
        // sync proves all reads of buffer cur^1 (iteration kt-1) are done
        if (kt + 1 < nIter) GF_ISSUE64(kt + 1, cur ^ 1);
        const __half* As = AsB + cur * AH64B_SZ;
        const __half* Bs = BsB + cur * AHB_SZ;
#pragma unroll
        for (int ks = 0; ks < 64; ks += 16) {
            unsigned af[2][4];
#pragma unroll
            for (int mt = 0; mt < 2; mt++) {
                int R = wm * 32 + mt * 16;
                ldsm4(af[mt], su32(&As[(R + l15) * HSTB + ks + lkh8]));
            }
#pragma unroll
            for (int p = 0; p < 2; p++) {
                unsigned bf[4];
                int nr = wn * 32 + p * 16;
                ldsm4(bf, su32(&Bs[(nr + l15) * HSTB + ks + lkh8]));
                mma_f16(acc[0][2 * p],     af[0], bf[0], bf[2]);
                mma_f16(acc[1][2 * p],     af[1], bf[0], bf[2]);
                mma_f16(acc[0][2 * p + 1], af[0], bf[1], bf[3]);
                mma_f16(acc[1][2 * p + 1], af[1], bf[1], bf[3]);
            }
        }
    }
#undef GF_ISSUE64

#pragma unroll
    for (int mt = 0; mt < 2; mt++) {
        int row0 = brow + wm * 32 + mt * 16 + g;
#pragma unroll
        for (int nt = 0; nt < 4; nt++) {
            int col = bcol + wn * 32 + nt * 8 + tig * 2;
            float b0 = bias[col], b1 = bias[col + 1];
            float v00 = acc[mt][nt][0] + b0;
            float v01 = acc[mt][nt][1] + b1;
            float v10 = acc[mt][nt][2] + b0;
            float v11 = acc[mt][nt][3] + b1;
            if (GELU) {
                v00 *= normcdff(v00); v01 *= normcdff(v01);
                v10 *= normcdff(v10); v11 *= normcdff(v11);
            }
            if (res) {
                const float* r0p = res + (size_t)row0 * N + col;
                const float* r1p = res + (size_t)(row0 + 8) * N + col;
                v00 += r0p[0]; v01 += r0p[1];
                v10 += r1p[0]; v11 += r1p[1];
            }
            if (OUTH) {
                __half* Ch = (__half*)Cv;
                *(__half2*)(Ch + (size_t)row0 * N + col) = __floats2half2_rn(v00, v01);
                *(__half2*)(Ch + (size_t)(row0 + 8) * N + col) = __floats2half2_rn(v10, v11);
            } else {
                float* Cf = (float*)Cv;
                *(float2*)(Cf + (size_t)row0 * N + col) = make_float2(v00, v01);
                *(float2*)(Cf + (size_t)(row0 + 8) * N + col) = make_float2(v10, v11);
            }
        }
    }
}

// ==================== fp16 flash attention: Q frags hoisted ================
#define QHS 72
#define KV_SZ (128 * QHS)
#define AT_SMEM_BYTES ((128 * QHS + 4 * KV_SZ) * 2)

__global__ __launch_bounds__(256, 2)
void attn_f16(const __half* __restrict__ QKV, const float* __restrict__ ab,
              __half* __restrict__ O) {
    extern __shared__ __half hsm[];
    __half* Qh = hsm;
    __half* KhB = Qh + 128 * QHS;
    __half* VhB = KhB + 2 * KV_SZ;

    int tid = threadIdx.x;
    int wid = tid >> 5, lane = tid & 31;
    int g = lane >> 2, tig = lane & 3;
    int m0 = wid * 16;
    int l15 = lane & 15, lkh8 = (lane >> 4) << 3;

    int qb = blockIdx.x * 128;
    int h = blockIdx.y, b = blockIdx.z;
    size_t bh = (size_t)b * T_TOK * QKV_N + h * HEAD_DIM;
    const __half* qp = QKV + bh;
    const __half* kp = QKV + bh + 768;
    const __half* vp = QKV + bh + 1536;

#define G_ISSUE(KT, BUF) do {                                                 \
        int kb_ = (KT) * 128;                                                 \
        __half* kd_ = KhB + (BUF) * KV_SZ;                                    \
        __half* vd_ = VhB + (BUF) * KV_SZ;                                    \
        _Pragma("unroll")                                                     \
        for (int it = 0; it < 4; it++) {                                      \
            int idx_ = tid + it * 256;                                        \
            int r_ = idx_ >> 3, c_ = (idx_ & 7) * 8;                          \
            cp16(&kd_[r_ * QHS + c_], kp + (size_t)(kb_ + r_) * QKV_N + c_);  \
            cp16(&vd_[r_ * QHS + c_], vp + (size_t)(kb_ + r_) * QKV_N + c_);  \
        }                                                                     \
        cp_commit();                                                          \
    } while (0)

    // stage Q (group 0), then K0/V0 (group 1)
#pragma unroll
    for (int it = 0; it < 4; it++) {
        int idx = tid + it * 256;
        int r = idx >> 3, c = (idx & 7) * 8;
        cp16(&Qh[r * QHS + c], qp + (size_t)(qb + r) * QKV_N + c);
    }
    cp_commit();
    G_ISSUE(0, 0);

    // hoist Q fragments: wait group 0 (Q) only, K0/V0 may still fly
    cp_wait<1>();
    __syncthreads();
    unsigned qf[4][4];
#pragma unroll
    for (int ks4 = 0; ks4 < 4; ks4++)
        ldsm4(qf[ks4], su32(&Qh[(m0 + l15) * QHS + ks4 * 16 + lkh8]));

    float mo0 = -1e30f, mo1 = -1e30f, l0 = 0.f, l1 = 0.f;
    float o[8][4];
#pragma unroll
    for (int nt = 0; nt < 8; nt++)
#pragma unroll
        for (int r = 0; r < 4; r++) o[nt][r] = 0.f;

    float bias0 = ab[h * 2 + 0], bias1 = ab[h * 2 + 1];
    int qvar = qb >> 7;

    for (int kt = 0; kt < 16; kt++) {
        cp_wait<0>();
        __syncthreads();
        int cur = kt & 1;
        if (kt + 1 < 16) G_ISSUE(kt + 1, cur ^ 1);
        float bias = (kt == qvar) ? bias0 : bias1;

#pragma unroll
        for (int hh = 0; hh < 2; hh++) {
            const __half* Kh = KhB + cur * KV_SZ + hh * 64 * QHS;
            const __half* Vh = VhB + cur * KV_SZ + hh * 64 * QHS;

            float s[8][4];
#pragma unroll
            for (int nt = 0; nt < 8; nt++)
#pragma unroll
                for (int r = 0; r < 4; r++) s[nt][r] = 0.f;
#pragma unroll
            for (int ks4 = 0; ks4 < 4; ks4++) {
#pragma unroll
                for (int p = 0; p < 4; p++) {
                    unsigned bf[4];
                    ldsm4(bf, su32(&Kh[(p * 16 + l15) * QHS + ks4 * 16 + lkh8]));
                    mma_f16(s[2 * p],     qf[ks4], bf[0], bf[2]);
                    mma_f16(s[2 * p + 1], qf[ks4], bf[1], bf[3]);
                }
            }

            float mx0 = mo0, mx1 = mo1;
#pragma unroll
            for (int nt = 0; nt < 8; nt++) {
                s[nt][0] += bias; s[nt][1] += bias; s[nt][2] += bias; s[nt][3] += bias;
                mx0 = fmaxf(mx0, fmaxf(s[nt][0], s[nt][1]));
                mx1 = fmaxf(mx1, fmaxf(s[nt][2], s[nt][3]));
            }
            mx0 = fmaxf(mx0, __shfl_xor_sync(0xffffffffu, mx0, 1));
            mx0 = fmaxf(mx0, __shfl_xor_sync(0xffffffffu, mx0, 2));
            mx1 = fmaxf(mx1, __shfl_xor_sync(0xffffffffu, mx1, 1));
            mx1 = fmaxf(mx1, __shfl_xor_sync(0xffffffffu, mx1, 2));
            float scl0 = __expf(mo0 - mx0), scl1 = __expf(mo1 - mx1);
            float sum0 = 0.f, sum1 = 0.f;
#pragma unroll
            for (int nt = 0; nt < 8; nt++) {
                s[nt][0] = __expf(s[nt][0] - mx0); sum0 += s[nt][0];
                s[nt][1] = __expf(s[nt][1] - mx0); sum0 += s[nt][1];
                s[nt][2] = __expf(s[nt][2] - mx1); sum1 += s[nt][2];
                s[nt][3] = __expf(s[nt][3] - mx1); sum1 += s[nt][3];
            }
            sum0 += __shfl_xor_sync(0xffffffffu, sum0, 1);
            sum0 += __shfl_xor_sync(0xffffffffu, sum0, 2);
            sum1 += __shfl_xor_sync(0xffffffffu, sum1, 1);
            sum1 += __shfl_xor_sync(0xffffffffu, sum1, 2);
            l0 = l0 * scl0 + sum0; mo0 = mx0;
            l1 = l1 * scl1 + sum1; mo1 = mx1;
#pragma unroll
            for (int nt = 0; nt < 8; nt++) {
                o[nt][0] *= scl0; o[nt][1] *= scl0;
                o[nt][2] *= scl1; o[nt][3] *= scl1;
            }

#pragma unroll
            for (int p = 0; p < 4; p++) {
                unsigned af2[4];
                af2[0] = pack2(s[2 * p][0],     s[2 * p][1]);
                af2[1] = pack2(s[2 * p][2],     s[2 * p][3]);
                af2[2] = pack2(s[2 * p + 1][0], s[2 * p + 1][1]);
                af2[3] = pack2(s[2 * p + 1][2], s[2 * p + 1][3]);
#pragma unroll
                for (int cbt = 0; cbt < 4; cbt++) {
                    unsigned bf[4];
                    ldsm4t(bf, su32(&Vh[(p * 16 + l15) * QHS + cbt * 16 + lkh8]));
                    mma_f16(o[2 * cbt],     af2, bf[0], bf[1]);
                    mma_f16(o[2 * cbt + 1], af2, bf[2], bf[3]);
                }
            }
        }
    }
#undef G_ISSUE

    float inv0 = 1.f / l0, inv1 = 1.f / l1;
    int row0 = qb + m0 + g;
#pragma unroll
    for (int nt = 0; nt < 8; nt++) {
        int col = nt * 8 + tig * 2;
        __half* o0 = O + (size_t)(b * T_TOK + row0) * D_MODEL + h * HEAD_DIM + col;
        __half* o1 = O + (size_t)(b * T_TOK + row0 + 8) * D_MODEL + h * HEAD_DIM + col;
        *(__half2*)o0 = __floats2half2_rn(o[nt][0] * inv0, o[nt][1] * inv0);
        *(__half2*)o1 = __floats2half2_rn(o[nt][2] * inv1, o[nt][3] * inv1);
    }
}

// -------------------- launch ----------------------------------------------
extern "C" void kernel_launch(void* const* d_in, const int* in_sizes, int n_in,
                              void* d_out, int out_size) {
    const float* hs  = (const float*)d_in[0];
    const float* wq  = (const float*)d_in[1];
    const float* bq  = (const float*)d_in[2];
    const float* wk  = (const float*)d_in[3];
    const float* bk  = (const float*)d_in[4];
    const float* wv  = (const float*)d_in[5];
    const float* bv  = (const float*)d_in[6];
    const float* wo  = (const float*)d_in[7];
    const float* bo  = (const float*)d_in[8];
    const float* ab  = (const float*)d_in[9];
    const float* g1  = (const float*)d_in[10];
    const float* be1 = (const float*)d_in[11];
    const float* g3  = (const float*)d_in[12];
    const float* be3 = (const float*)d_in[13];
    const float* w1  = (const float*)d_in[14];
    const float* b1  = (const float*)d_in[15];
    const float* w2  = (const float*)d_in[16];
    const float* b2  = (const float*)d_in[17];
    float* out = (float*)d_out;

    __half *ni, *qkv, *wqkvT, *woT, *w1T, *w2T, *attn, *ffin, *hbuf;
    float *bqkv, *res1, *trig;
    cudaGetSymbolAddress((void**)&ni,    g_ni);
    cudaGetSymbolAddress((void**)&qkv,   g_qkv);
    cudaGetSymbolAddress((void**)&wqkvT, g_wqkvT);
    cudaGetSymbolAddress((void**)&bqkv,  g_bqkv);
    cudaGetSymbolAddress((void**)&woT,   g_woT);
    cudaGetSymbolAddress((void**)&w1T,   g_w1T);
    cudaGetSymbolAddress((void**)&w2T,   g_w2T);
    cudaGetSymbolAddress((void**)&attn,  g_attn);
    cudaGetSymbolAddress((void**)&res1,  g_res1);
    cudaGetSymbolAddress((void**)&ffin,  g_ffin);
    cudaGetSymbolAddress((void**)&hbuf,  g_h);
    cudaGetSymbolAddress((void**)&trig,  g_trig);

    static bool attr_set = false;
    if (!attr_set) {
        cudaFuncSetAttribute(attn_f16, cudaFuncAttributeMaxDynamicSharedMemorySize,
                             AT_SMEM_BYTES);
        cudaFuncSetAttribute((gemm_f16<false, true, true>), cudaFuncAttributeMaxDynamicSharedMemorySize,
                             G128_SMEM_BYTES);
        cudaFuncSetAttribute((gemm_f16<true, true, false>), cudaFuncAttributeMaxDynamicSharedMemorySize,
                             G128_SMEM_BYTES);
        cudaFuncSetAttribute((gemm_f16_m64<false, false>), cudaFuncAttributeMaxDynamicSharedMemorySize,
                             G64_SMEM_BYTES);
        attr_set = true;
    }

    // 0. prep
    trig_kernel<<<(T_TOK * 16 + 255) / 256, 256>>>(trig);
    concat_bias<<<(QKV_N + 255) / 256, 256>>>(bq, bk, bv, bqkv);
    transpose_all<<<6912, dim3(32, 8)>>>(wq, wk, wv, wo, w1, w2, wqkvT, woT, w1T, w2T);

    // 1. LN1 -> fp16
    ln_warp<<<M_ROWS / 8, 256>>>(hs, g1, be1, ni);

    // 2. fused QKV projection + RoPE
    gemm_f16<false, true, true><<<dim3(QKV_N / 128, M_ROWS / 128), 256, G128_SMEM_BYTES>>>(
        ni, wqkvT, bqkv, nullptr, qkv, trig, M_ROWS, QKV_N, D_MODEL);

    // 3. attention
    {
        dim3 ga(T_TOK / 128, N_HEADS, BATCH);
        attn_f16<<<ga, 256, AT_SMEM_BYTES>>>(qkv, ab, attn);
    }

    // 4. out-proj + residual(hs)
    gemm_f16_m64<false, false><<<dim3(D_MODEL / 128, M_ROWS / 64), 256, G64_SMEM_BYTES>>>(
        attn, woT, bo, hs, res1, M_ROWS, D_MODEL, D_MODEL);

    // 5. LN3 -> fp16
    ln_warp<<<M_ROWS / 8, 256>>>(res1, g3, be3, ffin);

    // 6. FFN1 + GELU
    gemm_f16<true, true, false><<<dim3(FFN_DIM / 128, M_ROWS / 128), 256, G128_SMEM_BYTES>>>(
        ffin, w1T, b1, nullptr, hbuf, nullptr, M_ROWS, FFN_DIM, D_MODEL);

    // 7. FFN2 + residual(res1)
    gemm_f16_m64<false, false><<<dim3(D_MODEL / 128, M_ROWS / 64), 256, G64_SMEM_BYTES>>>(
        hbuf, w2T, b2, res1, out, M_ROWS, D_MODEL, FFN_DIM);
}